// round 10
// baseline (speedup 1.0000x reference)
#include <cuda_runtime.h>
#include <cuda_bf16.h>
#include <math.h>
#include <stdint.h>

#define NROWS 20544     // B*L = 64*321
#define LL 321
#define DD 512
#define HH 8
#define EE 64
#define NTOPK 10

// ---------------- scratch (allocation-free: __device__ globals) ----------------
__device__ float    g_buf512[6ULL * NROWS * 512];    // f32: qb,kb,vb,k1,v1,qu2
__device__ float    g_buf2048[4ULL * NROWS * 2048];  // f32: q1/k2, t1, v2, spare
__device__ uint32_t g_sp_small[4ULL * NROWS * 512];  // split: x/att2, att, zb, y2
__device__ uint32_t g_sp_big[2ULL * NROWS * 2048];   // split: Vf1, u
__device__ uint32_t g_wt[16252928];                  // split transposed weights [N,K]

#define OFF_AV   0u
#define OFF_AO   262144u
#define OFF_ENC  524288u
#define OFF_F1Q  786432u
#define OFF_F1K  1835008u
#define OFF_F1V  2097152u
#define OFF_F1O  2359296u
#define OFF_F2Q  6553600u
#define OFF_F2K  7602176u
#define OFF_F2V  11796480u
#define OFF_F2O  15990784u

// ---------------- bf16 split helpers -------------------------------------------
__device__ __forceinline__ uint32_t fsplit(float x) {
    __nv_bfloat16 h = __float2bfloat16(x);
    float hf = __bfloat162float(h);
    __nv_bfloat16 l = __float2bfloat16(x - hf);
    return (uint32_t)__bfloat16_as_ushort(h) | ((uint32_t)__bfloat16_as_ushort(l) << 16);
}
__device__ __forceinline__ void ld_pair(const uint32_t* s, uint32_t& hi, uint32_t& lo) {
    uint2 p = *(const uint2*)s;
    hi = __byte_perm(p.x, p.y, 0x5410);
    lo = __byte_perm(p.x, p.y, 0x7632);
}

// ------------- blocked compensation: Kahan-merge a block partial ---------------
__device__ __forceinline__ void kadd(float p, float& s, float& c) {
    float y = __fsub_rn(p, c);
    float t = __fadd_rn(s, y);
    c = __fsub_rn(__fsub_rn(t, s), y);
    s = t;
}
__device__ __forceinline__ float kfin(float s, float c) { return __fsub_rn(s, c); }

// ============================ weight transpose + split =========================
__global__ void transpose_split_kernel(const float* __restrict__ src, uint32_t* __restrict__ dst,
                                       int K, int N)
{
    __shared__ float t[32][33];
    int bx = blockIdx.x * 32, by = blockIdx.y * 32;
    int txi = threadIdx.x, tyi = threadIdx.y;
#pragma unroll
    for (int j = 0; j < 32; j += 8)
        t[tyi + j][txi] = src[(size_t)(by + tyi + j) * N + bx + txi];
    __syncthreads();
#pragma unroll
    for (int j = 0; j < 32; j += 8)
        dst[(size_t)(bx + tyi + j) * K + by + txi] = fsplit(t[txi][tyi + j]);
}

__global__ void convert_kernel(const float* __restrict__ in, uint32_t* __restrict__ outp, int n)
{
    for (int i = blockIdx.x * 256 + threadIdx.x; i < n; i += gridDim.x * 256)
        outp[i] = fsplit(in[i]);
}

// ================= bf16x3 mma.sync GEMM, 4-stage pipeline ======================
#define MM_PITCH 40
#define MM_HALF  (128 * MM_PITCH)
#define MM_STAGE (2 * MM_HALF)
#define MM_NSTG  4
#define MM_SMEM  (MM_NSTG * MM_STAGE * 4)   // 163840 bytes

__device__ __forceinline__ void mm_load_stage(
    const uint32_t* __restrict__ A, const uint32_t* __restrict__ Bt,
    int bm, int bn, int M, int K, int k0, uint32_t* st, int tid)
{
    uint32_t a_s, b_s;
    asm("{ .reg .u64 t; cvta.to.shared.u64 t, %1; cvt.u32.u64 %0, t; }" : "=r"(a_s) : "l"(st));
    b_s = a_s + MM_HALF * 4;
#pragma unroll
    for (int j = 0; j < 4; j++) {
        int idx = tid + j * 256;
        int r = idx >> 3, c = idx & 7;
        uint32_t doff = (uint32_t)(r * MM_PITCH + c * 4) * 4;
        int grow = bm + r;
        const uint32_t* srcA = A + (size_t)(grow < M ? grow : 0) * K + k0 + c * 4;
        int szA = (grow < M) ? 16 : 0;
        asm volatile("cp.async.ca.shared.global [%0], [%1], 16, %2;"
                     :: "r"(a_s + doff), "l"(srcA), "r"(szA));
        const uint32_t* srcB = Bt + (size_t)(bn + r) * K + k0 + c * 4;
        asm volatile("cp.async.ca.shared.global [%0], [%1], 16;"
                     :: "r"(b_s + doff), "l"(srcB));
    }
    asm volatile("cp.async.commit_group;" ::: "memory");
}

#define MMA_BF16(acc, a0, a1, a2, a3, b0, b1) \
    asm volatile( \
        "mma.sync.aligned.m16n8k16.row.col.f32.bf16.bf16.f32 " \
        "{%0,%1,%2,%3}, {%4,%5,%6,%7}, {%8,%9}, {%0,%1,%2,%3};" \
        : "+f"((acc)[0]), "+f"((acc)[1]), "+f"((acc)[2]), "+f"((acc)[3]) \
        : "r"(a0), "r"(a1), "r"(a2), "r"(a3), "r"(b0), "r"(b1))

template<int EP, int OM>
__global__ __launch_bounds__(256)
void mm_gemm_kernel(const uint32_t* __restrict__ A, const uint32_t* __restrict__ Bt,
                    const float* __restrict__ bias, const float* __restrict__ res,
                    void* __restrict__ Cv, int M, int N, int K)
{
    extern __shared__ uint32_t sm[];
    const int tid = threadIdx.x;
    const int wid = tid >> 5, lane = tid & 31;
    const int wm = wid >> 2, wn = wid & 3;
    const int g = lane >> 2, t = lane & 3;
    const int bm = blockIdx.y * 128, bn = blockIdx.x * 128;

    float acc[4][4][4];
#pragma unroll
    for (int i = 0; i < 4; i++)
#pragma unroll
        for (int j = 0; j < 4; j++)
#pragma unroll
            for (int q = 0; q < 4; q++) acc[i][j][q] = 0.f;

    const int nc = K >> 5;

    // prologue: fill 3 of 4 stages
#pragma unroll
    for (int j = 0; j < 3; j++)
        if (j < nc)
            mm_load_stage(A, Bt, bm, bn, M, K, j * 32, sm + j * MM_STAGE, tid);

    for (int c = 0; c < nc; c++) {
        // wait for chunk c (tail-aware in-flight count)
        int rem = nc - 1 - c;
        if (rem >= 2)      asm volatile("cp.async.wait_group 2;" ::: "memory");
        else if (rem == 1) asm volatile("cp.async.wait_group 1;" ::: "memory");
        else               asm volatile("cp.async.wait_group 0;" ::: "memory");
        __syncthreads();
        // refill the slot consumed at iteration c-1
        if (c + 3 < nc)
            mm_load_stage(A, Bt, bm, bn, M, K, (c + 3) * 32,
                          sm + ((c + 3) & 3) * MM_STAGE, tid);

        const uint32_t* As = sm + (c & 3) * MM_STAGE;
        const uint32_t* Bs = As + MM_HALF;
#pragma unroll
        for (int ks = 0; ks < 2; ks++) {
            uint32_t ah[4][4], al[4][4], bh[4][2], bl[4][2];
#pragma unroll
            for (int mt = 0; mt < 4; mt++) {
                const uint32_t* base = As + (wm * 64 + mt * 16 + g) * MM_PITCH + ks * 16 + 2 * t;
                ld_pair(base,                  ah[mt][0], al[mt][0]);
                ld_pair(base + 8 * MM_PITCH,   ah[mt][1], al[mt][1]);
                ld_pair(base + 8,              ah[mt][2], al[mt][2]);
                ld_pair(base + 8 * MM_PITCH + 8, ah[mt][3], al[mt][3]);
            }
#pragma unroll
            for (int nt = 0; nt < 4; nt++) {
                const uint32_t* base = Bs + (wn * 32 + nt * 8 + g) * MM_PITCH + ks * 16 + 2 * t;
                ld_pair(base,     bh[nt][0], bl[nt][0]);
                ld_pair(base + 8, bh[nt][1], bl[nt][1]);
            }
#pragma unroll
            for (int mt = 0; mt < 4; mt++)
#pragma unroll
                for (int nt = 0; nt < 4; nt++) {
                    MMA_BF16(acc[mt][nt], ah[mt][0], ah[mt][1], ah[mt][2], ah[mt][3],
                             bl[nt][0], bl[nt][1]);
                    MMA_BF16(acc[mt][nt], al[mt][0], al[mt][1], al[mt][2], al[mt][3],
                             bh[nt][0], bh[nt][1]);
                    MMA_BF16(acc[mt][nt], ah[mt][0], ah[mt][1], ah[mt][2], ah[mt][3],
                             bh[nt][0], bh[nt][1]);
                }
        }
    }

    float* Cf = (float*)Cv;
    uint32_t* Cs = (uint32_t*)Cv;
#pragma unroll
    for (int mt = 0; mt < 4; mt++) {
#pragma unroll
        for (int half = 0; half < 2; half++) {
            int row = bm + wm * 64 + mt * 16 + g + half * 8;
            if (row >= M) continue;
#pragma unroll
            for (int nt = 0; nt < 4; nt++) {
                int col = bn + wn * 32 + nt * 8 + t * 2;
                float v0 = acc[mt][nt][half * 2 + 0] + bias[col];
                float v1 = acc[mt][nt][half * 2 + 1] + bias[col + 1];
                if (EP >= 2) {
                    v0 += res[(size_t)row * N + col];
                    v1 += res[(size_t)row * N + col + 1];
                }
                if (EP == 1) { v0 = fmaxf(v0, 0.f); v1 = fmaxf(v1, 0.f); }
                if (EP == 2) { v0 = (v0 > 0.f) ? v0 : 0.5f * v0; v1 = (v1 > 0.f) ? v1 : 0.5f * v1; }
                if (EP == 3) { v0 = (v0 > 0.f) ? v0 : expm1f(v0); v1 = (v1 > 0.f) ? v1 : expm1f(v1); }
                if (OM == 0) {
                    *(float2*)(Cf + (size_t)row * N + col) = make_float2(v0, v1);
                } else {
                    uint2 o = make_uint2(fsplit(v0), fsplit(v1));
                    *(uint2*)(Cs + (size_t)row * N + col) = o;
                }
            }
        }
    }
}

// ---------- blocked-compensated fp32 GEMM (near-exact), q/k feeding top-k ------
__global__ __launch_bounds__(256) void kgemm_kernel(
    const float* __restrict__ A, const float* __restrict__ B,
    const float* __restrict__ bias, float* __restrict__ C,
    int M, int N, int K, int relu)
{
    __shared__ float As[16][68];   // [k][m]
    __shared__ float Bs[16][68];   // [k][n]
    const int tid = threadIdx.x;
    const int bm = blockIdx.y * 64;
    const int bn = blockIdx.x * 64;
    const int ty = tid >> 4, tx = tid & 15;

    float s[4][4], cc[4][4];
#pragma unroll
    for (int i = 0; i < 4; i++)
#pragma unroll
        for (int j = 0; j < 4; j++) { s[i][j] = 0.f; cc[i][j] = 0.f; }

    const int ar = tid >> 2;
    const int ac = (tid & 3) << 2;
    const int br = tid >> 4;
    const int bc = (tid & 15) << 2;

    for (int k0 = 0; k0 < K; k0 += 16) {
        {
            int grow = bm + ar;
            float4 v = make_float4(0.f, 0.f, 0.f, 0.f);
            if (grow < M) v = *(const float4*)(A + (size_t)grow * K + k0 + ac);
            As[ac + 0][ar] = v.x; As[ac + 1][ar] = v.y;
            As[ac + 2][ar] = v.z; As[ac + 3][ar] = v.w;
        }
        *(float4*)&Bs[br][bc] = *(const float4*)(B + (size_t)(k0 + br) * N + bn + bc);
        __syncthreads();
#pragma unroll
        for (int blkk = 0; blkk < 2; blkk++) {
            float p[4][4];
#pragma unroll
            for (int i = 0; i < 4; i++)
#pragma unroll
                for (int j = 0; j < 4; j++) p[i][j] = 0.f;
#pragma unroll
            for (int kk = blkk * 8; kk < blkk * 8 + 8; kk++) {
                float4 av = *(const float4*)&As[kk][ty * 4];
                float4 bv = *(const float4*)&Bs[kk][tx * 4];
                const float* a = (const float*)&av;
                const float* b = (const float*)&bv;
#pragma unroll
                for (int i = 0; i < 4; i++)
#pragma unroll
                    for (int j = 0; j < 4; j++)
                        p[i][j] = __fmaf_rn(a[i], b[j], p[i][j]);
            }
#pragma unroll
            for (int i = 0; i < 4; i++)
#pragma unroll
                for (int j = 0; j < 4; j++)
                    kadd(p[i][j], s[i][j], cc[i][j]);
        }
        __syncthreads();
    }

#pragma unroll
    for (int i = 0; i < 4; i++) {
        int row = bm + ty * 4 + i;
        if (row < M) {
            float4 o;
            float* ov = (float*)&o;
#pragma unroll
            for (int j = 0; j < 4; j++) {
                float v = __fadd_rn(kfin(s[i][j], cc[i][j]), bias[bn + tx * 4 + j]);
                if (relu) v = fmaxf(v, 0.f);
                ov[j] = v;
            }
            *(float4*)(C + (size_t)row * N + bn + tx * 4) = o;
        }
    }
}

// ---------------- batched scores (blocked-compensated fp32) ---------------------
__global__ __launch_bounds__(256) void scores_kernel(
    const float* __restrict__ q, const float* __restrict__ k, float* __restrict__ out)
{
    int bh = blockIdx.z;
    int b = bh >> 3, h = bh & 7;
    int l0 = blockIdx.y * 32, s0 = blockIdx.x * 32;
    __shared__ float Qs[32][72];
    __shared__ float Ks[32][72];
    int tid = threadIdx.x;
    int r = tid >> 3;
    int c = (tid & 7) * 8;
    {
        int l = l0 + r;
        if (l < LL) {
            const float* src = q + ((size_t)(b * LL + l)) * DD + h * EE + c;
            *(float4*)&Qs[r][c]     = *(const float4*)src;
            *(float4*)&Qs[r][c + 4] = *(const float4*)(src + 4);
        } else {
#pragma unroll
            for (int t = 0; t < 8; t++) Qs[r][c + t] = 0.f;
        }
        int sdx = s0 + r;
        if (sdx < LL) {
            const float* src = k + ((size_t)(b * LL + sdx)) * DD + h * EE + c;
            *(float4*)&Ks[r][c]     = *(const float4*)src;
            *(float4*)&Ks[r][c + 4] = *(const float4*)(src + 4);
        } else {
#pragma unroll
            for (int t = 0; t < 8; t++) Ks[r][c + t] = 0.f;
        }
    }
    __syncthreads();
    int ty = tid >> 4, tx = tid & 15;
    float s00 = 0.f, s01 = 0.f, s10 = 0.f, s11 = 0.f;
    float c00 = 0.f, c01 = 0.f, c10 = 0.f, c11 = 0.f;
#pragma unroll
    for (int blkk = 0; blkk < 8; blkk++) {
        float p00 = 0.f, p01 = 0.f, p10 = 0.f, p11 = 0.f;
#pragma unroll
        for (int kk = blkk * 8; kk < blkk * 8 + 8; kk++) {
            float a0 = Qs[ty * 2 + 0][kk], a1 = Qs[ty * 2 + 1][kk];
            float b0 = Ks[tx * 2 + 0][kk], b1 = Ks[tx * 2 + 1][kk];
            p00 = __fmaf_rn(a0, b0, p00);
            p01 = __fmaf_rn(a0, b1, p01);
            p10 = __fmaf_rn(a1, b0, p10);
            p11 = __fmaf_rn(a1, b1, p11);
        }
        kadd(p00, s00, c00);
        kadd(p01, s01, c01);
        kadd(p10, s10, c10);
        kadd(p11, s11, c11);
    }
    size_t base = (size_t)bh * LL * LL;
    int l_0 = l0 + ty * 2, s_0 = s0 + tx * 2;
    if (l_0 < LL) {
        if (s_0 < LL)     out[base + (size_t)l_0 * LL + s_0]     = kfin(s00, c00);
        if (s_0 + 1 < LL) out[base + (size_t)l_0 * LL + s_0 + 1] = kfin(s01, c01);
    }
    if (l_0 + 1 < LL) {
        if (s_0 < LL)     out[base + (size_t)(l_0 + 1) * LL + s_0]     = kfin(s10, c10);
        if (s_0 + 1 < LL) out[base + (size_t)(l_0 + 1) * LL + s_0 + 1] = kfin(s11, c11);
    }
}

// ---------------- top-k mask + softmax, in place on scores ----------------
__global__ __launch_bounds__(256) void topk_softmax_kernel(float* __restrict__ A)
{
    const int lane = threadIdx.x & 31;
    const int wslot = threadIdx.x >> 5;
    const size_t row = (size_t)blockIdx.x * 8 + wslot;
    __shared__ float sm[8][352];
    float* s = sm[wslot];
    float* rp = A + row * LL;

    float r[11];
#pragma unroll
    for (int j = 0; j < 11; j++) {
        int idx = lane + j * 32;
        float v = (idx < LL) ? rp[idx] : -INFINITY;
        r[j] = v;
        s[idx] = v;
    }
    __syncwarp();

    float kth = 0.f, mmax = 0.f;
    for (int it = 0; it < NTOPK; it++) {
        float lm = -INFINITY;
#pragma unroll
        for (int j = 0; j < 11; j++) lm = fmaxf(lm, s[lane + j * 32]);
        float gm = lm;
#pragma unroll
        for (int o = 16; o > 0; o >>= 1) gm = fmaxf(gm, __shfl_xor_sync(0xffffffffu, gm, o));
        if (it == 0) mmax = gm;
        kth = gm;
        int li = 0x7fffffff;
#pragma unroll
        for (int j = 10; j >= 0; j--) {
            int idx = lane + j * 32;
            if (s[idx] == gm) li = idx;
        }
        int gi = li;
#pragma unroll
        for (int o = 16; o > 0; o >>= 1) gi = min(gi, __shfl_xor_sync(0xffffffffu, gi, o));
        if (li == gi) s[li] = -INFINITY;
        __syncwarp();
    }

    const float scale = 0.125f;
    float e[11];
    float sum = 0.f;
#pragma unroll
    for (int j = 0; j < 11; j++) {
        int idx = lane + j * 32;
        float v = r[j];
        float t = (idx < LL && v >= kth) ? expf((v - mmax) * scale) : 0.f;
        e[j] = t;
        sum += t;
    }
#pragma unroll
    for (int o = 16; o > 0; o >>= 1) sum += __shfl_xor_sync(0xffffffffu, sum, o);
    float inv = 1.f / sum;
#pragma unroll
    for (int j = 0; j < 11; j++) {
        int idx = lane + j * 32;
        if (idx < LL) rp[idx] = e[j] * inv;
    }
}

// ---------------- A @ V -> split output -----------------------------------------
__global__ __launch_bounds__(256) void av_kernel(
    const float* __restrict__ A, const float* __restrict__ v, uint32_t* __restrict__ out)
{
    int bh = blockIdx.z;
    int b = bh >> 3, h = bh & 7;
    int l0 = blockIdx.y * 64;
    __shared__ float As2[64][17];
    __shared__ float Vs[16][65];
    int tid = threadIdx.x;
    int ty = tid >> 4, tx = tid & 15;
    float acc[4][4];
#pragma unroll
    for (int i = 0; i < 4; i++)
#pragma unroll
        for (int j = 0; j < 4; j++) acc[i][j] = 0.f;

    const int ar = tid >> 2, ac = (tid & 3) * 4;
    const int vr = tid >> 4, vc = (tid & 15) * 4;
    size_t abase = (size_t)bh * LL * LL;

    for (int s0 = 0; s0 < LL; s0 += 16) {
        int l = l0 + ar;
#pragma unroll
        for (int cc = 0; cc < 4; cc++) {
            int sidx = s0 + ac + cc;
            As2[ar][ac + cc] = (l < LL && sidx < LL) ? A[abase + (size_t)l * LL + sidx] : 0.f;
        }
        int sv = s0 + vr;
        if (sv < LL) {
            float4 t = *(const float4*)(v + ((size_t)(b * LL + sv)) * DD + h * EE + vc);
            Vs[vr][vc+0]=t.x; Vs[vr][vc+1]=t.y; Vs[vr][vc+2]=t.z; Vs[vr][vc+3]=t.w;
        } else {
#pragma unroll
            for (int t = 0; t < 4; t++) Vs[vr][vc+t] = 0.f;
        }
        __syncthreads();
#pragma unroll
        for (int kk = 0; kk < 16; kk++) {
            float a[4], bb2[4];
#pragma unroll
            for (int i = 0; i < 4; i++) a[i] = As2[ty*4+i][kk];
#pragma unroll
            for (int j = 0; j < 4; j++) bb2[j] = Vs[kk][tx*4+j];
#pragma unroll
            for (int i = 0; i < 4; i++)
#pragma unroll
                for (int j = 0; j < 4; j++) acc[i][j] = fmaf(a[i], bb2[j], acc[i][j]);
        }
        __syncthreads();
    }
#pragma unroll
    for (int i = 0; i < 4; i++) {
        int l = l0 + ty * 4 + i;
        if (l < LL) {
#pragma unroll
            for (int j = 0; j < 4; j++) {
                int e = tx * 4 + j;
                out[((size_t)(b * LL + l)) * DD + h * EE + e] = fsplit(acc[i][j]);
            }
        }
    }
}

// ---------------- pwattn1: split output -----------------------------------------
__global__ __launch_bounds__(128) void pwattn1_kernel(
    const float* __restrict__ q, const float* __restrict__ k,
    const float* __restrict__ v, uint32_t* __restrict__ out)
{
    int n = blockIdx.x;
    int l = threadIdx.x;
    __shared__ float sk[512];
    __shared__ float sv[512];
    int t4 = l * 4;
    *(float4*)&sk[t4] = *(const float4*)(k + (size_t)n * 512 + t4);
    *(float4*)&sv[t4] = *(const float4*)(v + (size_t)n * 512 + t4);
    __syncthreads();
    float qr[16];
    const float* qp = q + (size_t)n * 2048 + l * 16;
#pragma unroll
    for (int p = 0; p < 16; p++) qr[p] = qp[p];
    float sc[32];
    float m = -INFINITY;
#pragma unroll
    for (int s = 0; s < 32; s++) {
        float d = 0.f;
#pragma unroll
        for (int p = 0; p < 16; p++) d = fmaf(qr[p], sk[s * 16 + p], d);
        sc[s] = d;
        m = fmaxf(m, d);
    }
    float sum = 0.f;
    float V[16];
#pragma unroll
    for (int p = 0; p < 16; p++) V[p] = 0.f;
#pragma unroll
    for (int s = 0; s < 32; s++) {
        float w = expf((sc[s] - m) * 0.25f);
        sum += w;
#pragma unroll
        for (int p = 0; p < 16; p++) V[p] = fmaf(w, sv[s * 16 + p], V[p]);
    }
    float inv = 1.f / sum;
    uint32_t* op = out + (size_t)n * 2048 + l * 16;
#pragma unroll
    for (int p = 0; p < 16; p++) op[p] = fsplit(V[p] * inv);
}

// ---------------- pwattn2: split output -----------------------------------------
__global__ __launch_bounds__(128) void pwattn2_kernel(
    const float* __restrict__ q, const float* __restrict__ k2,
    const float* __restrict__ v2, uint32_t* __restrict__ out)
{
    int n = blockIdx.x * 4 + (threadIdx.x >> 5);
    int lane = threadIdx.x & 31;
    const float* kp = k2 + (size_t)n * 2048;
    const float* vp = v2 + (size_t)n * 2048;
    float qr[16];
    const float* qp = q + (size_t)n * 512 + lane * 16;
#pragma unroll
    for (int p = 0; p < 16; p++) qr[p] = qp[p];
    float m = -INFINITY;
    for (int s = 0; s < 128; s++) {
        float d = 0.f;
#pragma unroll
        for (int p = 0; p < 16; p++) d = fmaf(qr[p], kp[s * 16 + p], d);
        m = fmaxf(m, d);
    }
    float sum = 0.f;
    float V[16];
#pragma unroll
    for (int p = 0; p < 16; p++) V[p] = 0.f;
    for (int s = 0; s < 128; s++) {
        float d = 0.f;
#pragma unroll
        for (int p = 0; p < 16; p++) d = fmaf(qr[p], kp[s * 16 + p], d);
        float w = expf((d - m) * 0.25f);
        sum += w;
#pragma unroll
        for (int p = 0; p < 16; p++) V[p] = fmaf(w, vp[s * 16 + p], V[p]);
    }
    float inv = 1.f / sum;
    uint32_t* op = out + (size_t)n * 512 + lane * 16;
#pragma unroll
    for (int p = 0; p < 16; p++) op[p] = fsplit(V[p] * inv);
}

// ---------------- layernorm over 2048 -> split output ---------------------------
__global__ __launch_bounds__(256) void ln_kernel(
    const float* __restrict__ in, const float* __restrict__ g,
    const float* __restrict__ b, uint32_t* __restrict__ out)
{
    int n = blockIdx.x;
    int tid = threadIdx.x;
    __shared__ float red[256];
    const float* x = in + (size_t)n * 2048;
    float s = 0.f;
    for (int i = tid; i < 2048; i += 256) s += x[i];
    red[tid] = s; __syncthreads();
    for (int o = 128; o > 0; o >>= 1) { if (tid < o) red[tid] += red[tid + o]; __syncthreads(); }
    float mean = red[0] * (1.f / 2048.f);
    __syncthreads();
    float vs = 0.f;
    for (int i = tid; i < 2048; i += 256) { float d = x[i] - mean; vs += d * d; }
    red[tid] = vs; __syncthreads();
    for (int o = 128; o > 0; o >>= 1) { if (tid < o) red[tid] += red[tid + o]; __syncthreads(); }
    float var = red[0] * (1.f / 2048.f);
    float inv = rsqrtf(var + 1e-5f);
    uint32_t* op = out + (size_t)n * 2048;
    for (int i = tid; i < 2048; i += 256) op[i] = fsplit((x[i] - mean) * inv * g[i] + b[i]);
}

// ---------------- launch --------------------------------------------------------
extern "C" void kernel_launch(void* const* d_in, const int* in_sizes, int n_in,
                              void* d_out, int out_size)
{
    (void)in_sizes; (void)n_in; (void)out_size;
    const float* x     = (const float*)d_in[0];
    const float* aqw   = (const float*)d_in[1];
    const float* aqb   = (const float*)d_in[2];
    const float* akw   = (const float*)d_in[3];
    const float* akb   = (const float*)d_in[4];
    const float* avw   = (const float*)d_in[5];
    const float* avb   = (const float*)d_in[6];
    const float* aow   = (const float*)d_in[7];
    const float* aob   = (const float*)d_in[8];
    const float* encw  = (const float*)d_in[9];
    const float* encb  = (const float*)d_in[10];
    const float* f1qw  = (const float*)d_in[11];
    const float* f1qb  = (const float*)d_in[12];
    const float* f1kw  = (const float*)d_in[13];
    const float* f1kb  = (const float*)d_in[14];
    const float* f1vw  = (const float*)d_in[15];
    const float* f1vb  = (const float*)d_in[16];
    const float* f1ow  = (const float*)d_in[17];
    const float* f1ob  = (const float*)d_in[18];
    const float* f2qw  = (const float*)d_in[19];
    const float* f2qb  = (const float*)d_in[20];
    const float* f2kw  = (const float*)d_in[21];
    const float* f2kb  = (const float*)d_in[22];
    const float* f2vw  = (const float*)d_in[23];
    const float* f2vb  = (const float*)d_in[24];
    const float* f2ow  = (const float*)d_in[25];
    const float* f2ob  = (const float*)d_in[26];
    const float* lng   = (const float*)d_in[27];
    const float* lnb   = (const float*)d_in[28];

    float* out  = (float*)d_out;
    float* Aout = out + (size_t)NROWS * 512;

    float* b512; float* b2048; uint32_t* sps; uint32_t* spb; uint32_t* wt;
    cudaGetSymbolAddress((void**)&b512,  g_buf512);
    cudaGetSymbolAddress((void**)&b2048, g_buf2048);
    cudaGetSymbolAddress((void**)&sps,   g_sp_small);
    cudaGetSymbolAddress((void**)&spb,   g_sp_big);
    cudaGetSymbolAddress((void**)&wt,    g_wt);
    const size_t S = (size_t)NROWS * 512;
    const size_t T = (size_t)NROWS * 2048;
    float* qb   = b512;
    float* kb   = b512 + S;
    float* vb   = b512 + 2 * S;
    float* k1   = b512 + 3 * S;
    float* v1   = b512 + 4 * S;
    float* qu2  = b512 + 5 * S;
    float* q1   = b2048;
    float* t1   = b2048 + T;
    float* v2   = b2048 + 2 * T;
    uint32_t* x_sp   = sps;
    uint32_t* att_sp = sps + S;
    uint32_t* zb_sp  = sps + 2 * S;
    uint32_t* y2_sp  = sps + 3 * S;
    uint32_t* Vf1_sp = spb;
    uint32_t* u_sp   = spb + T;

    cudaFuncSetAttribute(mm_gemm_kernel<0,0>, cudaFuncAttributeMaxDynamicSharedMemorySize, MM_SMEM);
    cudaFuncSetAttribute(mm_gemm_kernel<1,0>, cudaFuncAttributeMaxDynamicSharedMemorySize, MM_SMEM);
    cudaFuncSetAttribute(mm_gemm_kernel<3,0>, cudaFuncAttributeMaxDynamicSharedMemorySize, MM_SMEM);
    cudaFuncSetAttribute(mm_gemm_kernel<4,0>, cudaFuncAttributeMaxDynamicSharedMemorySize, MM_SMEM);
    cudaFuncSetAttribute(mm_gemm_kernel<2,1>, cudaFuncAttributeMaxDynamicSharedMemorySize, MM_SMEM);
    cudaFuncSetAttribute(mm_gemm_kernel<0,1>, cudaFuncAttributeMaxDynamicSharedMemorySize, MM_SMEM);

    dim3 blk(256);
    dim3 tb(32, 8);
    dim3 tg512(4, (NROWS + 127) / 128);
    dim3 tg2048(16, (NROWS + 127) / 128);
    dim3 kg(8, (NROWS + 63) / 64);

    // ---- weight transpose+split ----
    transpose_split_kernel<<<dim3(16, 16), tb>>>(avw,  wt + OFF_AV,  512,  512);
    transpose_split_kernel<<<dim3(16, 16), tb>>>(aow,  wt + OFF_AO,  512,  512);
    transpose_split_kernel<<<dim3(16, 16), tb>>>(encw, wt + OFF_ENC, 512,  512);
    transpose_split_kernel<<<dim3(64, 16), tb>>>(f1qw, wt + OFF_F1Q, 512,  2048);
    transpose_split_kernel<<<dim3(16, 16), tb>>>(f1kw, wt + OFF_F1K, 512,  512);
    transpose_split_kernel<<<dim3(16, 16), tb>>>(f1vw, wt + OFF_F1V, 512,  512);
    transpose_split_kernel<<<dim3(64, 64), tb>>>(f1ow, wt + OFF_F1O, 2048, 2048);
    transpose_split_kernel<<<dim3(16, 64), tb>>>(f2qw, wt + OFF_F2Q, 2048, 512);
    transpose_split_kernel<<<dim3(64, 64), tb>>>(f2kw, wt + OFF_F2K, 2048, 2048);
    transpose_split_kernel<<<dim3(64, 64), tb>>>(f2vw, wt + OFF_F2V, 2048, 2048);
    transpose_split_kernel<<<dim3(16, 16), tb>>>(f2ow, wt + OFF_F2O, 512,  512);
    convert_kernel<<<4096, 256>>>(x, x_sp, (int)S);

    // ---- graph attention (q,k,scores near-exact blocked-compensated fp32) ----
    kgemm_kernel<<<kg, blk>>>(x, aqw, aqb, qb, NROWS, 512, 512, 1);
    kgemm_kernel<<<kg, blk>>>(x, akw, akb, kb, NROWS, 512, 512, 0);
    mm_gemm_kernel<1,0><<<tg512, blk, MM_SMEM>>>(x_sp, wt + OFF_AV, avb, nullptr, vb, NROWS, 512, 512);
    scores_kernel<<<dim3(11, 11, 512), blk>>>(qb, kb, Aout);
    topk_softmax_kernel<<<20544, blk>>>(Aout);
    av_kernel<<<dim3(1, 6, 512), blk>>>(Aout, vb, att_sp);
    mm_gemm_kernel<2,1><<<tg512, blk, MM_SMEM>>>(att_sp, wt + OFF_AO, aob, x, zb_sp, NROWS, 512, 512);
    mm_gemm_kernel<0,1><<<tg512, blk, MM_SMEM>>>(zb_sp, wt + OFF_ENC, encb, nullptr, y2_sp, NROWS, 512, 512);

    // ---- ff1 pwattn ----
    mm_gemm_kernel<1,0><<<tg2048, blk, MM_SMEM>>>(y2_sp, wt + OFF_F1Q, f1qb, nullptr, q1, NROWS, 2048, 512);
    mm_gemm_kernel<0,0><<<tg512, blk, MM_SMEM>>>(y2_sp, wt + OFF_F1K, f1kb, nullptr, k1, NROWS, 512, 512);
    mm_gemm_kernel<1,0><<<tg512, blk, MM_SMEM>>>(y2_sp, wt + OFF_F1V, f1vb, nullptr, v1, NROWS, 512, 512);
    pwattn1_kernel<<<NROWS, 128>>>(q1, k1, v1, Vf1_sp);
    mm_gemm_kernel<3,0><<<tg2048, blk, MM_SMEM>>>(Vf1_sp, wt + OFF_F1O, f1ob, q1, t1, NROWS, 2048, 2048);
    ln_kernel<<<NROWS, blk>>>(t1, lng, lnb, u_sp);

    // ---- ff2 pwattn ----
    mm_gemm_kernel<1,0><<<tg512, blk, MM_SMEM>>>(u_sp, wt + OFF_F2Q, f2qb, nullptr, qu2, NROWS, 512, 2048);
    mm_gemm_kernel<0,0><<<tg2048, blk, MM_SMEM>>>(u_sp, wt + OFF_F2K, f2kb, nullptr, q1, NROWS, 2048, 2048);
    mm_gemm_kernel<1,0><<<tg2048, blk, MM_SMEM>>>(u_sp, wt + OFF_F2V, f2vb, nullptr, v2, NROWS, 2048, 2048);
    pwattn2_kernel<<<NROWS / 4, 128>>>(qu2, q1, v2, x_sp);
    mm_gemm_kernel<4,0><<<tg512, blk, MM_SMEM>>>(x_sp, wt + OFF_F2O, f2ob, qu2, out, NROWS, 512, 512);
}

// round 11
// speedup vs baseline: 1.0510x; 1.0510x over previous
#include <cuda_runtime.h>
#include <cuda_bf16.h>
#include <math.h>
#include <stdint.h>

#define NROWS 20544     // B*L = 64*321
#define LL 321
#define DD 512
#define HH 8
#define EE 64
#define NTOPK 10

// ---------------- scratch (allocation-free: __device__ globals) ----------------
__device__ float    g_buf512[6ULL * NROWS * 512];
__device__ float    g_buf2048[4ULL * NROWS * 2048];
__device__ uint32_t g_sp_small[4ULL * NROWS * 512];
__device__ uint32_t g_sp_big[2ULL * NROWS * 2048];
__device__ uint32_t g_wt[16252928];                  // split transposed weights [N,K]

#define OFF_AV   0u
#define OFF_AO   262144u
#define OFF_ENC  524288u
#define OFF_F1Q  786432u
#define OFF_F1K  1835008u
#define OFF_F1V  2097152u
#define OFF_F1O  2359296u
#define OFF_F2Q  6553600u
#define OFF_F2K  7602176u
#define OFF_F2V  11796480u
#define OFF_F2O  15990784u

// ---------------- bf16 split helpers -------------------------------------------
__device__ __forceinline__ uint32_t fsplit(float x) {
    __nv_bfloat16 h = __float2bfloat16(x);
    float hf = __bfloat162float(h);
    __nv_bfloat16 l = __float2bfloat16(x - hf);
    return (uint32_t)__bfloat16_as_ushort(h) | ((uint32_t)__bfloat16_as_ushort(l) << 16);
}
__device__ __forceinline__ void ld_pair(const uint32_t* s, uint32_t& hi, uint32_t& lo) {
    uint2 p = *(const uint2*)s;
    hi = __byte_perm(p.x, p.y, 0x5410);
    lo = __byte_perm(p.x, p.y, 0x7632);
}

// ------------- blocked compensation: Kahan-merge a block partial ---------------
__device__ __forceinline__ void kadd(float p, float& s, float& c) {
    float y = __fsub_rn(p, c);
    float t = __fadd_rn(s, y);
    c = __fsub_rn(__fsub_rn(t, s), y);
    s = t;
}
__device__ __forceinline__ float kfin(float s, float c) { return __fsub_rn(s, c); }

// ==================== batched weight transpose + split =========================
// src [K,N] f32 row-major -> dst [N,K] packed-split u32 row-major, 11 jobs.
struct TransJob { const float* src; uint32_t dstoff; int K; int N; int tstart; };
struct TransArgs { TransJob job[11]; };

__global__ void transpose_split_all(TransArgs a)
{
    __shared__ float t[32][33];
    int tile = blockIdx.x;
    int ji = 0;
#pragma unroll
    for (int j = 1; j < 11; j++)
        if (tile >= a.job[j].tstart) ji = j;
    const TransJob& J = a.job[ji];
    int local = tile - J.tstart;
    int ntx = J.N >> 5;
    int bx = (local % ntx) * 32, by = (local / ntx) * 32;
    int txi = threadIdx.x, tyi = threadIdx.y;
    const float* src = J.src;
    uint32_t* dst = g_wt + J.dstoff;
#pragma unroll
    for (int j = 0; j < 32; j += 8)
        t[tyi + j][txi] = src[(size_t)(by + tyi + j) * J.N + bx + txi];
    __syncthreads();
#pragma unroll
    for (int j = 0; j < 32; j += 8)
        dst[(size_t)(bx + tyi + j) * J.K + by + txi] = fsplit(t[txi][tyi + j]);
}

__global__ void convert_kernel(const float* __restrict__ in, uint32_t* __restrict__ outp, int n)
{
    for (int i = blockIdx.x * 256 + threadIdx.x; i < n; i += gridDim.x * 256)
        outp[i] = fsplit(in[i]);
}

// ================= bf16x3 mma.sync GEMM (R9 2-stage config) ====================
#define MM_PITCH 40
#define MM_HALF  (128 * MM_PITCH)
#define MM_STAGE (2 * MM_HALF)
#define MM_SMEM  (2 * MM_STAGE * 4)

__device__ __forceinline__ void mm_load_stage(
    const uint32_t* __restrict__ A, const uint32_t* __restrict__ Bt,
    int bm, int bn, int M, int K, int k0, uint32_t* st, int tid)
{
    uint32_t a_s, b_s;
    asm("{ .reg .u64 t; cvta.to.shared.u64 t, %1; cvt.u32.u64 %0, t; }" : "=r"(a_s) : "l"(st));
    b_s = a_s + MM_HALF * 4;
#pragma unroll
    for (int j = 0; j < 4; j++) {
        int idx = tid + j * 256;
        int r = idx >> 3, c = idx & 7;
        uint32_t doff = (uint32_t)(r * MM_PITCH + c * 4) * 4;
        int grow = bm + r;
        const uint32_t* srcA = A + (size_t)(grow < M ? grow : 0) * K + k0 + c * 4;
        int szA = (grow < M) ? 16 : 0;
        asm volatile("cp.async.ca.shared.global [%0], [%1], 16, %2;"
                     :: "r"(a_s + doff), "l"(srcA), "r"(szA));
        const uint32_t* srcB = Bt + (size_t)(bn + r) * K + k0 + c * 4;
        asm volatile("cp.async.ca.shared.global [%0], [%1], 16;"
                     :: "r"(b_s + doff), "l"(srcB));
    }
    asm volatile("cp.async.commit_group;" ::: "memory");
}

#define MMA_BF16(acc, a0, a1, a2, a3, b0, b1) \
    asm volatile( \
        "mma.sync.aligned.m16n8k16.row.col.f32.bf16.bf16.f32 " \
        "{%0,%1,%2,%3}, {%4,%5,%6,%7}, {%8,%9}, {%0,%1,%2,%3};" \
        : "+f"((acc)[0]), "+f"((acc)[1]), "+f"((acc)[2]), "+f"((acc)[3]) \
        : "r"(a0), "r"(a1), "r"(a2), "r"(a3), "r"(b0), "r"(b1))

template<int EP, int OM>
__global__ __launch_bounds__(256)
void mm_gemm_kernel(const uint32_t* __restrict__ A, const uint32_t* __restrict__ Bt,
                    const float* __restrict__ bias, const float* __restrict__ res,
                    void* __restrict__ Cv, int M, int N, int K)
{
    extern __shared__ uint32_t sm[];
    const int tid = threadIdx.x;
    const int wid = tid >> 5, lane = tid & 31;
    const int wm = wid >> 2, wn = wid & 3;
    const int g = lane >> 2, t = lane & 3;
    const int bm = blockIdx.y * 128, bn = blockIdx.x * 128;

    float acc[4][4][4];
#pragma unroll
    for (int i = 0; i < 4; i++)
#pragma unroll
        for (int j = 0; j < 4; j++)
#pragma unroll
            for (int q = 0; q < 4; q++) acc[i][j][q] = 0.f;

    const int nc = K >> 5;
    mm_load_stage(A, Bt, bm, bn, M, K, 0, sm, tid);

    for (int c = 0; c < nc; c++) {
        if (c + 1 < nc)
            mm_load_stage(A, Bt, bm, bn, M, K, (c + 1) * 32, sm + ((c + 1) & 1) * MM_STAGE, tid);
        if (c + 1 < nc) asm volatile("cp.async.wait_group 1;" ::: "memory");
        else            asm volatile("cp.async.wait_group 0;" ::: "memory");
        __syncthreads();

        const uint32_t* As = sm + (c & 1) * MM_STAGE;
        const uint32_t* Bs = As + MM_HALF;
#pragma unroll
        for (int ks = 0; ks < 2; ks++) {
            uint32_t ah[4][4], al[4][4], bh[4][2], bl[4][2];
#pragma unroll
            for (int mt = 0; mt < 4; mt++) {
                const uint32_t* base = As + (wm * 64 + mt * 16 + g) * MM_PITCH + ks * 16 + 2 * t;
                ld_pair(base,                  ah[mt][0], al[mt][0]);
                ld_pair(base + 8 * MM_PITCH,   ah[mt][1], al[mt][1]);
                ld_pair(base + 8,              ah[mt][2], al[mt][2]);
                ld_pair(base + 8 * MM_PITCH + 8, ah[mt][3], al[mt][3]);
            }
#pragma unroll
            for (int nt = 0; nt < 4; nt++) {
                const uint32_t* base = Bs + (wn * 32 + nt * 8 + g) * MM_PITCH + ks * 16 + 2 * t;
                ld_pair(base,     bh[nt][0], bl[nt][0]);
                ld_pair(base + 8, bh[nt][1], bl[nt][1]);
            }
#pragma unroll
            for (int mt = 0; mt < 4; mt++)
#pragma unroll
                for (int nt = 0; nt < 4; nt++) {
                    MMA_BF16(acc[mt][nt], ah[mt][0], ah[mt][1], ah[mt][2], ah[mt][3],
                             bl[nt][0], bl[nt][1]);
                    MMA_BF16(acc[mt][nt], al[mt][0], al[mt][1], al[mt][2], al[mt][3],
                             bh[nt][0], bh[nt][1]);
                    MMA_BF16(acc[mt][nt], ah[mt][0], ah[mt][1], ah[mt][2], ah[mt][3],
                             bh[nt][0], bh[nt][1]);
                }
        }
        __syncthreads();
    }

    float* Cf = (float*)Cv;
    uint32_t* Cs = (uint32_t*)Cv;
#pragma unroll
    for (int mt = 0; mt < 4; mt++) {
#pragma unroll
        for (int half = 0; half < 2; half++) {
            int row = bm + wm * 64 + mt * 16 + g + half * 8;
            if (row >= M) continue;
#pragma unroll
            for (int nt = 0; nt < 4; nt++) {
                int col = bn + wn * 32 + nt * 8 + t * 2;
                float v0 = acc[mt][nt][half * 2 + 0] + bias[col];
                float v1 = acc[mt][nt][half * 2 + 1] + bias[col + 1];
                if (EP >= 2) {
                    v0 += res[(size_t)row * N + col];
                    v1 += res[(size_t)row * N + col + 1];
                }
                if (EP == 1) { v0 = fmaxf(v0, 0.f); v1 = fmaxf(v1, 0.f); }
                if (EP == 2) { v0 = (v0 > 0.f) ? v0 : 0.5f * v0; v1 = (v1 > 0.f) ? v1 : 0.5f * v1; }
                if (EP == 3) { v0 = (v0 > 0.f) ? v0 : expm1f(v0); v1 = (v1 > 0.f) ? v1 : expm1f(v1); }
                if (OM == 0) {
                    *(float2*)(Cf + (size_t)row * N + col) = make_float2(v0, v1);
                } else {
                    uint2 o = make_uint2(fsplit(v0), fsplit(v1));
                    *(uint2*)(Cs + (size_t)row * N + col) = o;
                }
            }
        }
    }
}

// ---------- blocked-compensated fp32 GEMM (near-exact), q/k feeding top-k ------
__global__ __launch_bounds__(256) void kgemm_kernel(
    const float* __restrict__ A, const float* __restrict__ B,
    const float* __restrict__ bias, float* __restrict__ C,
    int M, int N, int K, int relu)
{
    __shared__ float As[16][68];
    __shared__ float Bs[16][68];
    const int tid = threadIdx.x;
    const int bm = blockIdx.y * 64;
    const int bn = blockIdx.x * 64;
    const int ty = tid >> 4, tx = tid & 15;

    float s[4][4], cc[4][4];
#pragma unroll
    for (int i = 0; i < 4; i++)
#pragma unroll
        for (int j = 0; j < 4; j++) { s[i][j] = 0.f; cc[i][j] = 0.f; }

    const int ar = tid >> 2;
    const int ac = (tid & 3) << 2;
    const int br = tid >> 4;
    const int bc = (tid & 15) << 2;

    for (int k0 = 0; k0 < K; k0 += 16) {
        {
            int grow = bm + ar;
            float4 v = make_float4(0.f, 0.f, 0.f, 0.f);
            if (grow < M) v = *(const float4*)(A + (size_t)grow * K + k0 + ac);
            As[ac + 0][ar] = v.x; As[ac + 1][ar] = v.y;
            As[ac + 2][ar] = v.z; As[ac + 3][ar] = v.w;
        }
        *(float4*)&Bs[br][bc] = *(const float4*)(B + (size_t)(k0 + br) * N + bn + bc);
        __syncthreads();
#pragma unroll
        for (int blkk = 0; blkk < 2; blkk++) {
            float p[4][4];
#pragma unroll
            for (int i = 0; i < 4; i++)
#pragma unroll
                for (int j = 0; j < 4; j++) p[i][j] = 0.f;
#pragma unroll
            for (int kk = blkk * 8; kk < blkk * 8 + 8; kk++) {
                float4 av = *(const float4*)&As[kk][ty * 4];
                float4 bv = *(const float4*)&Bs[kk][tx * 4];
                const float* a = (const float*)&av;
                const float* b = (const float*)&bv;
#pragma unroll
                for (int i = 0; i < 4; i++)
#pragma unroll
                    for (int j = 0; j < 4; j++)
                        p[i][j] = __fmaf_rn(a[i], b[j], p[i][j]);
            }
#pragma unroll
            for (int i = 0; i < 4; i++)
#pragma unroll
                for (int j = 0; j < 4; j++)
                    kadd(p[i][j], s[i][j], cc[i][j]);
        }
        __syncthreads();
    }

#pragma unroll
    for (int i = 0; i < 4; i++) {
        int row = bm + ty * 4 + i;
        if (row < M) {
            float4 o;
            float* ov = (float*)&o;
#pragma unroll
            for (int j = 0; j < 4; j++) {
                float v = __fadd_rn(kfin(s[i][j], cc[i][j]), bias[bn + tx * 4 + j]);
                if (relu) v = fmaxf(v, 0.f);
                ov[j] = v;
            }
            *(float4*)(C + (size_t)row * N + bn + tx * 4) = o;
        }
    }
}

// ---------------- batched scores (blocked-compensated fp32) ---------------------
__global__ __launch_bounds__(256) void scores_kernel(
    const float* __restrict__ q, const float* __restrict__ k, float* __restrict__ out)
{
    int bh = blockIdx.z;
    int b = bh >> 3, h = bh & 7;
    int l0 = blockIdx.y * 32, s0 = blockIdx.x * 32;
    __shared__ float Qs[32][72];
    __shared__ float Ks[32][72];
    int tid = threadIdx.x;
    int r = tid >> 3;
    int c = (tid & 7) * 8;
    {
        int l = l0 + r;
        if (l < LL) {
            const float* src = q + ((size_t)(b * LL + l)) * DD + h * EE + c;
            *(float4*)&Qs[r][c]     = *(const float4*)src;
            *(float4*)&Qs[r][c + 4] = *(const float4*)(src + 4);
        } else {
#pragma unroll
            for (int t = 0; t < 8; t++) Qs[r][c + t] = 0.f;
        }
        int sdx = s0 + r;
        if (sdx < LL) {
            const float* src = k + ((size_t)(b * LL + sdx)) * DD + h * EE + c;
            *(float4*)&Ks[r][c]     = *(const float4*)src;
            *(float4*)&Ks[r][c + 4] = *(const float4*)(src + 4);
        } else {
#pragma unroll
            for (int t = 0; t < 8; t++) Ks[r][c + t] = 0.f;
        }
    }
    __syncthreads();
    int ty = tid >> 4, tx = tid & 15;
    float s00 = 0.f, s01 = 0.f, s10 = 0.f, s11 = 0.f;
    float c00 = 0.f, c01 = 0.f, c10 = 0.f, c11 = 0.f;
#pragma unroll
    for (int blkk = 0; blkk < 8; blkk++) {
        float p00 = 0.f, p01 = 0.f, p10 = 0.f, p11 = 0.f;
#pragma unroll
        for (int kk = blkk * 8; kk < blkk * 8 + 8; kk++) {
            float a0 = Qs[ty * 2 + 0][kk], a1 = Qs[ty * 2 + 1][kk];
            float b0 = Ks[tx * 2 + 0][kk], b1 = Ks[tx * 2 + 1][kk];
            p00 = __fmaf_rn(a0, b0, p00);
            p01 = __fmaf_rn(a0, b1, p01);
            p10 = __fmaf_rn(a1, b0, p10);
            p11 = __fmaf_rn(a1, b1, p11);
        }
        kadd(p00, s00, c00);
        kadd(p01, s01, c01);
        kadd(p10, s10, c10);
        kadd(p11, s11, c11);
    }
    size_t base = (size_t)bh * LL * LL;
    int l_0 = l0 + ty * 2, s_0 = s0 + tx * 2;
    if (l_0 < LL) {
        if (s_0 < LL)     out[base + (size_t)l_0 * LL + s_0]     = kfin(s00, c00);
        if (s_0 + 1 < LL) out[base + (size_t)l_0 * LL + s_0 + 1] = kfin(s01, c01);
    }
    if (l_0 + 1 < LL) {
        if (s_0 < LL)     out[base + (size_t)(l_0 + 1) * LL + s_0]     = kfin(s10, c10);
        if (s_0 + 1 < LL) out[base + (size_t)(l_0 + 1) * LL + s_0 + 1] = kfin(s11, c11);
    }
}

// ---------------- top-k mask + softmax, in place on scores ----------------
__global__ __launch_bounds__(256) void topk_softmax_kernel(float* __restrict__ A)
{
    const int lane = threadIdx.x & 31;
    const int wslot = threadIdx.x >> 5;
    const size_t row = (size_t)blockIdx.x * 8 + wslot;
    __shared__ float sm[8][352];
    float* s = sm[wslot];
    float* rp = A + row * LL;

    float r[11];
#pragma unroll
    for (int j = 0; j < 11; j++) {
        int idx = lane + j * 32;
        float v = (idx < LL) ? rp[idx] : -INFINITY;
        r[j] = v;
        s[idx] = v;
    }
    __syncwarp();

    float kth = 0.f, mmax = 0.f;
    for (int it = 0; it < NTOPK; it++) {
        float lm = -INFINITY;
#pragma unroll
        for (int j = 0; j < 11; j++) lm = fmaxf(lm, s[lane + j * 32]);
        float gm = lm;
#pragma unroll
        for (int o = 16; o > 0; o >>= 1) gm = fmaxf(gm, __shfl_xor_sync(0xffffffffu, gm, o));
        if (it == 0) mmax = gm;
        kth = gm;
        int li = 0x7fffffff;
#pragma unroll
        for (int j = 10; j >= 0; j--) {
            int idx = lane + j * 32;
            if (s[idx] == gm) li = idx;
        }
        int gi = li;
#pragma unroll
        for (int o = 16; o > 0; o >>= 1) gi = min(gi, __shfl_xor_sync(0xffffffffu, gi, o));
        if (li == gi) s[li] = -INFINITY;
        __syncwarp();
    }

    const float scale = 0.125f;
    float e[11];
    float sum = 0.f;
#pragma unroll
    for (int j = 0; j < 11; j++) {
        int idx = lane + j * 32;
        float v = r[j];
        float t = (idx < LL && v >= kth) ? expf((v - mmax) * scale) : 0.f;
        e[j] = t;
        sum += t;
    }
#pragma unroll
    for (int o = 16; o > 0; o >>= 1) sum += __shfl_xor_sync(0xffffffffu, sum, o);
    float inv = 1.f / sum;
#pragma unroll
    for (int j = 0; j < 11; j++) {
        int idx = lane + j * 32;
        if (idx < LL) rp[idx] = e[j] * inv;
    }
}

// ---------------- sparse A @ V -> split output ----------------------------------
// A rows have ~10 nonzeros after top-k masking. Ballot-compact nonzeros in
// ascending index order, then gather-FMA. Accumulation order == the dense
// ascending-index fmaf order (zeros are exact identities) -> bit-identical.
__global__ __launch_bounds__(256) void av_sparse_kernel(
    const float* __restrict__ A, const float* __restrict__ v, uint32_t* __restrict__ out)
{
    __shared__ short  sidx[8][24];
    __shared__ float  swt[8][24];
    __shared__ int    scnt[8];
    int blk = blockIdx.x;
    int b = blk / LL, l = blk % LL;
    int tid = threadIdx.x;
    int wid = tid >> 5, lane = tid & 31;

    // phase 1: warp h compacts nonzeros of A[(b*8+h), l, :]
    {
        int h = wid;
        const float* rp = A + ((size_t)(b * 8 + h) * LL + l) * LL;
        int cnt = 0;
#pragma unroll
        for (int j = 0; j < 11; j++) {
            int idx = lane + j * 32;
            float w = (idx < LL) ? rp[idx] : 0.f;
            unsigned m = __ballot_sync(0xffffffffu, w > 0.f);
            if (w > 0.f) {
                int pos = cnt + __popc(m & ((1u << lane) - 1u));
                if (pos < 24) { sidx[h][pos] = (short)idx; swt[h][pos] = w; }
            }
            cnt += __popc(m);
        }
        if (lane == 0) scnt[h] = (cnt < 24) ? cnt : 24;
    }
    __syncthreads();

    // phase 2: gather-FMA into 512 outputs
    const float* vbase = v + (size_t)b * LL * DD;
#pragma unroll
    for (int e0 = 0; e0 < 2; e0++) {
        int e = tid + e0 * 256;
        int h = e >> 6, c2 = e & 63;
        int n2 = scnt[h];
        const float* vp = vbase + h * EE + c2;
        float acc = 0.f;
        for (int j = 0; j < n2; j++)
            acc = __fmaf_rn(swt[h][j], vp[(size_t)sidx[h][j] * DD], acc);
        out[((size_t)(b * LL + l)) * DD + e] = fsplit(acc);
    }
}

// ---------------- pwattn1: split output -----------------------------------------
__global__ __launch_bounds__(128) void pwattn1_kernel(
    const float* __restrict__ q, const float* __restrict__ k,
    const float* __restrict__ v, uint32_t* __restrict__ out)
{
    int n = blockIdx.x;
    int l = threadIdx.x;
    __shared__ float sk[512];
    __shared__ float sv[512];
    int t4 = l * 4;
    *(float4*)&sk[t4] = *(const float4*)(k + (size_t)n * 512 + t4);
    *(float4*)&sv[t4] = *(const float4*)(v + (size_t)n * 512 + t4);
    __syncthreads();
    float qr[16];
    const float* qp = q + (size_t)n * 2048 + l * 16;
#pragma unroll
    for (int p = 0; p < 16; p++) qr[p] = qp[p];
    float sc[32];
    float m = -INFINITY;
#pragma unroll
    for (int s = 0; s < 32; s++) {
        float d = 0.f;
#pragma unroll
        for (int p = 0; p < 16; p++) d = fmaf(qr[p], sk[s * 16 + p], d);
        sc[s] = d;
        m = fmaxf(m, d);
    }
    float sum = 0.f;
    float V[16];
#pragma unroll
    for (int p = 0; p < 16; p++) V[p] = 0.f;
#pragma unroll
    for (int s = 0; s < 32; s++) {
        float w = expf((sc[s] - m) * 0.25f);
        sum += w;
#pragma unroll
        for (int p = 0; p < 16; p++) V[p] = fmaf(w, sv[s * 16 + p], V[p]);
    }
    float inv = 1.f / sum;
    uint32_t* op = out + (size_t)n * 2048 + l * 16;
#pragma unroll
    for (int p = 0; p < 16; p++) op[p] = fsplit(V[p] * inv);
}

// ---------------- pwattn2: split output -----------------------------------------
__global__ __launch_bounds__(128) void pwattn2_kernel(
    const float* __restrict__ q, const float* __restrict__ k2,
    const float* __restrict__ v2, uint32_t* __restrict__ out)
{
    int n = blockIdx.x * 4 + (threadIdx.x >> 5);
    int lane = threadIdx.x & 31;
    const float* kp = k2 + (size_t)n * 2048;
    const float* vp = v2 + (size_t)n * 2048;
    float qr[16];
    const float* qp = q + (size_t)n * 512 + lane * 16;
#pragma unroll
    for (int p = 0; p < 16; p++) qr[p] = qp[p];
    float m = -INFINITY;
    for (int s = 0; s < 128; s++) {
        float d = 0.f;
#pragma unroll
        for (int p = 0; p < 16; p++) d = fmaf(qr[p], kp[s * 16 + p], d);
        m = fmaxf(m, d);
    }
    float sum = 0.f;
    float V[16];
#pragma unroll
    for (int p = 0; p < 16; p++) V[p] = 0.f;
    for (int s = 0; s < 128; s++) {
        float d = 0.f;
#pragma unroll
        for (int p = 0; p < 16; p++) d = fmaf(qr[p], kp[s * 16 + p], d);
        float w = expf((d - m) * 0.25f);
        sum += w;
#pragma unroll
        for (int p = 0; p < 16; p++) V[p] = fmaf(w, vp[s * 16 + p], V[p]);
    }
    float inv = 1.f / sum;
    uint32_t* op = out + (size_t)n * 512 + lane * 16;
#pragma unroll
    for (int p = 0; p < 16; p++) op[p] = fsplit(V[p] * inv);
}

// ---------------- layernorm over 2048 -> split output ---------------------------
__global__ __launch_bounds__(256) void ln_kernel(
    const float* __restrict__ in, const float* __restrict__ g,
    const float* __restrict__ b, uint32_t* __restrict__ out)
{
    int n = blockIdx.x;
    int tid = threadIdx.x;
    __shared__ float red[256];
    const float* x = in + (size_t)n * 2048;
    float s = 0.f;
    for (int i = tid; i < 2048; i += 256) s += x[i];
    red[tid] = s; __syncthreads();
    for (int o = 128; o > 0; o >>= 1) { if (tid < o) red[tid] += red[tid + o]; __syncthreads(); }
    float mean = red[0] * (1.f / 2048.f);
    __syncthreads();
    float vs = 0.f;
    for (int i = tid; i < 2048; i += 256) { float d = x[i] - mean; vs += d * d; }
    red[tid] = vs; __syncthreads();
    for (int o = 128; o > 0; o >>= 1) { if (tid < o) red[tid] += red[tid + o]; __syncthreads(); }
    float var = red[0] * (1.f / 2048.f);
    float inv = rsqrtf(var + 1e-5f);
    uint32_t* op = out + (size_t)n * 2048;
    for (int i = tid; i < 2048; i += 256) op[i] = fsplit((x[i] - mean) * inv * g[i] + b[i]);
}

// ---------------- launch --------------------------------------------------------
extern "C" void kernel_launch(void* const* d_in, const int* in_sizes, int n_in,
                              void* d_out, int out_size)
{
    (void)in_sizes; (void)n_in; (void)out_size;
    const float* x     = (const float*)d_in[0];
    const float* aqw   = (const float*)d_in[1];
    const float* aqb   = (const float*)d_in[2];
    const float* akw   = (const float*)d_in[3];
    const float* akb   = (const float*)d_in[4];
    const float* avw   = (const float*)d_in[5];
    const float* avb   = (const float*)d_in[6];
    const float* aow   = (const float*)d_in[7];
    const float* aob   = (const float*)d_in[8];
    const float* encw  = (const float*)d_in[9];
    const float* encb  = (const float*)d_in[10];
    const float* f1qw  = (const float*)d_in[11];
    const float* f1qb  = (const float*)d_in[12];
    const float* f1kw  = (const float*)d_in[13];
    const float* f1kb  = (const float*)d_in[14];
    const float* f1vw  = (const float*)d_in[15];
    const float* f1vb  = (const float*)d_in[16];
    const float* f1ow  = (const float*)d_in[17];
    const float* f1ob  = (const float*)d_in[18];
    const float* f2qw  = (const float*)d_in[19];
    const float* f2qb  = (const float*)d_in[20];
    const float* f2kw  = (const float*)d_in[21];
    const float* f2kb  = (const float*)d_in[22];
    const float* f2vw  = (const float*)d_in[23];
    const float* f2vb  = (const float*)d_in[24];
    const float* f2ow  = (const float*)d_in[25];
    const float* f2ob  = (const float*)d_in[26];
    const float* lng   = (const float*)d_in[27];
    const float* lnb   = (const float*)d_in[28];

    float* out  = (float*)d_out;
    float* Aout = out + (size_t)NROWS * 512;

    float* b512; float* b2048; uint32_t* sps; uint32_t* spb;
    cudaGetSymbolAddress((void**)&b512,  g_buf512);
    cudaGetSymbolAddress((void**)&b2048, g_buf2048);
    cudaGetSymbolAddress((void**)&sps,   g_sp_small);
    cudaGetSymbolAddress((void**)&spb,   g_sp_big);
    uint32_t* wt;
    cudaGetSymbolAddress((void**)&wt,    g_wt);
    const size_t S = (size_t)NROWS * 512;
    const size_t T = (size_t)NROWS * 2048;
    float* qb   = b512;
    float* kb   = b512 + S;
    float* vb   = b512 + 2 * S;
    float* k1   = b512 + 3 * S;
    float* v1   = b512 + 4 * S;
    float* qu2  = b512 + 5 * S;
    float* q1   = b2048;
    float* t1   = b2048 + T;
    float* v2   = b2048 + 2 * T;
    uint32_t* x_sp   = sps;
    uint32_t* att_sp = sps + S;
    uint32_t* zb_sp  = sps + 2 * S;
    uint32_t* y2_sp  = sps + 3 * S;
    uint32_t* Vf1_sp = spb;
    uint32_t* u_sp   = spb + T;

    cudaFuncSetAttribute(mm_gemm_kernel<0,0>, cudaFuncAttributeMaxDynamicSharedMemorySize, MM_SMEM);
    cudaFuncSetAttribute(mm_gemm_kernel<1,0>, cudaFuncAttributeMaxDynamicSharedMemorySize, MM_SMEM);
    cudaFuncSetAttribute(mm_gemm_kernel<3,0>, cudaFuncAttributeMaxDynamicSharedMemorySize, MM_SMEM);
    cudaFuncSetAttribute(mm_gemm_kernel<4,0>, cudaFuncAttributeMaxDynamicSharedMemorySize, MM_SMEM);
    cudaFuncSetAttribute(mm_gemm_kernel<2,1>, cudaFuncAttributeMaxDynamicSharedMemorySize, MM_SMEM);
    cudaFuncSetAttribute(mm_gemm_kernel<0,1>, cudaFuncAttributeMaxDynamicSharedMemorySize, MM_SMEM);

    dim3 blk(256);
    dim3 tb(32, 8);
    dim3 tg512(4, (NROWS + 127) / 128);
    dim3 tg2048(16, (NROWS + 127) / 128);
    dim3 kg(8, (NROWS + 63) / 64);

    // ---- batched weight transpose+split (single launch) ----
    {
        TransArgs ta;
        const float* srcs[11] = {avw, aow, encw, f1qw, f1kw, f1vw, f1ow, f2qw, f2kw, f2vw, f2ow};
        uint32_t offs[11] = {OFF_AV, OFF_AO, OFF_ENC, OFF_F1Q, OFF_F1K, OFF_F1V,
                             OFF_F1O, OFF_F2Q, OFF_F2K, OFF_F2V, OFF_F2O};
        int Ks[11] = {512, 512, 512, 512, 512, 512, 2048, 2048, 2048, 2048, 512};
        int Ns[11] = {512, 512, 512, 2048, 512, 512, 2048, 512, 2048, 2048, 512};
        int acc = 0;
        for (int j = 0; j < 11; j++) {
            ta.job[j].src = srcs[j];
            ta.job[j].dstoff = offs[j];
            ta.job[j].K = Ks[j];
            ta.job[j].N = Ns[j];
            ta.job[j].tstart = acc;
            acc += (Ns[j] >> 5) * (Ks[j] >> 5);
        }
        transpose_split_all<<<acc, tb>>>(ta);           // launch 0
    }
    convert_kernel<<<4096, 256>>>(x, x_sp, (int)S);     // launch 1

    // ---- graph attention ----
    kgemm_kernel<<<kg, blk>>>(x, aqw, aqb, qb, NROWS, 512, 512, 1);                    // 2
    kgemm_kernel<<<kg, blk>>>(x, akw, akb, kb, NROWS, 512, 512, 0);                    // 3
    scores_kernel<<<dim3(11, 11, 512), blk>>>(qb, kb, Aout);                           // 4
    mm_gemm_kernel<1,0><<<tg512, blk, MM_SMEM>>>(x_sp, wt + OFF_AV, avb, nullptr, vb,
                                                 NROWS, 512, 512);                     // 5 (ncu)
    topk_softmax_kernel<<<20544, blk>>>(Aout);                                         // 6
    av_sparse_kernel<<<NROWS, blk>>>(Aout, vb, att_sp);                                // 7
    mm_gemm_kernel<2,1><<<tg512, blk, MM_SMEM>>>(att_sp, wt + OFF_AO, aob, x, zb_sp, NROWS, 512, 512);
    mm_gemm_kernel<0,1><<<tg512, blk, MM_SMEM>>>(zb_sp, wt + OFF_ENC, encb, nullptr, y2_sp, NROWS, 512, 512);

    // ---- ff1 pwattn ----
    mm_gemm_kernel<1,0><<<tg2048, blk, MM_SMEM>>>(y2_sp, wt + OFF_F1Q, f1qb, nullptr, q1, NROWS, 2048, 512);
    mm_gemm_kernel<0,0><<<tg512, blk, MM_SMEM>>>(y2_sp, wt + OFF_F1K, f1kb, nullptr, k1, NROWS, 512, 512);
    mm_gemm_kernel<1,0><<<tg512, blk, MM_SMEM>>>(y2_sp, wt + OFF_F1V, f1vb, nullptr, v1, NROWS, 512, 512);
    pwattn1_kernel<<<NROWS, 128>>>(q1, k1, v1, Vf1_sp);
    mm_gemm_kernel<3,0><<<tg2048, blk, MM_SMEM>>>(Vf1_sp, wt + OFF_F1O, f1ob, q1, t1, NROWS, 2048, 2048);
    ln_kernel<<<NROWS, blk>>>(t1, lng, lnb, u_sp);

    // ---- ff2 pwattn ----
    mm_gemm_kernel<1,0><<<tg512, blk, MM_SMEM>>>(u_sp, wt + OFF_F2Q, f2qb, nullptr, qu2, NROWS, 512, 2048);
    mm_gemm_kernel<0,0><<<tg2048, blk, MM_SMEM>>>(u_sp, wt + OFF_F2K, f2kb, nullptr, q1, NROWS, 2048, 2048);
    mm_gemm_kernel<1,0><<<tg2048, blk, MM_SMEM>>>(u_sp, wt + OFF_F2V, f2vb, nullptr, v2, NROWS, 2048, 2048);
    pwattn2_kernel<<<NROWS / 4, 128>>>(qu2, q1, v2, x_sp);
    mm_gemm_kernel<4,0><<<tg512, blk, MM_SMEM>>>(x_sp, wt + OFF_F2O, f2ob, qu2, out, NROWS, 512, 512);
}

// round 12
// speedup vs baseline: 1.0624x; 1.0108x over previous
#include <cuda_runtime.h>
#include <cuda_bf16.h>
#include <math.h>
#include <stdint.h>

#define NROWS 20544     // B*L = 64*321
#define LL 321
#define DD 512
#define HH 8
#define EE 64
#define NTOPK 10

// ---------------- scratch (allocation-free: __device__ globals) ----------------
__device__ float    g_buf512[6ULL * NROWS * 512];
__device__ float    g_buf2048[4ULL * NROWS * 2048];
__device__ uint32_t g_sp_small[4ULL * NROWS * 512];
__device__ uint32_t g_sp_big[2ULL * NROWS * 2048];
__device__ uint32_t g_wt[16252928];                  // split transposed weights [N,K]

#define OFF_AV   0u
#define OFF_AO   262144u
#define OFF_ENC  524288u
#define OFF_F1Q  786432u
#define OFF_F1K  1835008u
#define OFF_F1V  2097152u
#define OFF_F1O  2359296u
#define OFF_F2Q  6553600u
#define OFF_F2K  7602176u
#define OFF_F2V  11796480u
#define OFF_F2O  15990784u

// ---------------- bf16 split helpers -------------------------------------------
__device__ __forceinline__ uint32_t fsplit(float x) {
    __nv_bfloat16 h = __float2bfloat16(x);
    float hf = __bfloat162float(h);
    __nv_bfloat16 l = __float2bfloat16(x - hf);
    return (uint32_t)__bfloat16_as_ushort(h) | ((uint32_t)__bfloat16_as_ushort(l) << 16);
}
__device__ __forceinline__ void ld_pair(const uint32_t* s, uint32_t& hi, uint32_t& lo) {
    uint2 p = *(const uint2*)s;
    hi = __byte_perm(p.x, p.y, 0x5410);
    lo = __byte_perm(p.x, p.y, 0x7632);
}

// ------------- blocked compensation: Kahan-merge a block partial ---------------
__device__ __forceinline__ void kadd(float p, float& s, float& c) {
    float y = __fsub_rn(p, c);
    float t = __fadd_rn(s, y);
    c = __fsub_rn(__fsub_rn(t, s), y);
    s = t;
}
__device__ __forceinline__ float kfin(float s, float c) { return __fsub_rn(s, c); }

// ==================== batched weight transpose + split =========================
struct TransJob { const float* src; uint32_t dstoff; int K; int N; int tstart; };
struct TransArgs { TransJob job[11]; };

__global__ void transpose_split_all(TransArgs a)
{
    __shared__ float t[32][33];
    int tile = blockIdx.x;
    int ji = 0;
#pragma unroll
    for (int j = 1; j < 11; j++)
        if (tile >= a.job[j].tstart) ji = j;
    const TransJob& J = a.job[ji];
    int local = tile - J.tstart;
    int ntx = J.N >> 5;
    int bx = (local % ntx) * 32, by = (local / ntx) * 32;
    int txi = threadIdx.x, tyi = threadIdx.y;
    const float* src = J.src;
    uint32_t* dst = g_wt + J.dstoff;
#pragma unroll
    for (int j = 0; j < 32; j += 8)
        t[tyi + j][txi] = src[(size_t)(by + tyi + j) * J.N + bx + txi];
    __syncthreads();
#pragma unroll
    for (int j = 0; j < 32; j += 8)
        dst[(size_t)(bx + tyi + j) * J.K + by + txi] = fsplit(t[txi][tyi + j]);
}

__global__ void convert_kernel(const float* __restrict__ in, uint32_t* __restrict__ outp, int n)
{
    for (int i = blockIdx.x * 256 + threadIdx.x; i < n; i += gridDim.x * 256)
        outp[i] = fsplit(in[i]);
}

// ============ bf16x3 mma.sync GEMM: 128x64 tile, 2 CTA/SM, term-major ==========
#define MMP 40
#define MM_A_U32  (128 * MMP)               // 5120 u32
#define MM_B_U32  (64 * MMP)                // 2560 u32
#define MM_STAGE  (MM_A_U32 + MM_B_U32)     // 7680 u32
#define MM_SMEM   (2 * MM_STAGE * 4)        // 61440 bytes

__device__ __forceinline__ void mm_load_stage(
    const uint32_t* __restrict__ A, const uint32_t* __restrict__ Bt,
    int bm, int bn, int M, int K, int k0, uint32_t* st, int tid)
{
    uint32_t a_s, b_s;
    asm("{ .reg .u64 t; cvta.to.shared.u64 t, %1; cvt.u32.u64 %0, t; }" : "=r"(a_s) : "l"(st));
    b_s = a_s + MM_A_U32 * 4;
#pragma unroll
    for (int j = 0; j < 6; j++) {
        int idx = tid + j * 256;
        if (idx < 1024) {               // A: 128 rows x 8 chunks
            int r = idx >> 3, c = idx & 7;
            uint32_t doff = (uint32_t)(r * MMP + c * 4) * 4;
            int grow = bm + r;
            const uint32_t* srcA = A + (size_t)(grow < M ? grow : 0) * K + k0 + c * 4;
            int szA = (grow < M) ? 16 : 0;
            asm volatile("cp.async.ca.shared.global [%0], [%1], 16, %2;"
                         :: "r"(a_s + doff), "l"(srcA), "r"(szA));
        } else {                        // B: 64 rows x 8 chunks
            int idx2 = idx - 1024;
            int r = idx2 >> 3, c = idx2 & 7;
            uint32_t doff = (uint32_t)(r * MMP + c * 4) * 4;
            const uint32_t* srcB = Bt + (size_t)(bn + r) * K + k0 + c * 4;
            asm volatile("cp.async.ca.shared.global [%0], [%1], 16;"
                         :: "r"(b_s + doff), "l"(srcB));
        }
    }
    asm volatile("cp.async.commit_group;" ::: "memory");
}

#define MMA_BF16(acc, a0, a1, a2, a3, b0, b1) \
    asm volatile( \
        "mma.sync.aligned.m16n8k16.row.col.f32.bf16.bf16.f32 " \
        "{%0,%1,%2,%3}, {%4,%5,%6,%7}, {%8,%9}, {%0,%1,%2,%3};" \
        : "+f"((acc)[0]), "+f"((acc)[1]), "+f"((acc)[2]), "+f"((acc)[3]) \
        : "r"(a0), "r"(a1), "r"(a2), "r"(a3), "r"(b0), "r"(b1))

template<int EP, int OM>
__global__ __launch_bounds__(256, 2)
void mm_gemm_kernel(const uint32_t* __restrict__ A, const uint32_t* __restrict__ Bt,
                    const float* __restrict__ bias, const float* __restrict__ res,
                    void* __restrict__ Cv, int M, int N, int K)
{
    extern __shared__ uint32_t sm[];
    const int tid = threadIdx.x;
    const int wid = tid >> 5, lane = tid & 31;
    const int wm = wid >> 1, wn = wid & 1;   // 4 x 2 warps, warp tile 32x32
    const int g = lane >> 2, t = lane & 3;
    const int bm = blockIdx.y * 128, bn = blockIdx.x * 64;

    float acc[2][4][4];
#pragma unroll
    for (int i = 0; i < 2; i++)
#pragma unroll
        for (int j = 0; j < 4; j++)
#pragma unroll
            for (int q = 0; q < 4; q++) acc[i][j][q] = 0.f;

    const int nc = K >> 5;
    mm_load_stage(A, Bt, bm, bn, M, K, 0, sm, tid);

    for (int c = 0; c < nc; c++) {
        if (c + 1 < nc)
            mm_load_stage(A, Bt, bm, bn, M, K, (c + 1) * 32, sm + ((c + 1) & 1) * MM_STAGE, tid);
        if (c + 1 < nc) asm volatile("cp.async.wait_group 1;" ::: "memory");
        else            asm volatile("cp.async.wait_group 0;" ::: "memory");
        __syncthreads();

        const uint32_t* As = sm + (c & 1) * MM_STAGE;
        const uint32_t* Bs = As + MM_A_U32;
#pragma unroll
        for (int ks = 0; ks < 2; ks++) {
            uint32_t ah[2][4], al[2][4], bh[4][2], bl[4][2];
#pragma unroll
            for (int mt = 0; mt < 2; mt++) {
                const uint32_t* base = As + (wm * 32 + mt * 16 + g) * MMP + ks * 16 + 2 * t;
                ld_pair(base,             ah[mt][0], al[mt][0]);
                ld_pair(base + 8 * MMP,   ah[mt][1], al[mt][1]);
                ld_pair(base + 8,         ah[mt][2], al[mt][2]);
                ld_pair(base + 8 * MMP + 8, ah[mt][3], al[mt][3]);
            }
#pragma unroll
            for (int nt = 0; nt < 4; nt++) {
                const uint32_t* base = Bs + (wn * 32 + nt * 8 + g) * MMP + ks * 16 + 2 * t;
                ld_pair(base,     bh[nt][0], bl[nt][0]);
                ld_pair(base + 8, bh[nt][1], bl[nt][1]);
            }
            // term-major: consecutive MMAs hit distinct accumulators
#pragma unroll
            for (int mt = 0; mt < 2; mt++)
#pragma unroll
                for (int nt = 0; nt < 4; nt++)
                    MMA_BF16(acc[mt][nt], ah[mt][0], ah[mt][1], ah[mt][2], ah[mt][3],
                             bl[nt][0], bl[nt][1]);
#pragma unroll
            for (int mt = 0; mt < 2; mt++)
#pragma unroll
                for (int nt = 0; nt < 4; nt++)
                    MMA_BF16(acc[mt][nt], al[mt][0], al[mt][1], al[mt][2], al[mt][3],
                             bh[nt][0], bh[nt][1]);
#pragma unroll
            for (int mt = 0; mt < 2; mt++)
#pragma unroll
                for (int nt = 0; nt < 4; nt++)
                    MMA_BF16(acc[mt][nt], ah[mt][0], ah[mt][1], ah[mt][2], ah[mt][3],
                             bh[nt][0], bh[nt][1]);
        }
        __syncthreads();
    }

    float* Cf = (float*)Cv;
    uint32_t* Cs = (uint32_t*)Cv;
#pragma unroll
    for (int mt = 0; mt < 2; mt++) {
#pragma unroll
        for (int half = 0; half < 2; half++) {
            int row = bm + wm * 32 + mt * 16 + g + half * 8;
            if (row >= M) continue;
#pragma unroll
            for (int nt = 0; nt < 4; nt++) {
                int col = bn + wn * 32 + nt * 8 + t * 2;
                float v0 = acc[mt][nt][half * 2 + 0] + bias[col];
                float v1 = acc[mt][nt][half * 2 + 1] + bias[col + 1];
                if (EP >= 2) {
                    v0 += res[(size_t)row * N + col];
                    v1 += res[(size_t)row * N + col + 1];
                }
                if (EP == 1) { v0 = fmaxf(v0, 0.f); v1 = fmaxf(v1, 0.f); }
                if (EP == 2) { v0 = (v0 > 0.f) ? v0 : 0.5f * v0; v1 = (v1 > 0.f) ? v1 : 0.5f * v1; }
                if (EP == 3) { v0 = (v0 > 0.f) ? v0 : expm1f(v0); v1 = (v1 > 0.f) ? v1 : expm1f(v1); }
                if (OM == 0) {
                    *(float2*)(Cf + (size_t)row * N + col) = make_float2(v0, v1);
                } else {
                    uint2 o = make_uint2(fsplit(v0), fsplit(v1));
                    *(uint2*)(Cs + (size_t)row * N + col) = o;
                }
            }
        }
    }
}

// ---------- blocked-compensated fp32 GEMM (near-exact), q/k feeding top-k ------
__global__ __launch_bounds__(256) void kgemm_kernel(
    const float* __restrict__ A, const float* __restrict__ B,
    const float* __restrict__ bias, float* __restrict__ C,
    int M, int N, int K, int relu)
{
    __shared__ float As[16][68];
    __shared__ float Bs[16][68];
    const int tid = threadIdx.x;
    const int bm = blockIdx.y * 64;
    const int bn = blockIdx.x * 64;
    const int ty = tid >> 4, tx = tid & 15;

    float s[4][4], cc[4][4];
#pragma unroll
    for (int i = 0; i < 4; i++)
#pragma unroll
        for (int j = 0; j < 4; j++) { s[i][j] = 0.f; cc[i][j] = 0.f; }

    const int ar = tid >> 2;
    const int ac = (tid & 3) << 2;
    const int br = tid >> 4;
    const int bc = (tid & 15) << 2;

    for (int k0 = 0; k0 < K; k0 += 16) {
        {
            int grow = bm + ar;
            float4 v = make_float4(0.f, 0.f, 0.f, 0.f);
            if (grow < M) v = *(const float4*)(A + (size_t)grow * K + k0 + ac);
            As[ac + 0][ar] = v.x; As[ac + 1][ar] = v.y;
            As[ac + 2][ar] = v.z; As[ac + 3][ar] = v.w;
        }
        *(float4*)&Bs[br][bc] = *(const float4*)(B + (size_t)(k0 + br) * N + bn + bc);
        __syncthreads();
#pragma unroll
        for (int blkk = 0; blkk < 2; blkk++) {
            float p[4][4];
#pragma unroll
            for (int i = 0; i < 4; i++)
#pragma unroll
                for (int j = 0; j < 4; j++) p[i][j] = 0.f;
#pragma unroll
            for (int kk = blkk * 8; kk < blkk * 8 + 8; kk++) {
                float4 av = *(const float4*)&As[kk][ty * 4];
                float4 bv = *(const float4*)&Bs[kk][tx * 4];
                const float* a = (const float*)&av;
                const float* b = (const float*)&bv;
#pragma unroll
                for (int i = 0; i < 4; i++)
#pragma unroll
                    for (int j = 0; j < 4; j++)
                        p[i][j] = __fmaf_rn(a[i], b[j], p[i][j]);
            }
#pragma unroll
            for (int i = 0; i < 4; i++)
#pragma unroll
                for (int j = 0; j < 4; j++)
                    kadd(p[i][j], s[i][j], cc[i][j]);
        }
        __syncthreads();
    }

#pragma unroll
    for (int i = 0; i < 4; i++) {
        int row = bm + ty * 4 + i;
        if (row < M) {
            float4 o;
            float* ov = (float*)&o;
#pragma unroll
            for (int j = 0; j < 4; j++) {
                float v = __fadd_rn(kfin(s[i][j], cc[i][j]), bias[bn + tx * 4 + j]);
                if (relu) v = fmaxf(v, 0.f);
                ov[j] = v;
            }
            *(float4*)(C + (size_t)row * N + bn + tx * 4) = o;
        }
    }
}

// ---------------- batched scores (blocked-compensated fp32) ---------------------
__global__ __launch_bounds__(256) void scores_kernel(
    const float* __restrict__ q, const float* __restrict__ k, float* __restrict__ out)
{
    int bh = blockIdx.z;
    int b = bh >> 3, h = bh & 7;
    int l0 = blockIdx.y * 32, s0 = blockIdx.x * 32;
    __shared__ float Qs[32][72];
    __shared__ float Ks[32][72];
    int tid = threadIdx.x;
    int r = tid >> 3;
    int c = (tid & 7) * 8;
    {
        int l = l0 + r;
        if (l < LL) {
            const float* src = q + ((size_t)(b * LL + l)) * DD + h * EE + c;
            *(float4*)&Qs[r][c]     = *(const float4*)src;
            *(float4*)&Qs[r][c + 4] = *(const float4*)(src + 4);
        } else {
#pragma unroll
            for (int t = 0; t < 8; t++) Qs[r][c + t] = 0.f;
        }
        int sdx = s0 + r;
        if (sdx < LL) {
            const float* src = k + ((size_t)(b * LL + sdx)) * DD + h * EE + c;
            *(float4*)&Ks[r][c]     = *(const float4*)src;
            *(float4*)&Ks[r][c + 4] = *(const float4*)(src + 4);
        } else {
#pragma unroll
            for (int t = 0; t < 8; t++) Ks[r][c + t] = 0.f;
        }
    }
    __syncthreads();
    int ty = tid >> 4, tx = tid & 15;
    float s00 = 0.f, s01 = 0.f, s10 = 0.f, s11 = 0.f;
    float c00 = 0.f, c01 = 0.f, c10 = 0.f, c11 = 0.f;
#pragma unroll
    for (int blkk = 0; blkk < 8; blkk++) {
        float p00 = 0.f, p01 = 0.f, p10 = 0.f, p11 = 0.f;
#pragma unroll
        for (int kk = blkk * 8; kk < blkk * 8 + 8; kk++) {
            float a0 = Qs[ty * 2 + 0][kk], a1 = Qs[ty * 2 + 1][kk];
            float b0 = Ks[tx * 2 + 0][kk], b1 = Ks[tx * 2 + 1][kk];
            p00 = __fmaf_rn(a0, b0, p00);
            p01 = __fmaf_rn(a0, b1, p01);
            p10 = __fmaf_rn(a1, b0, p10);
            p11 = __fmaf_rn(a1, b1, p11);
        }
        kadd(p00, s00, c00);
        kadd(p01, s01, c01);
        kadd(p10, s10, c10);
        kadd(p11, s11, c11);
    }
    size_t base = (size_t)bh * LL * LL;
    int l_0 = l0 + ty * 2, s_0 = s0 + tx * 2;
    if (l_0 < LL) {
        if (s_0 < LL)     out[base + (size_t)l_0 * LL + s_0]     = kfin(s00, c00);
        if (s_0 + 1 < LL) out[base + (size_t)l_0 * LL + s_0 + 1] = kfin(s01, c01);
    }
    if (l_0 + 1 < LL) {
        if (s_0 < LL)     out[base + (size_t)(l_0 + 1) * LL + s_0]     = kfin(s10, c10);
        if (s_0 + 1 < LL) out[base + (size_t)(l_0 + 1) * LL + s_0 + 1] = kfin(s11, c11);
    }
}

// ---------------- top-k mask + softmax, in place on scores ----------------
__global__ __launch_bounds__(256) void topk_softmax_kernel(float* __restrict__ A)
{
    const int lane = threadIdx.x & 31;
    const int wslot = threadIdx.x >> 5;
    const size_t row = (size_t)blockIdx.x * 8 + wslot;
    __shared__ float sm[8][352];
    float* s = sm[wslot];
    float* rp = A + row * LL;

    float r[11];
#pragma unroll
    for (int j = 0; j < 11; j++) {
        int idx = lane + j * 32;
        float v = (idx < LL) ? rp[idx] : -INFINITY;
        r[j] = v;
        s[idx] = v;
    }
    __syncwarp();

    float kth = 0.f, mmax = 0.f;
    for (int it = 0; it < NTOPK; it++) {
        float lm = -INFINITY;
#pragma unroll
        for (int j = 0; j < 11; j++) lm = fmaxf(lm, s[lane + j * 32]);
        float gm = lm;
#pragma unroll
        for (int o = 16; o > 0; o >>= 1) gm = fmaxf(gm, __shfl_xor_sync(0xffffffffu, gm, o));
        if (it == 0) mmax = gm;
        kth = gm;
        int li = 0x7fffffff;
#pragma unroll
        for (int j = 10; j >= 0; j--) {
            int idx = lane + j * 32;
            if (s[idx] == gm) li = idx;
        }
        int gi = li;
#pragma unroll
        for (int o = 16; o > 0; o >>= 1) gi = min(gi, __shfl_xor_sync(0xffffffffu, gi, o));
        if (li == gi) s[li] = -INFINITY;
        __syncwarp();
    }

    const float scale = 0.125f;
    float e[11];
    float sum = 0.f;
#pragma unroll
    for (int j = 0; j < 11; j++) {
        int idx = lane + j * 32;
        float v = r[j];
        float t = (idx < LL && v >= kth) ? expf((v - mmax) * scale) : 0.f;
        e[j] = t;
        sum += t;
    }
#pragma unroll
    for (int o = 16; o > 0; o >>= 1) sum += __shfl_xor_sync(0xffffffffu, sum, o);
    float inv = 1.f / sum;
#pragma unroll
    for (int j = 0; j < 11; j++) {
        int idx = lane + j * 32;
        if (idx < LL) rp[idx] = e[j] * inv;
    }
}

// ---------------- sparse A @ V -> split output ----------------------------------
__global__ __launch_bounds__(256) void av_sparse_kernel(
    const float* __restrict__ A, const float* __restrict__ v, uint32_t* __restrict__ out)
{
    __shared__ short  sidx[8][24];
    __shared__ float  swt[8][24];
    __shared__ int    scnt[8];
    int blk = blockIdx.x;
    int b = blk / LL, l = blk % LL;
    int tid = threadIdx.x;
    int wid = tid >> 5, lane = tid & 31;

    {
        int h = wid;
        const float* rp = A + ((size_t)(b * 8 + h) * LL + l) * LL;
        int cnt = 0;
#pragma unroll
        for (int j = 0; j < 11; j++) {
            int idx = lane + j * 32;
            float w = (idx < LL) ? rp[idx] : 0.f;
            unsigned m = __ballot_sync(0xffffffffu, w > 0.f);
            if (w > 0.f) {
                int pos = cnt + __popc(m & ((1u << lane) - 1u));
                if (pos < 24) { sidx[h][pos] = (short)idx; swt[h][pos] = w; }
            }
            cnt += __popc(m);
        }
        if (lane == 0) scnt[h] = (cnt < 24) ? cnt : 24;
    }
    __syncthreads();

    const float* vbase = v + (size_t)b * LL * DD;
#pragma unroll
    for (int e0 = 0; e0 < 2; e0++) {
        int e = tid + e0 * 256;
        int h = e >> 6, c2 = e & 63;
        int n2 = scnt[h];
        const float* vp = vbase + h * EE + c2;
        float acc = 0.f;
        for (int j = 0; j < n2; j++)
            acc = __fmaf_rn(swt[h][j], vp[(size_t)sidx[h][j] * DD], acc);
        out[((size_t)(b * LL + l)) * DD + e] = fsplit(acc);
    }
}

// ---------------- pwattn1: split output -----------------------------------------
__global__ __launch_bounds__(128) void pwattn1_kernel(
    const float* __restrict__ q, const float* __restrict__ k,
    const float* __restrict__ v, uint32_t* __restrict__ out)
{
    int n = blockIdx.x;
    int l = threadIdx.x;
    __shared__ float sk[512];
    __shared__ float sv[512];
    int t4 = l * 4;
    *(float4*)&sk[t4] = *(const float4*)(k + (size_t)n * 512 + t4);
    *(float4*)&sv[t4] = *(const float4*)(v + (size_t)n * 512 + t4);
    __syncthreads();
    float qr[16];
    const float* qp = q + (size_t)n * 2048 + l * 16;
#pragma unroll
    for (int p = 0; p < 16; p++) qr[p] = qp[p];
    float sc[32];
    float m = -INFINITY;
#pragma unroll
    for (int s = 0; s < 32; s++) {
        float d = 0.f;
#pragma unroll
        for (int p = 0; p < 16; p++) d = fmaf(qr[p], sk[s * 16 + p], d);
        sc[s] = d;
        m = fmaxf(m, d);
    }
    float sum = 0.f;
    float V[16];
#pragma unroll
    for (int p = 0; p < 16; p++) V[p] = 0.f;
#pragma unroll
    for (int s = 0; s < 32; s++) {
        float w = expf((sc[s] - m) * 0.25f);
        sum += w;
#pragma unroll
        for (int p = 0; p < 16; p++) V[p] = fmaf(w, sv[s * 16 + p], V[p]);
    }
    float inv = 1.f / sum;
    uint32_t* op = out + (size_t)n * 2048 + l * 16;
#pragma unroll
    for (int p = 0; p < 16; p++) op[p] = fsplit(V[p] * inv);
}

// ---------------- pwattn2: split output -----------------------------------------
__global__ __launch_bounds__(128) void pwattn2_kernel(
    const float* __restrict__ q, const float* __restrict__ k2,
    const float* __restrict__ v2, uint32_t* __restrict__ out)
{
    int n = blockIdx.x * 4 + (threadIdx.x >> 5);
    int lane = threadIdx.x & 31;
    const float* kp = k2 + (size_t)n * 2048;
    const float* vp = v2 + (size_t)n * 2048;
    float qr[16];
    const float* qp = q + (size_t)n * 512 + lane * 16;
#pragma unroll
    for (int p = 0; p < 16; p++) qr[p] = qp[p];
    float m = -INFINITY;
    for (int s = 0; s < 128; s++) {
        float d = 0.f;
#pragma unroll
        for (int p = 0; p < 16; p++) d = fmaf(qr[p], kp[s * 16 + p], d);
        m = fmaxf(m, d);
    }
    float sum = 0.f;
    float V[16];
#pragma unroll
    for (int p = 0; p < 16; p++) V[p] = 0.f;
    for (int s = 0; s < 128; s++) {
        float d = 0.f;
#pragma unroll
        for (int p = 0; p < 16; p++) d = fmaf(qr[p], kp[s * 16 + p], d);
        float w = expf((d - m) * 0.25f);
        sum += w;
#pragma unroll
        for (int p = 0; p < 16; p++) V[p] = fmaf(w, vp[s * 16 + p], V[p]);
    }
    float inv = 1.f / sum;
    uint32_t* op = out + (size_t)n * 512 + lane * 16;
#pragma unroll
    for (int p = 0; p < 16; p++) op[p] = fsplit(V[p] * inv);
}

// ---------------- layernorm over 2048 -> split output ---------------------------
__global__ __launch_bounds__(256) void ln_kernel(
    const float* __restrict__ in, const float* __restrict__ g,
    const float* __restrict__ b, uint32_t* __restrict__ out)
{
    int n = blockIdx.x;
    int tid = threadIdx.x;
    __shared__ float red[256];
    const float* x = in + (size_t)n * 2048;
    float s = 0.f;
    for (int i = tid; i < 2048; i += 256) s += x[i];
    red[tid] = s; __syncthreads();
    for (int o = 128; o > 0; o >>= 1) { if (tid < o) red[tid] += red[tid + o]; __syncthreads(); }
    float mean = red[0] * (1.f / 2048.f);
    __syncthreads();
    float vs = 0.f;
    for (int i = tid; i < 2048; i += 256) { float d = x[i] - mean; vs += d * d; }
    red[tid] = vs; __syncthreads();
    for (int o = 128; o > 0; o >>= 1) { if (tid < o) red[tid] += red[tid + o]; __syncthreads(); }
    float var = red[0] * (1.f / 2048.f);
    float inv = rsqrtf(var + 1e-5f);
    uint32_t* op = out + (size_t)n * 2048;
    for (int i = tid; i < 2048; i += 256) op[i] = fsplit((x[i] - mean) * inv * g[i] + b[i]);
}

// ---------------- launch --------------------------------------------------------
extern "C" void kernel_launch(void* const* d_in, const int* in_sizes, int n_in,
                              void* d_out, int out_size)
{
    (void)in_sizes; (void)n_in; (void)out_size;
    const float* x     = (const float*)d_in[0];
    const float* aqw   = (const float*)d_in[1];
    const float* aqb   = (const float*)d_in[2];
    const float* akw   = (const float*)d_in[3];
    const float* akb   = (const float*)d_in[4];
    const float* avw   = (const float*)d_in[5];
    const float* avb   = (const float*)d_in[6];
    const float* aow   = (const float*)d_in[7];
    const float* aob   = (const float*)d_in[8];
    const float* encw  = (const float*)d_in[9];
    const float* encb  = (const float*)d_in[10];
    const float* f1qw  = (const float*)d_in[11];
    const float* f1qb  = (const float*)d_in[12];
    const float* f1kw  = (const float*)d_in[13];
    const float* f1kb  = (const float*)d_in[14];
    const float* f1vw  = (const float*)d_in[15];
    const float* f1vb  = (const float*)d_in[16];
    const float* f1ow  = (const float*)d_in[17];
    const float* f1ob  = (const float*)d_in[18];
    const float* f2qw  = (const float*)d_in[19];
    const float* f2qb  = (const float*)d_in[20];
    const float* f2kw  = (const float*)d_in[21];
    const float* f2kb  = (const float*)d_in[22];
    const float* f2vw  = (const float*)d_in[23];
    const float* f2vb  = (const float*)d_in[24];
    const float* f2ow  = (const float*)d_in[25];
    const float* f2ob  = (const float*)d_in[26];
    const float* lng   = (const float*)d_in[27];
    const float* lnb   = (const float*)d_in[28];

    float* out  = (float*)d_out;
    float* Aout = out + (size_t)NROWS * 512;

    float* b512; float* b2048; uint32_t* sps; uint32_t* spb;
    cudaGetSymbolAddress((void**)&b512,  g_buf512);
    cudaGetSymbolAddress((void**)&b2048, g_buf2048);
    cudaGetSymbolAddress((void**)&sps,   g_sp_small);
    cudaGetSymbolAddress((void**)&spb,   g_sp_big);
    uint32_t* wt;
    cudaGetSymbolAddress((void**)&wt,    g_wt);
    const size_t S = (size_t)NROWS * 512;
    const size_t T = (size_t)NROWS * 2048;
    float* qb   = b512;
    float* kb   = b512 + S;
    float* vb   = b512 + 2 * S;
    float* k1   = b512 + 3 * S;
    float* v1   = b512 + 4 * S;
    float* qu2  = b512 + 5 * S;
    float* q1   = b2048;
    float* t1   = b2048 + T;
    float* v2   = b2048 + 2 * T;
    uint32_t* x_sp   = sps;
    uint32_t* att_sp = sps + S;
    uint32_t* zb_sp  = sps + 2 * S;
    uint32_t* y2_sp  = sps + 3 * S;
    uint32_t* Vf1_sp = spb;
    uint32_t* u_sp   = spb + T;

    cudaFuncSetAttribute(mm_gemm_kernel<0,0>, cudaFuncAttributeMaxDynamicSharedMemorySize, MM_SMEM);
    cudaFuncSetAttribute(mm_gemm_kernel<1,0>, cudaFuncAttributeMaxDynamicSharedMemorySize, MM_SMEM);
    cudaFuncSetAttribute(mm_gemm_kernel<3,0>, cudaFuncAttributeMaxDynamicSharedMemorySize, MM_SMEM);
    cudaFuncSetAttribute(mm_gemm_kernel<4,0>, cudaFuncAttributeMaxDynamicSharedMemorySize, MM_SMEM);
    cudaFuncSetAttribute(mm_gemm_kernel<2,1>, cudaFuncAttributeMaxDynamicSharedMemorySize, MM_SMEM);
    cudaFuncSetAttribute(mm_gemm_kernel<0,1>, cudaFuncAttributeMaxDynamicSharedMemorySize, MM_SMEM);

    dim3 blk(256);
    dim3 tb(32, 8);
    dim3 tg512(8, (NROWS + 127) / 128);     // N=512 / 64-wide tiles
    dim3 tg2048(32, (NROWS + 127) / 128);   // N=2048 / 64-wide tiles
    dim3 kg(8, (NROWS + 63) / 64);

    // ---- batched weight transpose+split (single launch) ----
    {
        TransArgs ta;
        const float* srcs[11] = {avw, aow, encw, f1qw, f1kw, f1vw, f1ow, f2qw, f2kw, f2vw, f2ow};
        uint32_t offs[11] = {OFF_AV, OFF_AO, OFF_ENC, OFF_F1Q, OFF_F1K, OFF_F1V,
                             OFF_F1O, OFF_F2Q, OFF_F2K, OFF_F2V, OFF_F2O};
        int Ks[11] = {512, 512, 512, 512, 512, 512, 2048, 2048, 2048, 2048, 512};
        int Ns[11] = {512, 512, 512, 2048, 512, 512, 2048, 512, 2048, 2048, 512};
        int acc = 0;
        for (int j = 0; j < 11; j++) {
            ta.job[j].src = srcs[j];
            ta.job[j].dstoff = offs[j];
            ta.job[j].K = Ks[j];
            ta.job[j].N = Ns[j];
            ta.job[j].tstart = acc;
            acc += (Ns[j] >> 5) * (Ks[j] >> 5);
        }
        transpose_split_all<<<acc, tb>>>(ta);
    }
    convert_kernel<<<4096, 256>>>(x, x_sp, (int)S);

    // ---- graph attention ----
    kgemm_kernel<<<kg, blk>>>(x, aqw, aqb, qb, NROWS, 512, 512, 1);
    kgemm_kernel<<<kg, blk>>>(x, akw, akb, kb, NROWS, 512, 512, 0);
    scores_kernel<<<dim3(11, 11, 512), blk>>>(qb, kb, Aout);
    mm_gemm_kernel<1,0><<<tg512, blk, MM_SMEM>>>(x_sp, wt + OFF_AV, avb, nullptr, vb,
                                                 NROWS, 512, 512);   // launch 5 (ncu)
    topk_softmax_kernel<<<20544, blk>>>(Aout);
    av_sparse_kernel<<<NROWS, blk>>>(Aout, vb, att_sp);
    mm_gemm_kernel<2,1><<<tg512, blk, MM_SMEM>>>(att_sp, wt + OFF_AO, aob, x, zb_sp, NROWS, 512, 512);
    mm_gemm_kernel<0,1><<<tg512, blk, MM_SMEM>>>(zb_sp, wt + OFF_ENC, encb, nullptr, y2_sp, NROWS, 512, 512);

    // ---- ff1 pwattn ----
    mm_gemm_kernel<1,0><<<tg2048, blk, MM_SMEM>>>(y2_sp, wt + OFF_F1Q, f1qb, nullptr, q1, NROWS, 2048, 512);
    mm_gemm_kernel<0,0><<<tg512, blk, MM_SMEM>>>(y2_sp, wt + OFF_F1K, f1kb, nullptr, k1, NROWS, 512, 512);
    mm_gemm_kernel<1,0><<<tg512, blk, MM_SMEM>>>(y2_sp, wt + OFF_F1V, f1vb, nullptr, v1, NROWS, 512, 512);
    pwattn1_kernel<<<NROWS, 128>>>(q1, k1, v1, Vf1_sp);
    mm_gemm_kernel<3,0><<<tg2048, blk, MM_SMEM>>>(Vf1_sp, wt + OFF_F1O, f1ob, q1, t1, NROWS, 2048, 2048);
    ln_kernel<<<NROWS, blk>>>(t1, lng, lnb, u_sp);

    // ---- ff2 pwattn ----
    mm_gemm_kernel<1,0><<<tg512, blk, MM_SMEM>>>(u_sp, wt + OFF_F2Q, f2qb, nullptr, qu2, NROWS, 512, 2048);
    mm_gemm_kernel<0,0><<<tg2048, blk, MM_SMEM>>>(u_sp, wt + OFF_F2K, f2kb, nullptr, q1, NROWS, 2048, 2048);
    mm_gemm_kernel<1,0><<<tg2048, blk, MM_SMEM>>>(u_sp, wt + OFF_F2V, f2vb, nullptr, v2, NROWS, 2048, 2048);
    pwattn2_kernel<<<NROWS / 4, 128>>>(qu2, q1, v2, x_sp);
    mm_gemm_kernel<4,0><<<tg512, blk, MM_SMEM>>>(x_sp, wt + OFF_F2O, f2ob, qu2, out, NROWS, 512, 512);
}

// round 13
// speedup vs baseline: 1.0839x; 1.0203x over previous
#include <cuda_runtime.h>
#include <cuda_bf16.h>
#include <math.h>
#include <stdint.h>

#define NROWS 20544     // B*L = 64*321
#define LL 321
#define DD 512
#define HH 8
#define EE 64
#define NTOPK 10

// ---------------- scratch (allocation-free: __device__ globals) ----------------
__device__ float    g_buf512[6ULL * NROWS * 512];
__device__ float    g_buf2048[4ULL * NROWS * 2048];
__device__ uint32_t g_sp_small[4ULL * NROWS * 512];
__device__ uint32_t g_sp_big[2ULL * NROWS * 2048];
__device__ uint32_t g_wt[16252928];                  // split transposed weights [N,K]

#define OFF_AV   0u
#define OFF_AO   262144u
#define OFF_ENC  524288u
#define OFF_F1Q  786432u
#define OFF_F1K  1835008u      // f1k + f1v adjacent -> combined [1024,512]
#define OFF_F1V  2097152u
#define OFF_F1O  2359296u
#define OFF_F2Q  6553600u
#define OFF_F2K  7602176u      // f2k + f2v adjacent -> combined [4096,2048]
#define OFF_F2V  11796480u
#define OFF_F2O  15990784u

// ---------------- bf16 split helpers -------------------------------------------
__device__ __forceinline__ uint32_t fsplit(float x) {
    __nv_bfloat16 h = __float2bfloat16(x);
    float hf = __bfloat162float(h);
    __nv_bfloat16 l = __float2bfloat16(x - hf);
    return (uint32_t)__bfloat16_as_ushort(h) | ((uint32_t)__bfloat16_as_ushort(l) << 16);
}
__device__ __forceinline__ void ld_pair(const uint32_t* s, uint32_t& hi, uint32_t& lo) {
    uint2 p = *(const uint2*)s;
    hi = __byte_perm(p.x, p.y, 0x5410);
    lo = __byte_perm(p.x, p.y, 0x7632);
}

// ------------- blocked compensation: Kahan-merge a block partial ---------------
__device__ __forceinline__ void kadd(float p, float& s, float& c) {
    float y = __fsub_rn(p, c);
    float t = __fadd_rn(s, y);
    c = __fsub_rn(__fsub_rn(t, s), y);
    s = t;
}
__device__ __forceinline__ float kfin(float s, float c) { return __fsub_rn(s, c); }

// ==================== batched weight transpose + split =========================
struct TransJob { const float* src; uint32_t dstoff; int K; int N; int tstart; };
struct TransArgs { TransJob job[11]; };

__global__ void transpose_split_all(TransArgs a)
{
    __shared__ float t[32][33];
    int tile = blockIdx.x;
    int ji = 0;
#pragma unroll
    for (int j = 1; j < 11; j++)
        if (tile >= a.job[j].tstart) ji = j;
    const TransJob& J = a.job[ji];
    int local = tile - J.tstart;
    int ntx = J.N >> 5;
    int bx = (local % ntx) * 32, by = (local / ntx) * 32;
    int txi = threadIdx.x, tyi = threadIdx.y;
    const float* src = J.src;
    uint32_t* dst = g_wt + J.dstoff;
#pragma unroll
    for (int j = 0; j < 32; j += 8)
        t[tyi + j][txi] = src[(size_t)(by + tyi + j) * J.N + bx + txi];
    __syncthreads();
#pragma unroll
    for (int j = 0; j < 32; j += 8)
        dst[(size_t)(bx + tyi + j) * J.K + by + txi] = fsplit(t[txi][tyi + j]);
}

__global__ void convert_kernel(const float* __restrict__ in, uint32_t* __restrict__ outp, int n)
{
    for (int i = blockIdx.x * 256 + threadIdx.x; i < n; i += gridDim.x * 256)
        outp[i] = fsplit(in[i]);
}

// ============ bf16x3 mma.sync GEMM: 128x64 tile, 2 CTA/SM, term-major ==========
#define MMP 40
#define MM_A_U32  (128 * MMP)
#define MM_B_U32  (64 * MMP)
#define MM_STAGE  (MM_A_U32 + MM_B_U32)
#define MM_SMEM   (2 * MM_STAGE * 4)        // 61440 bytes

__device__ __forceinline__ void mm_load_stage(
    const uint32_t* __restrict__ A, const uint32_t* __restrict__ Bt,
    int bm, int bn, int M, int K, int k0, uint32_t* st, int tid)
{
    uint32_t a_s, b_s;
    asm("{ .reg .u64 t; cvta.to.shared.u64 t, %1; cvt.u32.u64 %0, t; }" : "=r"(a_s) : "l"(st));
    b_s = a_s + MM_A_U32 * 4;
#pragma unroll
    for (int j = 0; j < 6; j++) {
        int idx = tid + j * 256;
        if (idx < 1024) {
            int r = idx >> 3, c = idx & 7;
            uint32_t doff = (uint32_t)(r * MMP + c * 4) * 4;
            int grow = bm + r;
            const uint32_t* srcA = A + (size_t)(grow < M ? grow : 0) * K + k0 + c * 4;
            int szA = (grow < M) ? 16 : 0;
            asm volatile("cp.async.ca.shared.global [%0], [%1], 16, %2;"
                         :: "r"(a_s + doff), "l"(srcA), "r"(szA));
        } else {
            int idx2 = idx - 1024;
            int r = idx2 >> 3, c = idx2 & 7;
            uint32_t doff = (uint32_t)(r * MMP + c * 4) * 4;
            const uint32_t* srcB = Bt + (size_t)(bn + r) * K + k0 + c * 4;
            asm volatile("cp.async.ca.shared.global [%0], [%1], 16;"
                         :: "r"(b_s + doff), "l"(srcB));
        }
    }
    asm volatile("cp.async.commit_group;" ::: "memory");
}

#define MMA_BF16(acc, a0, a1, a2, a3, b0, b1) \
    asm volatile( \
        "mma.sync.aligned.m16n8k16.row.col.f32.bf16.bf16.f32 " \
        "{%0,%1,%2,%3}, {%4,%5,%6,%7}, {%8,%9}, {%0,%1,%2,%3};" \
        : "+f"((acc)[0]), "+f"((acc)[1]), "+f"((acc)[2]), "+f"((acc)[3]) \
        : "r"(a0), "r"(a1), "r"(a2), "r"(a3), "r"(b0), "r"(b1))

// EP: 0=bias, 1=bias+relu, 2=bias+res+leaky, 3=bias+res+elu, 4=bias+res,
//     5=dual-bias (bias=lower half, res=upper-half bias), relu on upper half
template<int EP, int OM>
__global__ __launch_bounds__(256, 2)
void mm_gemm_kernel(const uint32_t* __restrict__ A, const uint32_t* __restrict__ Bt,
                    const float* __restrict__ bias, const float* __restrict__ res,
                    void* __restrict__ Cv, int M, int N, int K)
{
    extern __shared__ uint32_t sm[];
    const int tid = threadIdx.x;
    const int wid = tid >> 5, lane = tid & 31;
    const int wm = wid >> 1, wn = wid & 1;
    const int g = lane >> 2, t = lane & 3;
    const int bm = blockIdx.y * 128, bn = blockIdx.x * 64;

    float acc[2][4][4];
#pragma unroll
    for (int i = 0; i < 2; i++)
#pragma unroll
        for (int j = 0; j < 4; j++)
#pragma unroll
            for (int q = 0; q < 4; q++) acc[i][j][q] = 0.f;

    const int nc = K >> 5;
    mm_load_stage(A, Bt, bm, bn, M, K, 0, sm, tid);

    for (int c = 0; c < nc; c++) {
        if (c + 1 < nc)
            mm_load_stage(A, Bt, bm, bn, M, K, (c + 1) * 32, sm + ((c + 1) & 1) * MM_STAGE, tid);
        if (c + 1 < nc) asm volatile("cp.async.wait_group 1;" ::: "memory");
        else            asm volatile("cp.async.wait_group 0;" ::: "memory");
        __syncthreads();

        const uint32_t* As = sm + (c & 1) * MM_STAGE;
        const uint32_t* Bs = As + MM_A_U32;
#pragma unroll
        for (int ks = 0; ks < 2; ks++) {
            uint32_t ah[2][4], al[2][4], bh[4][2], bl[4][2];
#pragma unroll
            for (int mt = 0; mt < 2; mt++) {
                const uint32_t* base = As + (wm * 32 + mt * 16 + g) * MMP + ks * 16 + 2 * t;
                ld_pair(base,             ah[mt][0], al[mt][0]);
                ld_pair(base + 8 * MMP,   ah[mt][1], al[mt][1]);
                ld_pair(base + 8,         ah[mt][2], al[mt][2]);
                ld_pair(base + 8 * MMP + 8, ah[mt][3], al[mt][3]);
            }
#pragma unroll
            for (int nt = 0; nt < 4; nt++) {
                const uint32_t* base = Bs + (wn * 32 + nt * 8 + g) * MMP + ks * 16 + 2 * t;
                ld_pair(base,     bh[nt][0], bl[nt][0]);
                ld_pair(base + 8, bh[nt][1], bl[nt][1]);
            }
#pragma unroll
            for (int mt = 0; mt < 2; mt++)
#pragma unroll
                for (int nt = 0; nt < 4; nt++)
                    MMA_BF16(acc[mt][nt], ah[mt][0], ah[mt][1], ah[mt][2], ah[mt][3],
                             bl[nt][0], bl[nt][1]);
#pragma unroll
            for (int mt = 0; mt < 2; mt++)
#pragma unroll
                for (int nt = 0; nt < 4; nt++)
                    MMA_BF16(acc[mt][nt], al[mt][0], al[mt][1], al[mt][2], al[mt][3],
                             bh[nt][0], bh[nt][1]);
#pragma unroll
            for (int mt = 0; mt < 2; mt++)
#pragma unroll
                for (int nt = 0; nt < 4; nt++)
                    MMA_BF16(acc[mt][nt], ah[mt][0], ah[mt][1], ah[mt][2], ah[mt][3],
                             bh[nt][0], bh[nt][1]);
        }
        __syncthreads();
    }

    float* Cf = (float*)Cv;
    uint32_t* Cs = (uint32_t*)Cv;
    const int half = N >> 1;
    const bool upper = (EP == 5) && (bn >= half);          // whole tile one side
    const float* bp = (EP == 5) ? (upper ? res - half : bias) : bias;
#pragma unroll
    for (int mt = 0; mt < 2; mt++) {
#pragma unroll
        for (int hf2 = 0; hf2 < 2; hf2++) {
            int row = bm + wm * 32 + mt * 16 + g + hf2 * 8;
            if (row >= M) continue;
#pragma unroll
            for (int nt = 0; nt < 4; nt++) {
                int col = bn + wn * 32 + nt * 8 + t * 2;
                float v0 = acc[mt][nt][hf2 * 2 + 0] + bp[col];
                float v1 = acc[mt][nt][hf2 * 2 + 1] + bp[col + 1];
                if (EP >= 2 && EP <= 4) {
                    v0 += res[(size_t)row * N + col];
                    v1 += res[(size_t)row * N + col + 1];
                }
                if (EP == 1 || (EP == 5 && upper)) { v0 = fmaxf(v0, 0.f); v1 = fmaxf(v1, 0.f); }
                if (EP == 2) { v0 = (v0 > 0.f) ? v0 : 0.5f * v0; v1 = (v1 > 0.f) ? v1 : 0.5f * v1; }
                if (EP == 3) { v0 = (v0 > 0.f) ? v0 : expm1f(v0); v1 = (v1 > 0.f) ? v1 : expm1f(v1); }
                if (OM == 0) {
                    *(float2*)(Cf + (size_t)row * N + col) = make_float2(v0, v1);
                } else {
                    uint2 o = make_uint2(fsplit(v0), fsplit(v1));
                    *(uint2*)(Cs + (size_t)row * N + col) = o;
                }
            }
        }
    }
}

// ---------- blocked-compensated fp32 GEMM (near-exact), q & k fused (grid.z) ---
__global__ __launch_bounds__(256) void kgemm_qk_kernel(
    const float* __restrict__ A,
    const float* __restrict__ Bq, const float* __restrict__ bq, float* __restrict__ Cq,
    const float* __restrict__ Bk, const float* __restrict__ bk, float* __restrict__ Ck,
    int M, int N, int K)
{
    const float* B  = blockIdx.z ? Bk : Bq;
    const float* bb = blockIdx.z ? bk : bq;
    float* C        = blockIdx.z ? Ck : Cq;
    const int relu  = blockIdx.z ? 0 : 1;

    __shared__ float As[16][68];
    __shared__ float Bs[16][68];
    const int tid = threadIdx.x;
    const int bm = blockIdx.y * 64;
    const int bn = blockIdx.x * 64;
    const int ty = tid >> 4, tx = tid & 15;

    float s[4][4], cc[4][4];
#pragma unroll
    for (int i = 0; i < 4; i++)
#pragma unroll
        for (int j = 0; j < 4; j++) { s[i][j] = 0.f; cc[i][j] = 0.f; }

    const int ar = tid >> 2;
    const int ac = (tid & 3) << 2;
    const int br = tid >> 4;
    const int bc = (tid & 15) << 2;

    for (int k0 = 0; k0 < K; k0 += 16) {
        {
            int grow = bm + ar;
            float4 v = make_float4(0.f, 0.f, 0.f, 0.f);
            if (grow < M) v = *(const float4*)(A + (size_t)grow * K + k0 + ac);
            As[ac + 0][ar] = v.x; As[ac + 1][ar] = v.y;
            As[ac + 2][ar] = v.z; As[ac + 3][ar] = v.w;
        }
        *(float4*)&Bs[br][bc] = *(const float4*)(B + (size_t)(k0 + br) * N + bn + bc);
        __syncthreads();
#pragma unroll
        for (int blkk = 0; blkk < 2; blkk++) {
            float p[4][4];
#pragma unroll
            for (int i = 0; i < 4; i++)
#pragma unroll
                for (int j = 0; j < 4; j++) p[i][j] = 0.f;
#pragma unroll
            for (int kk = blkk * 8; kk < blkk * 8 + 8; kk++) {
                float4 av = *(const float4*)&As[kk][ty * 4];
                float4 bv = *(const float4*)&Bs[kk][tx * 4];
                const float* a = (const float*)&av;
                const float* b = (const float*)&bv;
#pragma unroll
                for (int i = 0; i < 4; i++)
#pragma unroll
                    for (int j = 0; j < 4; j++)
                        p[i][j] = __fmaf_rn(a[i], b[j], p[i][j]);
            }
#pragma unroll
            for (int i = 0; i < 4; i++)
#pragma unroll
                for (int j = 0; j < 4; j++)
                    kadd(p[i][j], s[i][j], cc[i][j]);
        }
        __syncthreads();
    }

#pragma unroll
    for (int i = 0; i < 4; i++) {
        int row = bm + ty * 4 + i;
        if (row < M) {
            float4 o;
            float* ov = (float*)&o;
#pragma unroll
            for (int j = 0; j < 4; j++) {
                float v = __fadd_rn(kfin(s[i][j], cc[i][j]), bb[bn + tx * 4 + j]);
                if (relu) v = fmaxf(v, 0.f);
                ov[j] = v;
            }
            *(float4*)(C + (size_t)row * N + bn + tx * 4) = o;
        }
    }
}

// ---------------- batched scores (blocked-compensated fp32) ---------------------
__global__ __launch_bounds__(256) void scores_kernel(
    const float* __restrict__ q, const float* __restrict__ k, float* __restrict__ out)
{
    int bh = blockIdx.z;
    int b = bh >> 3, h = bh & 7;
    int l0 = blockIdx.y * 32, s0 = blockIdx.x * 32;
    __shared__ float Qs[32][72];
    __shared__ float Ks[32][72];
    int tid = threadIdx.x;
    int r = tid >> 3;
    int c = (tid & 7) * 8;
    {
        int l = l0 + r;
        if (l < LL) {
            const float* src = q + ((size_t)(b * LL + l)) * DD + h * EE + c;
            *(float4*)&Qs[r][c]     = *(const float4*)src;
            *(float4*)&Qs[r][c + 4] = *(const float4*)(src + 4);
        } else {
#pragma unroll
            for (int t = 0; t < 8; t++) Qs[r][c + t] = 0.f;
        }
        int sdx = s0 + r;
        if (sdx < LL) {
            const float* src = k + ((size_t)(b * LL + sdx)) * DD + h * EE + c;
            *(float4*)&Ks[r][c]     = *(const float4*)src;
            *(float4*)&Ks[r][c + 4] = *(const float4*)(src + 4);
        } else {
#pragma unroll
            for (int t = 0; t < 8; t++) Ks[r][c + t] = 0.f;
        }
    }
    __syncthreads();
    int ty = tid >> 4, tx = tid & 15;
    float s00 = 0.f, s01 = 0.f, s10 = 0.f, s11 = 0.f;
    float c00 = 0.f, c01 = 0.f, c10 = 0.f, c11 = 0.f;
#pragma unroll
    for (int blkk = 0; blkk < 8; blkk++) {
        float p00 = 0.f, p01 = 0.f, p10 = 0.f, p11 = 0.f;
#pragma unroll
        for (int kk = blkk * 8; kk < blkk * 8 + 8; kk++) {
            float a0 = Qs[ty * 2 + 0][kk], a1 = Qs[ty * 2 + 1][kk];
            float b0 = Ks[tx * 2 + 0][kk], b1 = Ks[tx * 2 + 1][kk];
            p00 = __fmaf_rn(a0, b0, p00);
            p01 = __fmaf_rn(a0, b1, p01);
            p10 = __fmaf_rn(a1, b0, p10);
            p11 = __fmaf_rn(a1, b1, p11);
        }
        kadd(p00, s00, c00);
        kadd(p01, s01, c01);
        kadd(p10, s10, c10);
        kadd(p11, s11, c11);
    }
    size_t base = (size_t)bh * LL * LL;
    int l_0 = l0 + ty * 2, s_0 = s0 + tx * 2;
    if (l_0 < LL) {
        if (s_0 < LL)     out[base + (size_t)l_0 * LL + s_0]     = kfin(s00, c00);
        if (s_0 + 1 < LL) out[base + (size_t)l_0 * LL + s_0 + 1] = kfin(s01, c01);
    }
    if (l_0 + 1 < LL) {
        if (s_0 < LL)     out[base + (size_t)(l_0 + 1) * LL + s_0]     = kfin(s10, c10);
        if (s_0 + 1 < LL) out[base + (size_t)(l_0 + 1) * LL + s_0 + 1] = kfin(s11, c11);
    }
}

// ---------------- top-k mask + softmax, in place on scores ----------------
__global__ __launch_bounds__(256) void topk_softmax_kernel(float* __restrict__ A)
{
    const int lane = threadIdx.x & 31;
    const int wslot = threadIdx.x >> 5;
    const size_t row = (size_t)blockIdx.x * 8 + wslot;
    __shared__ float sm[8][352];
    float* s = sm[wslot];
    float* rp = A + row * LL;

    float r[11];
#pragma unroll
    for (int j = 0; j < 11; j++) {
        int idx = lane + j * 32;
        float v = (idx < LL) ? rp[idx] : -INFINITY;
        r[j] = v;
        s[idx] = v;
    }
    __syncwarp();

    float kth = 0.f, mmax = 0.f;
    for (int it = 0; it < NTOPK; it++) {
        float lm = -INFINITY;
#pragma unroll
        for (int j = 0; j < 11; j++) lm = fmaxf(lm, s[lane + j * 32]);
        float gm = lm;
#pragma unroll
        for (int o = 16; o > 0; o >>= 1) gm = fmaxf(gm, __shfl_xor_sync(0xffffffffu, gm, o));
        if (it == 0) mmax = gm;
        kth = gm;
        int li = 0x7fffffff;
#pragma unroll
        for (int j = 10; j >= 0; j--) {
            int idx = lane + j * 32;
            if (s[idx] == gm) li = idx;
        }
        int gi = li;
#pragma unroll
        for (int o = 16; o > 0; o >>= 1) gi = min(gi, __shfl_xor_sync(0xffffffffu, gi, o));
        if (li == gi) s[li] = -INFINITY;
        __syncwarp();
    }

    const float scale = 0.125f;
    float e[11];
    float sum = 0.f;
#pragma unroll
    for (int j = 0; j < 11; j++) {
        int idx = lane + j * 32;
        float v = r[j];
        float t = (idx < LL && v >= kth) ? expf((v - mmax) * scale) : 0.f;
        e[j] = t;
        sum += t;
    }
#pragma unroll
    for (int o = 16; o > 0; o >>= 1) sum += __shfl_xor_sync(0xffffffffu, sum, o);
    float inv = 1.f / sum;
#pragma unroll
    for (int j = 0; j < 11; j++) {
        int idx = lane + j * 32;
        if (idx < LL) rp[idx] = e[j] * inv;
    }
}

// ---------------- sparse A @ V -> split output ----------------------------------
__global__ __launch_bounds__(256) void av_sparse_kernel(
    const float* __restrict__ A, const float* __restrict__ v, uint32_t* __restrict__ out)
{
    __shared__ short  sidx[8][24];
    __shared__ float  swt[8][24];
    __shared__ int    scnt[8];
    int blk = blockIdx.x;
    int b = blk / LL, l = blk % LL;
    int tid = threadIdx.x;
    int wid = tid >> 5, lane = tid & 31;

    {
        int h = wid;
        const float* rp = A + ((size_t)(b * 8 + h) * LL + l) * LL;
        int cnt = 0;
#pragma unroll
        for (int j = 0; j < 11; j++) {
            int idx = lane + j * 32;
            float w = (idx < LL) ? rp[idx] : 0.f;
            unsigned m = __ballot_sync(0xffffffffu, w > 0.f);
            if (w > 0.f) {
                int pos = cnt + __popc(m & ((1u << lane) - 1u));
                if (pos < 24) { sidx[h][pos] = (short)idx; swt[h][pos] = w; }
            }
            cnt += __popc(m);
        }
        if (lane == 0) scnt[h] = (cnt < 24) ? cnt : 24;
    }
    __syncthreads();

    const float* vbase = v + (size_t)b * LL * DD;
#pragma unroll
    for (int e0 = 0; e0 < 2; e0++) {
        int e = tid + e0 * 256;
        int h = e >> 6, c2 = e & 63;
        int n2 = scnt[h];
        const float* vp = vbase + h * EE + c2;
        float acc = 0.f;
        for (int j = 0; j < n2; j++)
            acc = __fmaf_rn(swt[h][j], vp[(size_t)sidx[h][j] * DD], acc);
        out[((size_t)(b * LL + l)) * DD + e] = fsplit(acc);
    }
}

// ---------------- pwattn1 (combined k|v buffer, row stride 1024) ----------------
__global__ __launch_bounds__(128) void pwattn1_kernel(
    const float* __restrict__ q, const float* __restrict__ kv,
    uint32_t* __restrict__ out)
{
    int n = blockIdx.x;
    int l = threadIdx.x;
    __shared__ float sk[512];
    __shared__ float sv[512];
    int t4 = l * 4;
    const float* kvp = kv + (size_t)n * 1024;
    *(float4*)&sk[t4] = *(const float4*)(kvp + t4);
    *(float4*)&sv[t4] = *(const float4*)(kvp + 512 + t4);
    __syncthreads();
    float qr[16];
    const float* qp = q + (size_t)n * 2048 + l * 16;
#pragma unroll
    for (int p = 0; p < 16; p++) qr[p] = qp[p];
    float sc[32];
    float m = -INFINITY;
#pragma unroll
    for (int s = 0; s < 32; s++) {
        float d = 0.f;
#pragma unroll
        for (int p = 0; p < 16; p++) d = fmaf(qr[p], sk[s * 16 + p], d);
        sc[s] = d;
        m = fmaxf(m, d);
    }
    float sum = 0.f;
    float V[16];
#pragma unroll
    for (int p = 0; p < 16; p++) V[p] = 0.f;
#pragma unroll
    for (int s = 0; s < 32; s++) {
        float w = expf((sc[s] - m) * 0.25f);
        sum += w;
#pragma unroll
        for (int p = 0; p < 16; p++) V[p] = fmaf(w, sv[s * 16 + p], V[p]);
    }
    float inv = 1.f / sum;
    uint32_t* op = out + (size_t)n * 2048 + l * 16;
#pragma unroll
    for (int p = 0; p < 16; p++) op[p] = fsplit(V[p] * inv);
}

// ------- pwattn2: combined k|v buffer (stride 4096), single-pass online --------
__global__ __launch_bounds__(128) void pwattn2_kernel(
    const float* __restrict__ q, const float* __restrict__ kv2,
    uint32_t* __restrict__ out)
{
    int n = blockIdx.x * 4 + (threadIdx.x >> 5);
    int lane = threadIdx.x & 31;
    const float* kp = kv2 + (size_t)n * 4096;
    const float* vp = kp + 2048;
    float qr[16];
    const float* qp = q + (size_t)n * 512 + lane * 16;
#pragma unroll
    for (int p = 0; p < 16; p++) qr[p] = qp[p];
    float m = -INFINITY, sum = 0.f;
    float V[16];
#pragma unroll
    for (int p = 0; p < 16; p++) V[p] = 0.f;
    for (int s = 0; s < 128; s++) {
        float d = 0.f;
#pragma unroll
        for (int p = 0; p < 16; p++) d = fmaf(qr[p], kp[s * 16 + p], d);
        if (d > m) {
            float f = expf((m - d) * 0.25f);   // 0 on first iteration (m=-inf)
            sum *= f;
#pragma unroll
            for (int p = 0; p < 16; p++) V[p] *= f;
            m = d;
        }
        float w = expf((d - m) * 0.25f);
        sum += w;
#pragma unroll
        for (int p = 0; p < 16; p++) V[p] = fmaf(w, vp[s * 16 + p], V[p]);
    }
    float inv = 1.f / sum;
    uint32_t* op = out + (size_t)n * 512 + lane * 16;
#pragma unroll
    for (int p = 0; p < 16; p++) op[p] = fsplit(V[p] * inv);
}

// ---------------- layernorm over 2048 -> split output ---------------------------
__global__ __launch_bounds__(256) void ln_kernel(
    const float* __restrict__ in, const float* __restrict__ g,
    const float* __restrict__ b, uint32_t* __restrict__ out)
{
    int n = blockIdx.x;
    int tid = threadIdx.x;
    __shared__ float red[256];
    const float* x = in + (size_t)n * 2048;
    float s = 0.f;
    for (int i = tid; i < 2048; i += 256) s += x[i];
    red[tid] = s; __syncthreads();
    for (int o = 128; o > 0; o >>= 1) { if (tid < o) red[tid] += red[tid + o]; __syncthreads(); }
    float mean = red[0] * (1.f / 2048.f);
    __syncthreads();
    float vs = 0.f;
    for (int i = tid; i < 2048; i += 256) { float d = x[i] - mean; vs += d * d; }
    red[tid] = vs; __syncthreads();
    for (int o = 128; o > 0; o >>= 1) { if (tid < o) red[tid] += red[tid + o]; __syncthreads(); }
    float var = red[0] * (1.f / 2048.f);
    float inv = rsqrtf(var + 1e-5f);
    uint32_t* op = out + (size_t)n * 2048;
    for (int i = tid; i < 2048; i += 256) op[i] = fsplit((x[i] - mean) * inv * g[i] + b[i]);
}

// ---------------- launch --------------------------------------------------------
extern "C" void kernel_launch(void* const* d_in, const int* in_sizes, int n_in,
                              void* d_out, int out_size)
{
    (void)in_sizes; (void)n_in; (void)out_size;
    const float* x     = (const float*)d_in[0];
    const float* aqw   = (const float*)d_in[1];
    const float* aqb   = (const float*)d_in[2];
    const float* akw   = (const float*)d_in[3];
    const float* akb   = (const float*)d_in[4];
    const float* avw   = (const float*)d_in[5];
    const float* avb   = (const float*)d_in[6];
    const float* aow   = (const float*)d_in[7];
    const float* aob   = (const float*)d_in[8];
    const float* encw  = (const float*)d_in[9];
    const float* encb  = (const float*)d_in[10];
    const float* f1qw  = (const float*)d_in[11];
    const float* f1qb  = (const float*)d_in[12];
    const float* f1kw  = (const float*)d_in[13];
    const float* f1kb  = (const float*)d_in[14];
    const float* f1vw  = (const float*)d_in[15];
    const float* f1vb  = (const float*)d_in[16];
    const float* f1ow  = (const float*)d_in[17];
    const float* f1ob  = (const float*)d_in[18];
    const float* f2qw  = (const float*)d_in[19];
    const float* f2qb  = (const float*)d_in[20];
    const float* f2kw  = (const float*)d_in[21];
    const float* f2kb  = (const float*)d_in[22];
    const float* f2vw  = (const float*)d_in[23];
    const float* f2vb  = (const float*)d_in[24];
    const float* f2ow  = (const float*)d_in[25];
    const float* f2ob  = (const float*)d_in[26];
    const float* lng   = (const float*)d_in[27];
    const float* lnb   = (const float*)d_in[28];

    float* out  = (float*)d_out;
    float* Aout = out + (size_t)NROWS * 512;

    float* b512; float* b2048; uint32_t* sps; uint32_t* spb; uint32_t* wt;
    cudaGetSymbolAddress((void**)&b512,  g_buf512);
    cudaGetSymbolAddress((void**)&b2048, g_buf2048);
    cudaGetSymbolAddress((void**)&sps,   g_sp_small);
    cudaGetSymbolAddress((void**)&spb,   g_sp_big);
    cudaGetSymbolAddress((void**)&wt,    g_wt);
    const size_t S = (size_t)NROWS * 512;
    const size_t T = (size_t)NROWS * 2048;
    float* qb   = b512;
    float* kb   = b512 + S;
    float* vb   = b512 + 2 * S;
    float* kv1  = b512 + 3 * S;      // [NROWS,1024] combined k1|v1
    float* qu2  = b512 + 5 * S;
    float* q1   = b2048;
    float* t1   = b2048 + T;
    float* kv2  = b2048 + 2 * T;     // [NROWS,4096] combined k2|v2
    uint32_t* x_sp   = sps;
    uint32_t* att_sp = sps + S;
    uint32_t* zb_sp  = sps + 2 * S;
    uint32_t* y2_sp  = sps + 3 * S;
    uint32_t* Vf1_sp = spb;
    uint32_t* u_sp   = spb + T;

    cudaFuncSetAttribute(mm_gemm_kernel<0,1>, cudaFuncAttributeMaxDynamicSharedMemorySize, MM_SMEM);
    cudaFuncSetAttribute(mm_gemm_kernel<1,0>, cudaFuncAttributeMaxDynamicSharedMemorySize, MM_SMEM);
    cudaFuncSetAttribute(mm_gemm_kernel<2,1>, cudaFuncAttributeMaxDynamicSharedMemorySize, MM_SMEM);
    cudaFuncSetAttribute(mm_gemm_kernel<3,0>, cudaFuncAttributeMaxDynamicSharedMemorySize, MM_SMEM);
    cudaFuncSetAttribute(mm_gemm_kernel<4,0>, cudaFuncAttributeMaxDynamicSharedMemorySize, MM_SMEM);
    cudaFuncSetAttribute(mm_gemm_kernel<5,0>, cudaFuncAttributeMaxDynamicSharedMemorySize, MM_SMEM);

    static cudaStream_t s2 = nullptr;
    static cudaEvent_t evF = nullptr, evJ = nullptr;
    if (!s2) {
        cudaStreamCreateWithFlags(&s2, cudaStreamNonBlocking);
        cudaEventCreateWithFlags(&evF, cudaEventDisableTiming);
        cudaEventCreateWithFlags(&evJ, cudaEventDisableTiming);
    }

    dim3 blk(256);
    dim3 tb(32, 8);
    dim3 tg512(8, (NROWS + 127) / 128);
    dim3 tg1024(16, (NROWS + 127) / 128);
    dim3 tg2048(32, (NROWS + 127) / 128);
    dim3 tg4096(64, (NROWS + 127) / 128);
    dim3 kg(8, (NROWS + 63) / 64, 2);

    // ===== fork: A-path (q,k,scores,topk) on s2 ∥ transpose/convert/av on main ==
    cudaEventRecord(evF, 0);
    cudaStreamWaitEvent(s2, evF, 0);

    kgemm_qk_kernel<<<kg, blk, 0, s2>>>(x, aqw, aqb, qb, akw, akb, kb, NROWS, 512, 512);
    scores_kernel<<<dim3(11, 11, 512), blk, 0, s2>>>(qb, kb, Aout);
    topk_softmax_kernel<<<20544, blk, 0, s2>>>(Aout);
    cudaEventRecord(evJ, s2);

    {
        TransArgs ta;
        const float* srcs[11] = {avw, aow, encw, f1qw, f1kw, f1vw, f1ow, f2qw, f2kw, f2vw, f2ow};
        uint32_t offs[11] = {OFF_AV, OFF_AO, OFF_ENC, OFF_F1Q, OFF_F1K, OFF_F1V,
                             OFF_F1O, OFF_F2Q, OFF_F2K, OFF_F2V, OFF_F2O};
        int Ks[11] = {512, 512, 512, 512, 512, 512, 2048, 2048, 2048, 2048, 512};
        int Ns[11] = {512, 512, 512, 2048, 512, 512, 2048, 512, 2048, 2048, 512};
        int acc = 0;
        for (int j = 0; j < 11; j++) {
            ta.job[j].src = srcs[j];
            ta.job[j].dstoff = offs[j];
            ta.job[j].K = Ks[j];
            ta.job[j].N = Ns[j];
            ta.job[j].tstart = acc;
            acc += (Ns[j] >> 5) * (Ks[j] >> 5);
        }
        transpose_split_all<<<acc, tb>>>(ta);
    }
    convert_kernel<<<4096, 256>>>(x, x_sp, (int)S);
    mm_gemm_kernel<1,0><<<tg512, blk, MM_SMEM>>>(x_sp, wt + OFF_AV, avb, nullptr, vb, NROWS, 512, 512);

    cudaStreamWaitEvent(0, evJ, 0);   // join
    // ===========================================================================

    av_sparse_kernel<<<NROWS, blk>>>(Aout, vb, att_sp);
    mm_gemm_kernel<2,1><<<tg512, blk, MM_SMEM>>>(att_sp, wt + OFF_AO, aob, x, zb_sp, NROWS, 512, 512);
    mm_gemm_kernel<0,1><<<tg512, blk, MM_SMEM>>>(zb_sp, wt + OFF_ENC, encb, nullptr, y2_sp, NROWS, 512, 512);

    // ---- ff1 pwattn ----
    mm_gemm_kernel<1,0><<<tg2048, blk, MM_SMEM>>>(y2_sp, wt + OFF_F1Q, f1qb, nullptr, q1, NROWS, 2048, 512);
    mm_gemm_kernel<5,0><<<tg1024, blk, MM_SMEM>>>(y2_sp, wt + OFF_F1K, f1kb, f1vb, kv1, NROWS, 1024, 512);
    pwattn1_kernel<<<NROWS, 128>>>(q1, kv1, Vf1_sp);
    mm_gemm_kernel<3,0><<<tg2048, blk, MM_SMEM>>>(Vf1_sp, wt + OFF_F1O, f1ob, q1, t1, NROWS, 2048, 2048);
    ln_kernel<<<NROWS, blk>>>(t1, lng, lnb, u_sp);

    // ---- ff2 pwattn ----
    mm_gemm_kernel<1,0><<<tg512, blk, MM_SMEM>>>(u_sp, wt + OFF_F2Q, f2qb, nullptr, qu2, NROWS, 512, 2048);
    mm_gemm_kernel<5,0><<<tg4096, blk, MM_SMEM>>>(u_sp, wt + OFF_F2K, f2kb, f2vb, kv2, NROWS, 4096, 2048);
    pwattn2_kernel<<<NROWS / 4, 128>>>(qu2, kv2, x_sp);
    mm_gemm_kernel<4,0><<<tg512, blk, MM_SMEM>>>(x_sp, wt + OFF_F2O, f2ob, qu2, out, NROWS, 512, 512);
}

// round 14
// speedup vs baseline: 1.0883x; 1.0041x over previous
#include <cuda_runtime.h>
#include <cuda_bf16.h>
#include <math.h>
#include <stdint.h>

#define NROWS 20544     // B*L = 64*321
#define LL 321
#define DD 512
#define HH 8
#define EE 64
#define NTOPK 10

// ---------------- scratch (allocation-free: __device__ globals) ----------------
__device__ float    g_buf512[6ULL * NROWS * 512];
__device__ float    g_buf2048[4ULL * NROWS * 2048];
__device__ uint32_t g_sp_small[4ULL * NROWS * 512];
__device__ uint32_t g_sp_big[2ULL * NROWS * 2048];
__device__ uint32_t g_wt[16252928];                  // split transposed weights [N,K]

#define OFF_AV   0u
#define OFF_AO   262144u
#define OFF_ENC  524288u
#define OFF_F1Q  786432u
#define OFF_F1K  1835008u
#define OFF_F1V  2097152u
#define OFF_F1O  2359296u
#define OFF_F2Q  6553600u
#define OFF_F2K  7602176u
#define OFF_F2V  11796480u
#define OFF_F2O  15990784u

// ---------------- bf16 split helpers -------------------------------------------
__device__ __forceinline__ uint32_t fsplit(float x) {
    __nv_bfloat16 h = __float2bfloat16(x);
    float hf = __bfloat162float(h);
    __nv_bfloat16 l = __float2bfloat16(x - hf);
    return (uint32_t)__bfloat16_as_ushort(h) | ((uint32_t)__bfloat16_as_ushort(l) << 16);
}
__device__ __forceinline__ void ld_pair(const uint32_t* s, uint32_t& hi, uint32_t& lo) {
    uint2 p = *(const uint2*)s;
    hi = __byte_perm(p.x, p.y, 0x5410);
    lo = __byte_perm(p.x, p.y, 0x7632);
}

// ------------- blocked compensation: Kahan-merge a block partial ---------------
__device__ __forceinline__ void kadd(float p, float& s, float& c) {
    float y = __fsub_rn(p, c);
    float t = __fadd_rn(s, y);
    c = __fsub_rn(__fsub_rn(t, s), y);
    s = t;
}
__device__ __forceinline__ float kfin(float s, float c) { return __fsub_rn(s, c); }

// ==================== batched weight transpose + split =========================
struct TransJob { const float* src; uint32_t dstoff; int K; int N; int tstart; };
struct TransArgs { TransJob job[11]; };

__global__ void transpose_split_all(TransArgs a)
{
    __shared__ float t[32][33];
    int tile = blockIdx.x;
    int ji = 0;
#pragma unroll
    for (int j = 1; j < 11; j++)
        if (tile >= a.job[j].tstart) ji = j;
    const TransJob& J = a.job[ji];
    int local = tile - J.tstart;
    int ntx = J.N >> 5;
    int bx = (local % ntx) * 32, by = (local / ntx) * 32;
    int txi = threadIdx.x, tyi = threadIdx.y;
    const float* src = J.src;
    uint32_t* dst = g_wt + J.dstoff;
#pragma unroll
    for (int j = 0; j < 32; j += 8)
        t[tyi + j][txi] = src[(size_t)(by + tyi + j) * J.N + bx + txi];
    __syncthreads();
#pragma unroll
    for (int j = 0; j < 32; j += 8)
        dst[(size_t)(bx + tyi + j) * J.K + by + txi] = fsplit(t[txi][tyi + j]);
}

__global__ void convert_kernel(const float* __restrict__ in, uint32_t* __restrict__ outp, int n)
{
    for (int i = blockIdx.x * 256 + threadIdx.x; i < n; i += gridDim.x * 256)
        outp[i] = fsplit(in[i]);
}

// ============ bf16x3 mma.sync GEMM: 128x64 tile, 2 CTA/SM, term-major ==========
#define MMP 40
#define MM_A_U32  (128 * MMP)
#define MM_B_U32  (64 * MMP)
#define MM_STAGE  (MM_A_U32 + MM_B_U32)
#define MM_SMEM   (2 * MM_STAGE * 4)        // 61440 bytes

__device__ __forceinline__ void mm_load_stage(
    const uint32_t* __restrict__ A, const uint32_t* __restrict__ Bt,
    int bm, int bn, int M, int K, int k0, uint32_t* st, int tid)
{
    uint32_t a_s, b_s;
    asm("{ .reg .u64 t; cvta.to.shared.u64 t, %1; cvt.u32.u64 %0, t; }" : "=r"(a_s) : "l"(st));
    b_s = a_s + MM_A_U32 * 4;
#pragma unroll
    for (int j = 0; j < 6; j++) {
        int idx = tid + j * 256;
        if (idx < 1024) {
            int r = idx >> 3, c = idx & 7;
            uint32_t doff = (uint32_t)(r * MMP + c * 4) * 4;
            int grow = bm + r;
            const uint32_t* srcA = A + (size_t)(grow < M ? grow : 0) * K + k0 + c * 4;
            int szA = (grow < M) ? 16 : 0;
            asm volatile("cp.async.ca.shared.global [%0], [%1], 16, %2;"
                         :: "r"(a_s + doff), "l"(srcA), "r"(szA));
        } else {
            int idx2 = idx - 1024;
            int r = idx2 >> 3, c = idx2 & 7;
            uint32_t doff = (uint32_t)(r * MMP + c * 4) * 4;
            const uint32_t* srcB = Bt + (size_t)(bn + r) * K + k0 + c * 4;
            asm volatile("cp.async.ca.shared.global [%0], [%1], 16;"
                         :: "r"(b_s + doff), "l"(srcB));
        }
    }
    asm volatile("cp.async.commit_group;" ::: "memory");
}

#define MMA_BF16(acc, a0, a1, a2, a3, b0, b1) \
    asm volatile( \
        "mma.sync.aligned.m16n8k16.row.col.f32.bf16.bf16.f32 " \
        "{%0,%1,%2,%3}, {%4,%5,%6,%7}, {%8,%9}, {%0,%1,%2,%3};" \
        : "+f"((acc)[0]), "+f"((acc)[1]), "+f"((acc)[2]), "+f"((acc)[3]) \
        : "r"(a0), "r"(a1), "r"(a2), "r"(a3), "r"(b0), "r"(b1))

// EP: 0=bias, 1=bias+relu, 2=bias+res+leaky, 3=bias+res+elu, 4=bias+res,
//     5=dual-bias (bias=lower half, res=upper-half bias), relu on upper half
template<int EP, int OM>
__global__ __launch_bounds__(256, 2)
void mm_gemm_kernel(const uint32_t* __restrict__ A, const uint32_t* __restrict__ Bt,
                    const float* __restrict__ bias, const float* __restrict__ res,
                    void* __restrict__ Cv, int M, int N, int K)
{
    extern __shared__ uint32_t sm[];
    const int tid = threadIdx.x;
    const int wid = tid >> 5, lane = tid & 31;
    const int wm = wid >> 1, wn = wid & 1;
    const int g = lane >> 2, t = lane & 3;
    const int bm = blockIdx.y * 128, bn = blockIdx.x * 64;

    float acc[2][4][4];
#pragma unroll
    for (int i = 0; i < 2; i++)
#pragma unroll
        for (int j = 0; j < 4; j++)
#pragma unroll
            for (int q = 0; q < 4; q++) acc[i][j][q] = 0.f;

    const int nc = K >> 5;
    mm_load_stage(A, Bt, bm, bn, M, K, 0, sm, tid);

    for (int c = 0; c < nc; c++) {
        if (c + 1 < nc)
            mm_load_stage(A, Bt, bm, bn, M, K, (c + 1) * 32, sm + ((c + 1) & 1) * MM_STAGE, tid);
        if (c + 1 < nc) asm volatile("cp.async.wait_group 1;" ::: "memory");
        else            asm volatile("cp.async.wait_group 0;" ::: "memory");
        __syncthreads();

        const uint32_t* As = sm + (c & 1) * MM_STAGE;
        const uint32_t* Bs = As + MM_A_U32;
#pragma unroll
        for (int ks = 0; ks < 2; ks++) {
            uint32_t ah[2][4], al[2][4], bh[4][2], bl[4][2];
#pragma unroll
            for (int mt = 0; mt < 2; mt++) {
                const uint32_t* base = As + (wm * 32 + mt * 16 + g) * MMP + ks * 16 + 2 * t;
                ld_pair(base,             ah[mt][0], al[mt][0]);
                ld_pair(base + 8 * MMP,   ah[mt][1], al[mt][1]);
                ld_pair(base + 8,         ah[mt][2], al[mt][2]);
                ld_pair(base + 8 * MMP + 8, ah[mt][3], al[mt][3]);
            }
#pragma unroll
            for (int nt = 0; nt < 4; nt++) {
                const uint32_t* base = Bs + (wn * 32 + nt * 8 + g) * MMP + ks * 16 + 2 * t;
                ld_pair(base,     bh[nt][0], bl[nt][0]);
                ld_pair(base + 8, bh[nt][1], bl[nt][1]);
            }
#pragma unroll
            for (int mt = 0; mt < 2; mt++)
#pragma unroll
                for (int nt = 0; nt < 4; nt++)
                    MMA_BF16(acc[mt][nt], ah[mt][0], ah[mt][1], ah[mt][2], ah[mt][3],
                             bl[nt][0], bl[nt][1]);
#pragma unroll
            for (int mt = 0; mt < 2; mt++)
#pragma unroll
                for (int nt = 0; nt < 4; nt++)
                    MMA_BF16(acc[mt][nt], al[mt][0], al[mt][1], al[mt][2], al[mt][3],
                             bh[nt][0], bh[nt][1]);
#pragma unroll
            for (int mt = 0; mt < 2; mt++)
#pragma unroll
                for (int nt = 0; nt < 4; nt++)
                    MMA_BF16(acc[mt][nt], ah[mt][0], ah[mt][1], ah[mt][2], ah[mt][3],
                             bh[nt][0], bh[nt][1]);
        }
        __syncthreads();
    }

    float* Cf = (float*)Cv;
    uint32_t* Cs = (uint32_t*)Cv;
    const int half = N >> 1;
    const bool upper = (EP == 5) && (bn >= half);
    const float* bp = (EP == 5) ? (upper ? res - half : bias) : bias;
#pragma unroll
    for (int mt = 0; mt < 2; mt++) {
#pragma unroll
        for (int hf2 = 0; hf2 < 2; hf2++) {
            int row = bm + wm * 32 + mt * 16 + g + hf2 * 8;
            if (row >= M) continue;
#pragma unroll
            for (int nt = 0; nt < 4; nt++) {
                int col = bn + wn * 32 + nt * 8 + t * 2;
                float v0 = acc[mt][nt][hf2 * 2 + 0] + bp[col];
                float v1 = acc[mt][nt][hf2 * 2 + 1] + bp[col + 1];
                if (EP >= 2 && EP <= 4) {
                    v0 += res[(size_t)row * N + col];
                    v1 += res[(size_t)row * N + col + 1];
                }
                if (EP == 1 || (EP == 5 && upper)) { v0 = fmaxf(v0, 0.f); v1 = fmaxf(v1, 0.f); }
                if (EP == 2) { v0 = (v0 > 0.f) ? v0 : 0.5f * v0; v1 = (v1 > 0.f) ? v1 : 0.5f * v1; }
                if (EP == 3) { v0 = (v0 > 0.f) ? v0 : expm1f(v0); v1 = (v1 > 0.f) ? v1 : expm1f(v1); }
                if (OM == 0) {
                    *(float2*)(Cf + (size_t)row * N + col) = make_float2(v0, v1);
                } else {
                    uint2 o = make_uint2(fsplit(v0), fsplit(v1));
                    *(uint2*)(Cs + (size_t)row * N + col) = o;
                }
            }
        }
    }
}

// ---------- blocked-compensated fp32 GEMM (block 16), q & k fused (grid.z) -----
__global__ __launch_bounds__(256) void kgemm_qk_kernel(
    const float* __restrict__ A,
    const float* __restrict__ Bq, const float* __restrict__ bq, float* __restrict__ Cq,
    const float* __restrict__ Bk, const float* __restrict__ bk, float* __restrict__ Ck,
    int M, int N, int K)
{
    const float* B  = blockIdx.z ? Bk : Bq;
    const float* bb = blockIdx.z ? bk : bq;
    float* C        = blockIdx.z ? Ck : Cq;
    const int relu  = blockIdx.z ? 0 : 1;

    __shared__ float As[16][68];
    __shared__ float Bs[16][68];
    const int tid = threadIdx.x;
    const int bm = blockIdx.y * 64;
    const int bn = blockIdx.x * 64;
    const int ty = tid >> 4, tx = tid & 15;

    float s[4][4], cc[4][4];
#pragma unroll
    for (int i = 0; i < 4; i++)
#pragma unroll
        for (int j = 0; j < 4; j++) { s[i][j] = 0.f; cc[i][j] = 0.f; }

    const int ar = tid >> 2;
    const int ac = (tid & 3) << 2;
    const int br = tid >> 4;
    const int bc = (tid & 15) << 2;

    for (int k0 = 0; k0 < K; k0 += 16) {
        {
            int grow = bm + ar;
            float4 v = make_float4(0.f, 0.f, 0.f, 0.f);
            if (grow < M) v = *(const float4*)(A + (size_t)grow * K + k0 + ac);
            As[ac + 0][ar] = v.x; As[ac + 1][ar] = v.y;
            As[ac + 2][ar] = v.z; As[ac + 3][ar] = v.w;
        }
        *(float4*)&Bs[br][bc] = *(const float4*)(B + (size_t)(k0 + br) * N + bn + bc);
        __syncthreads();
        // one 16-deep plain-FMA block, one Kahan merge (1.25 ops/MAC)
        {
            float p[4][4];
#pragma unroll
            for (int i = 0; i < 4; i++)
#pragma unroll
                for (int j = 0; j < 4; j++) p[i][j] = 0.f;
#pragma unroll
            for (int kk = 0; kk < 16; kk++) {
                float4 av = *(const float4*)&As[kk][ty * 4];
                float4 bv = *(const float4*)&Bs[kk][tx * 4];
                const float* a = (const float*)&av;
                const float* b = (const float*)&bv;
#pragma unroll
                for (int i = 0; i < 4; i++)
#pragma unroll
                    for (int j = 0; j < 4; j++)
                        p[i][j] = __fmaf_rn(a[i], b[j], p[i][j]);
            }
#pragma unroll
            for (int i = 0; i < 4; i++)
#pragma unroll
                for (int j = 0; j < 4; j++)
                    kadd(p[i][j], s[i][j], cc[i][j]);
        }
        __syncthreads();
    }

#pragma unroll
    for (int i = 0; i < 4; i++) {
        int row = bm + ty * 4 + i;
        if (row < M) {
            float4 o;
            float* ov = (float*)&o;
#pragma unroll
            for (int j = 0; j < 4; j++) {
                float v = __fadd_rn(kfin(s[i][j], cc[i][j]), bb[bn + tx * 4 + j]);
                if (relu) v = fmaxf(v, 0.f);
                ov[j] = v;
            }
            *(float4*)(C + (size_t)row * N + bn + tx * 4) = o;
        }
    }
}

// ---------------- batched scores (blocked-compensated fp32, block 16) -----------
__global__ __launch_bounds__(256) void scores_kernel(
    const float* __restrict__ q, const float* __restrict__ k, float* __restrict__ out)
{
    int bh = blockIdx.z;
    int b = bh >> 3, h = bh & 7;
    int l0 = blockIdx.y * 32, s0 = blockIdx.x * 32;
    __shared__ float Qs[32][72];
    __shared__ float Ks[32][72];
    int tid = threadIdx.x;
    int r = tid >> 3;
    int c = (tid & 7) * 8;
    {
        int l = l0 + r;
        if (l < LL) {
            const float* src = q + ((size_t)(b * LL + l)) * DD + h * EE + c;
            *(float4*)&Qs[r][c]     = *(const float4*)src;
            *(float4*)&Qs[r][c + 4] = *(const float4*)(src + 4);
        } else {
#pragma unroll
            for (int t = 0; t < 8; t++) Qs[r][c + t] = 0.f;
        }
        int sdx = s0 + r;
        if (sdx < LL) {
            const float* src = k + ((size_t)(b * LL + sdx)) * DD + h * EE + c;
            *(float4*)&Ks[r][c]     = *(const float4*)src;
            *(float4*)&Ks[r][c + 4] = *(const float4*)(src + 4);
        } else {
#pragma unroll
            for (int t = 0; t < 8; t++) Ks[r][c + t] = 0.f;
        }
    }
    __syncthreads();
    int ty = tid >> 4, tx = tid & 15;
    float s00 = 0.f, s01 = 0.f, s10 = 0.f, s11 = 0.f;
    float c00 = 0.f, c01 = 0.f, c10 = 0.f, c11 = 0.f;
#pragma unroll
    for (int blkk = 0; blkk < 4; blkk++) {
        float p00 = 0.f, p01 = 0.f, p10 = 0.f, p11 = 0.f;
#pragma unroll
        for (int kk = blkk * 16; kk < blkk * 16 + 16; kk++) {
            float a0 = Qs[ty * 2 + 0][kk], a1 = Qs[ty * 2 + 1][kk];
            float b0 = Ks[tx * 2 + 0][kk], b1 = Ks[tx * 2 + 1][kk];
            p00 = __fmaf_rn(a0, b0, p00);
            p01 = __fmaf_rn(a0, b1, p01);
            p10 = __fmaf_rn(a1, b0, p10);
            p11 = __fmaf_rn(a1, b1, p11);
        }
        kadd(p00, s00, c00);
        kadd(p01, s01, c01);
        kadd(p10, s10, c10);
        kadd(p11, s11, c11);
    }
    size_t base = (size_t)bh * LL * LL;
    int l_0 = l0 + ty * 2, s_0 = s0 + tx * 2;
    if (l_0 < LL) {
        if (s_0 < LL)     out[base + (size_t)l_0 * LL + s_0]     = kfin(s00, c00);
        if (s_0 + 1 < LL) out[base + (size_t)l_0 * LL + s_0 + 1] = kfin(s01, c01);
    }
    if (l_0 + 1 < LL) {
        if (s_0 < LL)     out[base + (size_t)(l_0 + 1) * LL + s_0]     = kfin(s10, c10);
        if (s_0 + 1 < LL) out[base + (size_t)(l_0 + 1) * LL + s_0 + 1] = kfin(s11, c11);
    }
}

// ---------------- top-k mask + softmax, in place on scores ----------------
__global__ __launch_bounds__(256) void topk_softmax_kernel(float* __restrict__ A)
{
    const int lane = threadIdx.x & 31;
    const int wslot = threadIdx.x >> 5;
    const size_t row = (size_t)blockIdx.x * 8 + wslot;
    __shared__ float sm[8][352];
    float* s = sm[wslot];
    float* rp = A + row * LL;

    float r[11];
#pragma unroll
    for (int j = 0; j < 11; j++) {
        int idx = lane + j * 32;
        float v = (idx < LL) ? rp[idx] : -INFINITY;
        r[j] = v;
        s[idx] = v;
    }
    __syncwarp();

    float kth = 0.f, mmax = 0.f;
    for (int it = 0; it < NTOPK; it++) {
        float lm = -INFINITY;
#pragma unroll
        for (int j = 0; j < 11; j++) lm = fmaxf(lm, s[lane + j * 32]);
        float gm = lm;
#pragma unroll
        for (int o = 16; o > 0; o >>= 1) gm = fmaxf(gm, __shfl_xor_sync(0xffffffffu, gm, o));
        if (it == 0) mmax = gm;
        kth = gm;
        int li = 0x7fffffff;
#pragma unroll
        for (int j = 10; j >= 0; j--) {
            int idx = lane + j * 32;
            if (s[idx] == gm) li = idx;
        }
        int gi = li;
#pragma unroll
        for (int o = 16; o > 0; o >>= 1) gi = min(gi, __shfl_xor_sync(0xffffffffu, gi, o));
        if (li == gi) s[li] = -INFINITY;
        __syncwarp();
    }

    const float scale = 0.125f;
    float e[11];
    float sum = 0.f;
#pragma unroll
    for (int j = 0; j < 11; j++) {
        int idx = lane + j * 32;
        float v = r[j];
        float t = (idx < LL && v >= kth) ? expf((v - mmax) * scale) : 0.f;
        e[j] = t;
        sum += t;
    }
#pragma unroll
    for (int o = 16; o > 0; o >>= 1) sum += __shfl_xor_sync(0xffffffffu, sum, o);
    float inv = 1.f / sum;
#pragma unroll
    for (int j = 0; j < 11; j++) {
        int idx = lane + j * 32;
        if (idx < LL) rp[idx] = e[j] * inv;
    }
}

// ---------------- sparse A @ V -> split output ----------------------------------
__global__ __launch_bounds__(256) void av_sparse_kernel(
    const float* __restrict__ A, const float* __restrict__ v, uint32_t* __restrict__ out)
{
    __shared__ short  sidx[8][24];
    __shared__ float  swt[8][24];
    __shared__ int    scnt[8];
    int blk = blockIdx.x;
    int b = blk / LL, l = blk % LL;
    int tid = threadIdx.x;
    int wid = tid >> 5, lane = tid & 31;

    {
        int h = wid;
        const float* rp = A + ((size_t)(b * 8 + h) * LL + l) * LL;
        int cnt = 0;
#pragma unroll
        for (int j = 0; j < 11; j++) {
            int idx = lane + j * 32;
            float w = (idx < LL) ? rp[idx] : 0.f;
            unsigned m = __ballot_sync(0xffffffffu, w > 0.f);
            if (w > 0.f) {
                int pos = cnt + __popc(m & ((1u << lane) - 1u));
                if (pos < 24) { sidx[h][pos] = (short)idx; swt[h][pos] = w; }
            }
            cnt += __popc(m);
        }
        if (lane == 0) scnt[h] = (cnt < 24) ? cnt : 24;
    }
    __syncthreads();

    const float* vbase = v + (size_t)b * LL * DD;
#pragma unroll
    for (int e0 = 0; e0 < 2; e0++) {
        int e = tid + e0 * 256;
        int h = e >> 6, c2 = e & 63;
        int n2 = scnt[h];
        const float* vp = vbase + h * EE + c2;
        float acc = 0.f;
        for (int j = 0; j < n2; j++)
            acc = __fmaf_rn(swt[h][j], vp[(size_t)sidx[h][j] * DD], acc);
        out[((size_t)(b * LL + l)) * DD + e] = fsplit(acc);
    }
}

// ---------------- pwattn1 (combined k|v buffer, row stride 1024) ----------------
__global__ __launch_bounds__(128) void pwattn1_kernel(
    const float* __restrict__ q, const float* __restrict__ kv,
    uint32_t* __restrict__ out)
{
    int n = blockIdx.x;
    int l = threadIdx.x;
    __shared__ float sk[512];
    __shared__ float sv[512];
    int t4 = l * 4;
    const float* kvp = kv + (size_t)n * 1024;
    *(float4*)&sk[t4] = *(const float4*)(kvp + t4);
    *(float4*)&sv[t4] = *(const float4*)(kvp + 512 + t4);
    __syncthreads();
    float qr[16];
    const float* qp = q + (size_t)n * 2048 + l * 16;
#pragma unroll
    for (int p = 0; p < 16; p++) qr[p] = qp[p];
    float sc[32];
    float m = -INFINITY;
#pragma unroll
    for (int s = 0; s < 32; s++) {
        float d = 0.f;
#pragma unroll
        for (int p = 0; p < 16; p++) d = fmaf(qr[p], sk[s * 16 + p], d);
        sc[s] = d;
        m = fmaxf(m, d);
    }
    float sum = 0.f;
    float V[16];
#pragma unroll
    for (int p = 0; p < 16; p++) V[p] = 0.f;
#pragma unroll
    for (int s = 0; s < 32; s++) {
        float w = expf((sc[s] - m) * 0.25f);
        sum += w;
#pragma unroll
        for (int p = 0; p < 16; p++) V[p] = fmaf(w, sv[s * 16 + p], V[p]);
    }
    float inv = 1.f / sum;
    uint32_t* op = out + (size_t)n * 2048 + l * 16;
#pragma unroll
    for (int p = 0; p < 16; p++) op[p] = fsplit(V[p] * inv);
}

// ------- pwattn2: combined k|v buffer (stride 4096), single-pass online --------
__global__ __launch_bounds__(128) void pwattn2_kernel(
    const float* __restrict__ q, const float* __restrict__ kv2,
    uint32_t* __restrict__ out)
{
    int n = blockIdx.x * 4 + (threadIdx.x >> 5);
    int lane = threadIdx.x & 31;
    const float* kp = kv2 + (size_t)n * 4096;
    const float* vp = kp + 2048;
    float qr[16];
    const float* qp = q + (size_t)n * 512 + lane * 16;
#pragma unroll
    for (int p = 0; p < 16; p++) qr[p] = qp[p];
    float m = -INFINITY, sum = 0.f;
    float V[16];
#pragma unroll
    for (int p = 0; p < 16; p++) V[p] = 0.f;
    for (int s = 0; s < 128; s++) {
        float d = 0.f;
#pragma unroll
        for (int p = 0; p < 16; p++) d = fmaf(qr[p], kp[s * 16 + p], d);
        if (d > m) {
            float f = expf((m - d) * 0.25f);
            sum *= f;
#pragma unroll
            for (int p = 0; p < 16; p++) V[p] *= f;
            m = d;
        }
        float w = expf((d - m) * 0.25f);
        sum += w;
#pragma unroll
        for (int p = 0; p < 16; p++) V[p] = fmaf(w, vp[s * 16 + p], V[p]);
    }
    float inv = 1.f / sum;
    uint32_t* op = out + (size_t)n * 512 + lane * 16;
#pragma unroll
    for (int p = 0; p < 16; p++) op[p] = fsplit(V[p] * inv);
}

// ---------------- layernorm over 2048 -> split output ---------------------------
__global__ __launch_bounds__(256) void ln_kernel(
    const float* __restrict__ in, const float* __restrict__ g,
    const float* __restrict__ b, uint32_t* __restrict__ out)
{
    int n = blockIdx.x;
    int tid = threadIdx.x;
    __shared__ float red[256];
    const float* x = in + (size_t)n * 2048;
    float s = 0.f;
    for (int i = tid; i < 2048; i += 256) s += x[i];
    red[tid] = s; __syncthreads();
    for (int o = 128; o > 0; o >>= 1) { if (tid < o) red[tid] += red[tid + o]; __syncthreads(); }
    float mean = red[0] * (1.f / 2048.f);
    __syncthreads();
    float vs = 0.f;
    for (int i = tid; i < 2048; i += 256) { float d = x[i] - mean; vs += d * d; }
    red[tid] = vs; __syncthreads();
    for (int o = 128; o > 0; o >>= 1) { if (tid < o) red[tid] += red[tid + o]; __syncthreads(); }
    float var = red[0] * (1.f / 2048.f);
    float inv = rsqrtf(var + 1e-5f);
    uint32_t* op = out + (size_t)n * 2048;
    for (int i = tid; i < 2048; i += 256) op[i] = fsplit((x[i] - mean) * inv * g[i] + b[i]);
}

// ---------------- launch --------------------------------------------------------
extern "C" void kernel_launch(void* const* d_in, const int* in_sizes, int n_in,
                              void* d_out, int out_size)
{
    (void)in_sizes; (void)n_in; (void)out_size;
    const float* x     = (const float*)d_in[0];
    const float* aqw   = (const float*)d_in[1];
    const float* aqb   = (const float*)d_in[2];
    const float* akw   = (const float*)d_in[3];
    const float* akb   = (const float*)d_in[4];
    const float* avw   = (const float*)d_in[5];
    const float* avb   = (const float*)d_in[6];
    const float* aow   = (const float*)d_in[7];
    const float* aob   = (const float*)d_in[8];
    const float* encw  = (const float*)d_in[9];
    const float* encb  = (const float*)d_in[10];
    const float* f1qw  = (const float*)d_in[11];
    const float* f1qb  = (const float*)d_in[12];
    const float* f1kw  = (const float*)d_in[13];
    const float* f1kb  = (const float*)d_in[14];
    const float* f1vw  = (const float*)d_in[15];
    const float* f1vb  = (const float*)d_in[16];
    const float* f1ow  = (const float*)d_in[17];
    const float* f1ob  = (const float*)d_in[18];
    const float* f2qw  = (const float*)d_in[19];
    const float* f2qb  = (const float*)d_in[20];
    const float* f2kw  = (const float*)d_in[21];
    const float* f2kb  = (const float*)d_in[22];
    const float* f2vw  = (const float*)d_in[23];
    const float* f2vb  = (const float*)d_in[24];
    const float* f2ow  = (const float*)d_in[25];
    const float* f2ob  = (const float*)d_in[26];
    const float* lng   = (const float*)d_in[27];
    const float* lnb   = (const float*)d_in[28];

    float* out  = (float*)d_out;
    float* Aout = out + (size_t)NROWS * 512;

    float* b512; float* b2048; uint32_t* sps; uint32_t* spb; uint32_t* wt;
    cudaGetSymbolAddress((void**)&b512,  g_buf512);
    cudaGetSymbolAddress((void**)&b2048, g_buf2048);
    cudaGetSymbolAddress((void**)&sps,   g_sp_small);
    cudaGetSymbolAddress((void**)&spb,   g_sp_big);
    cudaGetSymbolAddress((void**)&wt,    g_wt);
    const size_t S = (size_t)NROWS * 512;
    const size_t T = (size_t)NROWS * 2048;
    float* qb   = b512;
    float* kb   = b512 + S;
    float* vb   = b512 + 2 * S;
    float* kv1  = b512 + 3 * S;
    float* qu2  = b512 + 5 * S;
    float* q1   = b2048;
    float* t1   = b2048 + T;
    float* kv2  = b2048 + 2 * T;
    uint32_t* x_sp   = sps;
    uint32_t* att_sp = sps + S;
    uint32_t* zb_sp  = sps + 2 * S;
    uint32_t* y2_sp  = sps + 3 * S;
    uint32_t* Vf1_sp = spb;
    uint32_t* u_sp   = spb + T;

    cudaFuncSetAttribute(mm_gemm_kernel<0,1>, cudaFuncAttributeMaxDynamicSharedMemorySize, MM_SMEM);
    cudaFuncSetAttribute(mm_gemm_kernel<1,0>, cudaFuncAttributeMaxDynamicSharedMemorySize, MM_SMEM);
    cudaFuncSetAttribute(mm_gemm_kernel<2,1>, cudaFuncAttributeMaxDynamicSharedMemorySize, MM_SMEM);
    cudaFuncSetAttribute(mm_gemm_kernel<3,0>, cudaFuncAttributeMaxDynamicSharedMemorySize, MM_SMEM);
    cudaFuncSetAttribute(mm_gemm_kernel<4,0>, cudaFuncAttributeMaxDynamicSharedMemorySize, MM_SMEM);
    cudaFuncSetAttribute(mm_gemm_kernel<5,0>, cudaFuncAttributeMaxDynamicSharedMemorySize, MM_SMEM);

    static cudaStream_t s2 = nullptr;
    static cudaEvent_t evF = nullptr, evJ = nullptr, evF1 = nullptr, evJ1 = nullptr,
                       evF2 = nullptr, evJ2 = nullptr;
    if (!s2) {
        cudaStreamCreateWithFlags(&s2, cudaStreamNonBlocking);
        cudaEventCreateWithFlags(&evF,  cudaEventDisableTiming);
        cudaEventCreateWithFlags(&evJ,  cudaEventDisableTiming);
        cudaEventCreateWithFlags(&evF1, cudaEventDisableTiming);
        cudaEventCreateWithFlags(&evJ1, cudaEventDisableTiming);
        cudaEventCreateWithFlags(&evF2, cudaEventDisableTiming);
        cudaEventCreateWithFlags(&evJ2, cudaEventDisableTiming);
    }

    dim3 blk(256);
    dim3 tb(32, 8);
    dim3 tg512(8, (NROWS + 127) / 128);
    dim3 tg1024(16, (NROWS + 127) / 128);
    dim3 tg2048(32, (NROWS + 127) / 128);
    dim3 tg4096(64, (NROWS + 127) / 128);
    dim3 kg(8, (NROWS + 63) / 64, 2);

    // ===== fork 0: A-path on s2 ∥ transpose/convert/av on main =================
    cudaEventRecord(evF, 0);
    cudaStreamWaitEvent(s2, evF, 0);

    kgemm_qk_kernel<<<kg, blk, 0, s2>>>(x, aqw, aqb, qb, akw, akb, kb, NROWS, 512, 512);
    scores_kernel<<<dim3(11, 11, 512), blk, 0, s2>>>(qb, kb, Aout);
    topk_softmax_kernel<<<20544, blk, 0, s2>>>(Aout);
    cudaEventRecord(evJ, s2);

    {
        TransArgs ta;
        const float* srcs[11] = {avw, aow, encw, f1qw, f1kw, f1vw, f1ow, f2qw, f2kw, f2vw, f2ow};
        uint32_t offs[11] = {OFF_AV, OFF_AO, OFF_ENC, OFF_F1Q, OFF_F1K, OFF_F1V,
                             OFF_F1O, OFF_F2Q, OFF_F2K, OFF_F2V, OFF_F2O};
        int Ks[11] = {512, 512, 512, 512, 512, 512, 2048, 2048, 2048, 2048, 512};
        int Ns[11] = {512, 512, 512, 2048, 512, 512, 2048, 512, 2048, 2048, 512};
        int acc = 0;
        for (int j = 0; j < 11; j++) {
            ta.job[j].src = srcs[j];
            ta.job[j].dstoff = offs[j];
            ta.job[j].K = Ks[j];
            ta.job[j].N = Ns[j];
            ta.job[j].tstart = acc;
            acc += (Ns[j] >> 5) * (Ks[j] >> 5);
        }
        transpose_split_all<<<acc, tb>>>(ta);
    }
    convert_kernel<<<4096, 256>>>(x, x_sp, (int)S);
    mm_gemm_kernel<1,0><<<tg512, blk, MM_SMEM>>>(x_sp, wt + OFF_AV, avb, nullptr, vb, NROWS, 512, 512);

    cudaStreamWaitEvent(0, evJ, 0);   // join 0
    // ===========================================================================

    av_sparse_kernel<<<NROWS, blk>>>(Aout, vb, att_sp);
    mm_gemm_kernel<2,1><<<tg512, blk, MM_SMEM>>>(att_sp, wt + OFF_AO, aob, x, zb_sp, NROWS, 512, 512);
    mm_gemm_kernel<0,1><<<tg512, blk, MM_SMEM>>>(zb_sp, wt + OFF_ENC, encb, nullptr, y2_sp, NROWS, 512, 512);

    // ---- ff1: f1q (main) ∥ f1kv (s2) ----
    cudaEventRecord(evF1, 0);
    cudaStreamWaitEvent(s2, evF1, 0);
    mm_gemm_kernel<5,0><<<tg1024, blk, MM_SMEM, s2>>>(y2_sp, wt + OFF_F1K, f1kb, f1vb, kv1, NROWS, 1024, 512);
    cudaEventRecord(evJ1, s2);
    mm_gemm_kernel<1,0><<<tg2048, blk, MM_SMEM>>>(y2_sp, wt + OFF_F1Q, f1qb, nullptr, q1, NROWS, 2048, 512);
    cudaStreamWaitEvent(0, evJ1, 0);

    pwattn1_kernel<<<NROWS, 128>>>(q1, kv1, Vf1_sp);
    mm_gemm_kernel<3,0><<<tg2048, blk, MM_SMEM>>>(Vf1_sp, wt + OFF_F1O, f1ob, q1, t1, NROWS, 2048, 2048);
    ln_kernel<<<NROWS, blk>>>(t1, lng, lnb, u_sp);

    // ---- ff2: f2q (s2) ∥ f2kv (main) ----
    cudaEventRecord(evF2, 0);
    cudaStreamWaitEvent(s2, evF2, 0);
    mm_gemm_kernel<1,0><<<tg512, blk, MM_SMEM, s2>>>(u_sp, wt + OFF_F2Q, f2qb, nullptr, qu2, NROWS, 512, 2048);
    cudaEventRecord(evJ2, s2);
    mm_gemm_kernel<5,0><<<tg4096, blk, MM_SMEM>>>(u_sp, wt + OFF_F2K, f2kb, f2vb, kv2, NROWS, 4096, 2048);
    cudaStreamWaitEvent(0, evJ2, 0);

    pwattn2_kernel<<<NROWS / 4, 128>>>(qu2, kv2, x_sp);
    mm_gemm_kernel<4,0><<<tg512, blk, MM_SMEM>>>(x_sp, wt + OFF_F2O, f2ob, qu2, out, NROWS, 512, 512);
}

// round 15
// speedup vs baseline: 1.0954x; 1.0065x over previous
#include <cuda_runtime.h>
#include <cuda_bf16.h>
#include <math.h>
#include <stdint.h>

#define NROWS 20544     // B*L = 64*321
#define LL 321
#define DD 512
#define HH 8
#define EE 64
#define NTOPK 10

// ---------------- scratch (allocation-free: __device__ globals) ----------------
__device__ float    g_buf512[6ULL * NROWS * 512];
__device__ float    g_buf2048[4ULL * NROWS * 2048];
__device__ uint32_t g_sp_small[4ULL * NROWS * 512];
__device__ uint32_t g_sp_big[2ULL * NROWS * 2048];
__device__ uint32_t g_wt[16252928];                  // split transposed weights [N,K]
__device__ short    g_avidx[164352 * 24];            // compact top-k lists
__device__ float    g_avwt[164352 * 24];
__device__ int      g_avcnt[164352];

#define OFF_AV   0u
#define OFF_AO   262144u
#define OFF_ENC  524288u
#define OFF_F1Q  786432u
#define OFF_F1K  1835008u
#define OFF_F1V  2097152u
#define OFF_F1O  2359296u
#define OFF_F2Q  6553600u
#define OFF_F2K  7602176u
#define OFF_F2V  11796480u
#define OFF_F2O  15990784u

// ---------------- bf16 split helpers -------------------------------------------
__device__ __forceinline__ uint32_t fsplit(float x) {
    __nv_bfloat16 h = __float2bfloat16(x);
    float hf = __bfloat162float(h);
    __nv_bfloat16 l = __float2bfloat16(x - hf);
    return (uint32_t)__bfloat16_as_ushort(h) | ((uint32_t)__bfloat16_as_ushort(l) << 16);
}
__device__ __forceinline__ void ld_pair(const uint32_t* s, uint32_t& hi, uint32_t& lo) {
    uint2 p = *(const uint2*)s;
    hi = __byte_perm(p.x, p.y, 0x5410);
    lo = __byte_perm(p.x, p.y, 0x7632);
}

// ------------- blocked compensation: Kahan-merge a block partial ---------------
__device__ __forceinline__ void kadd(float p, float& s, float& c) {
    float y = __fsub_rn(p, c);
    float t = __fadd_rn(s, y);
    c = __fsub_rn(__fsub_rn(t, s), y);
    s = t;
}
__device__ __forceinline__ float kfin(float s, float c) { return __fsub_rn(s, c); }

// ==================== batched weight transpose + split =========================
struct TransJob { const float* src; uint32_t dstoff; int K; int N; int tstart; };
struct TransArgs { TransJob job[11]; };

__global__ void transpose_split_all(TransArgs a)
{
    __shared__ float t[32][33];
    int tile = blockIdx.x;
    int ji = 0;
#pragma unroll
    for (int j = 1; j < 11; j++)
        if (tile >= a.job[j].tstart) ji = j;
    const TransJob& J = a.job[ji];
    int local = tile - J.tstart;
    int ntx = J.N >> 5;
    int bx = (local % ntx) * 32, by = (local / ntx) * 32;
    int txi = threadIdx.x, tyi = threadIdx.y;
    const float* src = J.src;
    uint32_t* dst = g_wt + J.dstoff;
#pragma unroll
    for (int j = 0; j < 32; j += 8)
        t[tyi + j][txi] = src[(size_t)(by + tyi + j) * J.N + bx + txi];
    __syncthreads();
#pragma unroll
    for (int j = 0; j < 32; j += 8)
        dst[(size_t)(bx + tyi + j) * J.K + by + txi] = fsplit(t[txi][tyi + j]);
}

__global__ void convert_kernel(const float* __restrict__ in, uint32_t* __restrict__ outp, int n)
{
    for (int i = blockIdx.x * 256 + threadIdx.x; i < n; i += gridDim.x * 256)
        outp[i] = fsplit(in[i]);
}

// ============ bf16x3 mma.sync GEMM: 128x64 tile, 2 CTA/SM, term-major ==========
#define MMP 40
#define MM_A_U32  (128 * MMP)
#define MM_B_U32  (64 * MMP)
#define MM_STAGE  (MM_A_U32 + MM_B_U32)
#define MM_SMEM   (2 * MM_STAGE * 4)        // 61440 bytes

__device__ __forceinline__ void mm_load_stage(
    const uint32_t* __restrict__ A, const uint32_t* __restrict__ Bt,
    int bm, int bn, int M, int K, int k0, uint32_t* st, int tid)
{
    uint32_t a_s, b_s;
    asm("{ .reg .u64 t; cvta.to.shared.u64 t, %1; cvt.u32.u64 %0, t; }" : "=r"(a_s) : "l"(st));
    b_s = a_s + MM_A_U32 * 4;
#pragma unroll
    for (int j = 0; j < 6; j++) {
        int idx = tid + j * 256;
        if (idx < 1024) {
            int r = idx >> 3, c = idx & 7;
            uint32_t doff = (uint32_t)(r * MMP + c * 4) * 4;
            int grow = bm + r;
            const uint32_t* srcA = A + (size_t)(grow < M ? grow : 0) * K + k0 + c * 4;
            int szA = (grow < M) ? 16 : 0;
            asm volatile("cp.async.ca.shared.global [%0], [%1], 16, %2;"
                         :: "r"(a_s + doff), "l"(srcA), "r"(szA));
        } else {
            int idx2 = idx - 1024;
            int r = idx2 >> 3, c = idx2 & 7;
            uint32_t doff = (uint32_t)(r * MMP + c * 4) * 4;
            const uint32_t* srcB = Bt + (size_t)(bn + r) * K + k0 + c * 4;
            asm volatile("cp.async.ca.shared.global [%0], [%1], 16;"
                         :: "r"(b_s + doff), "l"(srcB));
        }
    }
    asm volatile("cp.async.commit_group;" ::: "memory");
}

#define MMA_BF16(acc, a0, a1, a2, a3, b0, b1) \
    asm volatile( \
        "mma.sync.aligned.m16n8k16.row.col.f32.bf16.bf16.f32 " \
        "{%0,%1,%2,%3}, {%4,%5,%6,%7}, {%8,%9}, {%0,%1,%2,%3};" \
        : "+f"((acc)[0]), "+f"((acc)[1]), "+f"((acc)[2]), "+f"((acc)[3]) \
        : "r"(a0), "r"(a1), "r"(a2), "r"(a3), "r"(b0), "r"(b1))

// EP: 0=bias, 1=bias+relu, 2=bias+res+leaky, 3=bias+res+elu, 4=bias+res,
//     5=dual-bias (bias=lower half, res=upper-half bias), relu on upper half
template<int EP, int OM>
__global__ __launch_bounds__(256, 2)
void mm_gemm_kernel(const uint32_t* __restrict__ A, const uint32_t* __restrict__ Bt,
                    const float* __restrict__ bias, const float* __restrict__ res,
                    void* __restrict__ Cv, int M, int N, int K)
{
    extern __shared__ uint32_t sm[];
    const int tid = threadIdx.x;
    const int wid = tid >> 5, lane = tid & 31;
    const int wm = wid >> 1, wn = wid & 1;
    const int g = lane >> 2, t = lane & 3;
    const int bm = blockIdx.y * 128, bn = blockIdx.x * 64;

    float acc[2][4][4];
#pragma unroll
    for (int i = 0; i < 2; i++)
#pragma unroll
        for (int j = 0; j < 4; j++)
#pragma unroll
            for (int q = 0; q < 4; q++) acc[i][j][q] = 0.f;

    const int nc = K >> 5;
    mm_load_stage(A, Bt, bm, bn, M, K, 0, sm, tid);

    for (int c = 0; c < nc; c++) {
        if (c + 1 < nc)
            mm_load_stage(A, Bt, bm, bn, M, K, (c + 1) * 32, sm + ((c + 1) & 1) * MM_STAGE, tid);
        if (c + 1 < nc) asm volatile("cp.async.wait_group 1;" ::: "memory");
        else            asm volatile("cp.async.wait_group 0;" ::: "memory");
        __syncthreads();

        const uint32_t* As = sm + (c & 1) * MM_STAGE;
        const uint32_t* Bs = As + MM_A_U32;
#pragma unroll
        for (int ks = 0; ks < 2; ks++) {
            uint32_t ah[2][4], al[2][4], bh[4][2], bl[4][2];
#pragma unroll
            for (int mt = 0; mt < 2; mt++) {
                const uint32_t* base = As + (wm * 32 + mt * 16 + g) * MMP + ks * 16 + 2 * t;
                ld_pair(base,             ah[mt][0], al[mt][0]);
                ld_pair(base + 8 * MMP,   ah[mt][1], al[mt][1]);
                ld_pair(base + 8,         ah[mt][2], al[mt][2]);
                ld_pair(base + 8 * MMP + 8, ah[mt][3], al[mt][3]);
            }
#pragma unroll
            for (int nt = 0; nt < 4; nt++) {
                const uint32_t* base = Bs + (wn * 32 + nt * 8 + g) * MMP + ks * 16 + 2 * t;
                ld_pair(base,     bh[nt][0], bl[nt][0]);
                ld_pair(base + 8, bh[nt][1], bl[nt][1]);
            }
#pragma unroll
            for (int mt = 0; mt < 2; mt++)
#pragma unroll
                for (int nt = 0; nt < 4; nt++)
                    MMA_BF16(acc[mt][nt], ah[mt][0], ah[mt][1], ah[mt][2], ah[mt][3],
                             bl[nt][0], bl[nt][1]);
#pragma unroll
            for (int mt = 0; mt < 2; mt++)
#pragma unroll
                for (int nt = 0; nt < 4; nt++)
                    MMA_BF16(acc[mt][nt], al[mt][0], al[mt][1], al[mt][2], al[mt][3],
                             bh[nt][0], bh[nt][1]);
#pragma unroll
            for (int mt = 0; mt < 2; mt++)
#pragma unroll
                for (int nt = 0; nt < 4; nt++)
                    MMA_BF16(acc[mt][nt], ah[mt][0], ah[mt][1], ah[mt][2], ah[mt][3],
                             bh[nt][0], bh[nt][1]);
        }
        __syncthreads();
    }

    float* Cf = (float*)Cv;
    uint32_t* Cs = (uint32_t*)Cv;
    const int half = N >> 1;
    const bool upper = (EP == 5) && (bn >= half);
    const float* bp = (EP == 5) ? (upper ? res - half : bias) : bias;
#pragma unroll
    for (int mt = 0; mt < 2; mt++) {
#pragma unroll
        for (int hf2 = 0; hf2 < 2; hf2++) {
            int row = bm + wm * 32 + mt * 16 + g + hf2 * 8;
            if (row >= M) continue;
#pragma unroll
            for (int nt = 0; nt < 4; nt++) {
                int col = bn + wn * 32 + nt * 8 + t * 2;
                float v0 = acc[mt][nt][hf2 * 2 + 0] + bp[col];
                float v1 = acc[mt][nt][hf2 * 2 + 1] + bp[col + 1];
                if (EP >= 2 && EP <= 4) {
                    v0 += res[(size_t)row * N + col];
                    v1 += res[(size_t)row * N + col + 1];
                }
                if (EP == 1 || (EP == 5 && upper)) { v0 = fmaxf(v0, 0.f); v1 = fmaxf(v1, 0.f); }
                if (EP == 2) { v0 = (v0 > 0.f) ? v0 : 0.5f * v0; v1 = (v1 > 0.f) ? v1 : 0.5f * v1; }
                if (EP == 3) { v0 = (v0 > 0.f) ? v0 : expm1f(v0); v1 = (v1 > 0.f) ? v1 : expm1f(v1); }
                if (OM == 0) {
                    *(float2*)(Cf + (size_t)row * N + col) = make_float2(v0, v1);
                } else {
                    uint2 o = make_uint2(fsplit(v0), fsplit(v1));
                    *(uint2*)(Cs + (size_t)row * N + col) = o;
                }
            }
        }
    }
}

// ---------- blocked-compensated fp32 GEMM (block 16), q & k fused (grid.z) -----
__global__ __launch_bounds__(256) void kgemm_qk_kernel(
    const float* __restrict__ A,
    const float* __restrict__ Bq, const float* __restrict__ bq, float* __restrict__ Cq,
    const float* __restrict__ Bk, const float* __restrict__ bk, float* __restrict__ Ck,
    int M, int N, int K)
{
    const float* B  = blockIdx.z ? Bk : Bq;
    const float* bb = blockIdx.z ? bk : bq;
    float* C        = blockIdx.z ? Ck : Cq;
    const int relu  = blockIdx.z ? 0 : 1;

    __shared__ float As[16][68];
    __shared__ float Bs[16][68];
    const int tid = threadIdx.x;
    const int bm = blockIdx.y * 64;
    const int bn = blockIdx.x * 64;
    const int ty = tid >> 4, tx = tid & 15;

    float s[4][4], cc[4][4];
#pragma unroll
    for (int i = 0; i < 4; i++)
#pragma unroll
        for (int j = 0; j < 4; j++) { s[i][j] = 0.f; cc[i][j] = 0.f; }

    const int ar = tid >> 2;
    const int ac = (tid & 3) << 2;
    const int br = tid >> 4;
    const int bc = (tid & 15) << 2;

    for (int k0 = 0; k0 < K; k0 += 16) {
        {
            int grow = bm + ar;
            float4 v = make_float4(0.f, 0.f, 0.f, 0.f);
            if (grow < M) v = *(const float4*)(A + (size_t)grow * K + k0 + ac);
            As[ac + 0][ar] = v.x; As[ac + 1][ar] = v.y;
            As[ac + 2][ar] = v.z; As[ac + 3][ar] = v.w;
        }
        *(float4*)&Bs[br][bc] = *(const float4*)(B + (size_t)(k0 + br) * N + bn + bc);
        __syncthreads();
        {
            float p[4][4];
#pragma unroll
            for (int i = 0; i < 4; i++)
#pragma unroll
                for (int j = 0; j < 4; j++) p[i][j] = 0.f;
#pragma unroll
            for (int kk = 0; kk < 16; kk++) {
                float4 av = *(const float4*)&As[kk][ty * 4];
                float4 bv = *(const float4*)&Bs[kk][tx * 4];
                const float* a = (const float*)&av;
                const float* b = (const float*)&bv;
#pragma unroll
                for (int i = 0; i < 4; i++)
#pragma unroll
                    for (int j = 0; j < 4; j++)
                        p[i][j] = __fmaf_rn(a[i], b[j], p[i][j]);
            }
#pragma unroll
            for (int i = 0; i < 4; i++)
#pragma unroll
                for (int j = 0; j < 4; j++)
                    kadd(p[i][j], s[i][j], cc[i][j]);
        }
        __syncthreads();
    }

#pragma unroll
    for (int i = 0; i < 4; i++) {
        int row = bm + ty * 4 + i;
        if (row < M) {
            float4 o;
            float* ov = (float*)&o;
#pragma unroll
            for (int j = 0; j < 4; j++) {
                float v = __fadd_rn(kfin(s[i][j], cc[i][j]), bb[bn + tx * 4 + j]);
                if (relu) v = fmaxf(v, 0.f);
                ov[j] = v;
            }
            *(float4*)(C + (size_t)row * N + bn + tx * 4) = o;
        }
    }
}

// ========== FUSED scores + top-k + softmax + compact-list emission =============
// grid (11, 512): block = 32 l-rows x full s-range for one (b,h).
// Scores computed tile-by-tile into smem (identical arithmetic to the old
// scores_kernel), then the old warp top-k runs in smem; A written once;
// compact (idx,weight) lists emitted for av_sparse. Bit-identical results.
#define ST_SMEM ((32 * 72 * 2 + 32 * 360) * 4)   // Qs + Ks + SC = 64512 B

__global__ __launch_bounds__(256) void scores_topk_kernel(
    const float* __restrict__ q, const float* __restrict__ k, float* __restrict__ out,
    short* __restrict__ avidx, float* __restrict__ avwt, int* __restrict__ avcnt)
{
    extern __shared__ float shb[];
    float (*Qs)[72]  = (float(*)[72])shb;
    float (*Ks)[72]  = (float(*)[72])(shb + 32 * 72);
    float (*SC)[360] = (float(*)[360])(shb + 2 * 32 * 72);

    int bh = blockIdx.y;
    int b = bh >> 3, h = bh & 7;
    int l0 = blockIdx.x * 32;
    int tid = threadIdx.x;
    int r = tid >> 3;
    int c = (tid & 7) * 8;
    {
        int l = l0 + r;
        if (l < LL) {
            const float* src = q + ((size_t)(b * LL + l)) * DD + h * EE + c;
            *(float4*)&Qs[r][c]     = *(const float4*)src;
            *(float4*)&Qs[r][c + 4] = *(const float4*)(src + 4);
        } else {
#pragma unroll
            for (int t = 0; t < 8; t++) Qs[r][c + t] = 0.f;
        }
    }
    int ty = tid >> 4, tx = tid & 15;

    for (int s0 = 0; s0 < 352; s0 += 32) {
        __syncthreads();   // protect Ks before overwrite
        {
            int sdx = s0 + r;
            if (sdx < LL) {
                const float* src = k + ((size_t)(b * LL + sdx)) * DD + h * EE + c;
                *(float4*)&Ks[r][c]     = *(const float4*)src;
                *(float4*)&Ks[r][c + 4] = *(const float4*)(src + 4);
            } else {
#pragma unroll
                for (int t = 0; t < 8; t++) Ks[r][c + t] = 0.f;
            }
        }
        __syncthreads();
        float s00 = 0.f, s01 = 0.f, s10 = 0.f, s11 = 0.f;
        float c00 = 0.f, c01 = 0.f, c10 = 0.f, c11 = 0.f;
#pragma unroll
        for (int blkk = 0; blkk < 4; blkk++) {
            float p00 = 0.f, p01 = 0.f, p10 = 0.f, p11 = 0.f;
#pragma unroll
            for (int kk = blkk * 16; kk < blkk * 16 + 16; kk++) {
                float a0 = Qs[ty * 2 + 0][kk], a1 = Qs[ty * 2 + 1][kk];
                float b0 = Ks[tx * 2 + 0][kk], b1 = Ks[tx * 2 + 1][kk];
                p00 = __fmaf_rn(a0, b0, p00);
                p01 = __fmaf_rn(a0, b1, p01);
                p10 = __fmaf_rn(a1, b0, p10);
                p11 = __fmaf_rn(a1, b1, p11);
            }
            kadd(p00, s00, c00);
            kadd(p01, s01, c01);
            kadd(p10, s10, c10);
            kadd(p11, s11, c11);
        }
        SC[ty * 2 + 0][s0 + tx * 2 + 0] = kfin(s00, c00);
        SC[ty * 2 + 0][s0 + tx * 2 + 1] = kfin(s01, c01);
        SC[ty * 2 + 1][s0 + tx * 2 + 0] = kfin(s10, c10);
        SC[ty * 2 + 1][s0 + tx * 2 + 1] = kfin(s11, c11);
    }
    __syncthreads();

    // ---- top-k + softmax phase: warp w handles rows w*4 .. w*4+3 ----
    int wid = tid >> 5, lane = tid & 31;
    for (int rr = 0; rr < 4; rr++) {
        int lrow = wid * 4 + rr;
        int l = l0 + lrow;
        if (l >= LL) break;
        float* s = SC[lrow];
        float rc[11];
#pragma unroll
        for (int j = 0; j < 11; j++) {
            int idx = lane + j * 32;
            float v = (idx < LL) ? s[idx] : -INFINITY;
            rc[j] = v;
            s[idx] = v;
        }
        __syncwarp();

        float kth = 0.f, mmax = 0.f;
        for (int it = 0; it < NTOPK; it++) {
            float lm = -INFINITY;
#pragma unroll
            for (int j = 0; j < 11; j++) lm = fmaxf(lm, s[lane + j * 32]);
            float gm = lm;
#pragma unroll
            for (int o = 16; o > 0; o >>= 1) gm = fmaxf(gm, __shfl_xor_sync(0xffffffffu, gm, o));
            if (it == 0) mmax = gm;
            kth = gm;
            int li = 0x7fffffff;
#pragma unroll
            for (int j = 10; j >= 0; j--) {
                int idx = lane + j * 32;
                if (s[idx] == gm) li = idx;
            }
            int gi = li;
#pragma unroll
            for (int o = 16; o > 0; o >>= 1) gi = min(gi, __shfl_xor_sync(0xffffffffu, gi, o));
            if (li == gi) s[li] = -INFINITY;
            __syncwarp();
        }

        const float scale = 0.125f;
        float e[11];
        float sum = 0.f;
#pragma unroll
        for (int j = 0; j < 11; j++) {
            int idx = lane + j * 32;
            float v = rc[j];
            float t = (idx < LL && v >= kth) ? expf((v - mmax) * scale) : 0.f;
            e[j] = t;
            sum += t;
        }
#pragma unroll
        for (int o = 16; o > 0; o >>= 1) sum += __shfl_xor_sync(0xffffffffu, sum, o);
        float inv = 1.f / sum;

        size_t row = (size_t)bh * LL + l;
        float* rp = out + row * LL;
        int cnt = 0;
#pragma unroll
        for (int j = 0; j < 11; j++) {
            int idx = lane + j * 32;
            float w = (idx < LL) ? e[j] * inv : 0.f;
            if (idx < LL) rp[idx] = w;
            unsigned mk = __ballot_sync(0xffffffffu, w > 0.f);
            if (w > 0.f) {
                int pos = cnt + __popc(mk & ((1u << lane) - 1u));
                if (pos < 24) { avidx[row * 24 + pos] = (short)idx; avwt[row * 24 + pos] = w; }
            }
            cnt += __popc(mk);
        }
        if (lane == 0) avcnt[row] = (cnt < 24) ? cnt : 24;
        __syncwarp();
    }
}

// ---------------- sparse A @ V from compact lists -> split output ---------------
__global__ __launch_bounds__(256) void av_sparse_kernel(
    const short* __restrict__ avidx, const float* __restrict__ avwt,
    const int* __restrict__ avcnt,
    const float* __restrict__ v, uint32_t* __restrict__ out)
{
    __shared__ short  sidx[8][24];
    __shared__ float  swt[8][24];
    __shared__ int    scnt[8];
    int blk = blockIdx.x;
    int b = blk / LL, l = blk % LL;
    int tid = threadIdx.x;
    int wid = tid >> 5, lane = tid & 31;

    {
        int h = wid;
        size_t row = (size_t)(b * 8 + h) * LL + l;
        if (lane < 24) {
            sidx[h][lane] = avidx[row * 24 + lane];
            swt[h][lane]  = avwt[row * 24 + lane];
        }
        if (lane == 0) scnt[h] = avcnt[row];
    }
    __syncthreads();

    const float* vbase = v + (size_t)b * LL * DD;
#pragma unroll
    for (int e0 = 0; e0 < 2; e0++) {
        int e = tid + e0 * 256;
        int h = e >> 6, c2 = e & 63;
        int n2 = scnt[h];
        const float* vp = vbase + h * EE + c2;
        float acc = 0.f;
        for (int j = 0; j < n2; j++)
            acc = __fmaf_rn(swt[h][j], vp[(size_t)sidx[h][j] * DD], acc);
        out[((size_t)(b * LL + l)) * DD + e] = fsplit(acc);
    }
}

// ---------------- pwattn1 (combined k|v buffer, row stride 1024) ----------------
__global__ __launch_bounds__(128) void pwattn1_kernel(
    const float* __restrict__ q, const float* __restrict__ kv,
    uint32_t* __restrict__ out)
{
    int n = blockIdx.x;
    int l = threadIdx.x;
    __shared__ float sk[512];
    __shared__ float sv[512];
    int t4 = l * 4;
    const float* kvp = kv + (size_t)n * 1024;
    *(float4*)&sk[t4] = *(const float4*)(kvp + t4);
    *(float4*)&sv[t4] = *(const float4*)(kvp + 512 + t4);
    __syncthreads();
    float qr[16];
    const float* qp = q + (size_t)n * 2048 + l * 16;
#pragma unroll
    for (int p = 0; p < 16; p++) qr[p] = qp[p];
    float sc[32];
    float m = -INFINITY;
#pragma unroll
    for (int s = 0; s < 32; s++) {
        float d = 0.f;
#pragma unroll
        for (int p = 0; p < 16; p++) d = fmaf(qr[p], sk[s * 16 + p], d);
        sc[s] = d;
        m = fmaxf(m, d);
    }
    float sum = 0.f;
    float V[16];
#pragma unroll
    for (int p = 0; p < 16; p++) V[p] = 0.f;
#pragma unroll
    for (int s = 0; s < 32; s++) {
        float w = expf((sc[s] - m) * 0.25f);
        sum += w;
#pragma unroll
        for (int p = 0; p < 16; p++) V[p] = fmaf(w, sv[s * 16 + p], V[p]);
    }
    float inv = 1.f / sum;
    uint32_t* op = out + (size_t)n * 2048 + l * 16;
#pragma unroll
    for (int p = 0; p < 16; p++) op[p] = fsplit(V[p] * inv);
}

// ------- pwattn2: combined k|v buffer (stride 4096), single-pass online --------
__global__ __launch_bounds__(128) void pwattn2_kernel(
    const float* __restrict__ q, const float* __restrict__ kv2,
    uint32_t* __restrict__ out)
{
    int n = blockIdx.x * 4 + (threadIdx.x >> 5);
    int lane = threadIdx.x & 31;
    const float* kp = kv2 + (size_t)n * 4096;
    const float* vp = kp + 2048;
    float qr[16];
    const float* qp = q + (size_t)n * 512 + lane * 16;
#pragma unroll
    for (int p = 0; p < 16; p++) qr[p] = qp[p];
    float m = -INFINITY, sum = 0.f;
    float V[16];
#pragma unroll
    for (int p = 0; p < 16; p++) V[p] = 0.f;
    for (int s = 0; s < 128; s++) {
        float d = 0.f;
#pragma unroll
        for (int p = 0; p < 16; p++) d = fmaf(qr[p], kp[s * 16 + p], d);
        if (d > m) {
            float f = expf((m - d) * 0.25f);
            sum *= f;
#pragma unroll
            for (int p = 0; p < 16; p++) V[p] *= f;
            m = d;
        }
        float w = expf((d - m) * 0.25f);
        sum += w;
#pragma unroll
        for (int p = 0; p < 16; p++) V[p] = fmaf(w, vp[s * 16 + p], V[p]);
    }
    float inv = 1.f / sum;
    uint32_t* op = out + (size_t)n * 512 + lane * 16;
#pragma unroll
    for (int p = 0; p < 16; p++) op[p] = fsplit(V[p] * inv);
}

// ---------------- layernorm over 2048 -> split output ---------------------------
__global__ __launch_bounds__(256) void ln_kernel(
    const float* __restrict__ in, const float* __restrict__ g,
    const float* __restrict__ b, uint32_t* __restrict__ out)
{
    int n = blockIdx.x;
    int tid = threadIdx.x;
    __shared__ float red[256];
    const float* x = in + (size_t)n * 2048;
    float s = 0.f;
    for (int i = tid; i < 2048; i += 256) s += x[i];
    red[tid] = s; __syncthreads();
    for (int o = 128; o > 0; o >>= 1) { if (tid < o) red[tid] += red[tid + o]; __syncthreads(); }
    float mean = red[0] * (1.f / 2048.f);
    __syncthreads();
    float vs = 0.f;
    for (int i = tid; i < 2048; i += 256) { float d = x[i] - mean; vs += d * d; }
    red[tid] = vs; __syncthreads();
    for (int o = 128; o > 0; o >>= 1) { if (tid < o) red[tid] += red[tid + o]; __syncthreads(); }
    float var = red[0] * (1.f / 2048.f);
    float inv = rsqrtf(var + 1e-5f);
    uint32_t* op = out + (size_t)n * 2048;
    for (int i = tid; i < 2048; i += 256) op[i] = fsplit((x[i] - mean) * inv * g[i] + b[i]);
}

// ---------------- launch --------------------------------------------------------
extern "C" void kernel_launch(void* const* d_in, const int* in_sizes, int n_in,
                              void* d_out, int out_size)
{
    (void)in_sizes; (void)n_in; (void)out_size;
    const float* x     = (const float*)d_in[0];
    const float* aqw   = (const float*)d_in[1];
    const float* aqb   = (const float*)d_in[2];
    const float* akw   = (const float*)d_in[3];
    const float* akb   = (const float*)d_in[4];
    const float* avw   = (const float*)d_in[5];
    const float* avb   = (const float*)d_in[6];
    const float* aow   = (const float*)d_in[7];
    const float* aob   = (const float*)d_in[8];
    const float* encw  = (const float*)d_in[9];
    const float* encb  = (const float*)d_in[10];
    const float* f1qw  = (const float*)d_in[11];
    const float* f1qb  = (const float*)d_in[12];
    const float* f1kw  = (const float*)d_in[13];
    const float* f1kb  = (const float*)d_in[14];
    const float* f1vw  = (const float*)d_in[15];
    const float* f1vb  = (const float*)d_in[16];
    const float* f1ow  = (const float*)d_in[17];
    const float* f1ob  = (const float*)d_in[18];
    const float* f2qw  = (const float*)d_in[19];
    const float* f2qb  = (const float*)d_in[20];
    const float* f2kw  = (const float*)d_in[21];
    const float* f2kb  = (const float*)d_in[22];
    const float* f2vw  = (const float*)d_in[23];
    const float* f2vb  = (const float*)d_in[24];
    const float* f2ow  = (const float*)d_in[25];
    const float* f2ob  = (const float*)d_in[26];
    const float* lng   = (const float*)d_in[27];
    const float* lnb   = (const float*)d_in[28];

    float* out  = (float*)d_out;
    float* Aout = out + (size_t)NROWS * 512;

    float* b512; float* b2048; uint32_t* sps; uint32_t* spb; uint32_t* wt;
    short* avidx; float* avwt; int* avcnt;
    cudaGetSymbolAddress((void**)&b512,  g_buf512);
    cudaGetSymbolAddress((void**)&b2048, g_buf2048);
    cudaGetSymbolAddress((void**)&sps,   g_sp_small);
    cudaGetSymbolAddress((void**)&spb,   g_sp_big);
    cudaGetSymbolAddress((void**)&wt,    g_wt);
    cudaGetSymbolAddress((void**)&avidx, g_avidx);
    cudaGetSymbolAddress((void**)&avwt,  g_avwt);
    cudaGetSymbolAddress((void**)&avcnt, g_avcnt);
    const size_t S = (size_t)NROWS * 512;
    const size_t T = (size_t)NROWS * 2048;
    float* qb   = b512;
    float* kb   = b512 + S;
    float* vb   = b512 + 2 * S;
    float* kv1  = b512 + 3 * S;
    float* qu2  = b512 + 5 * S;
    float* q1   = b2048;
    float* t1   = b2048 + T;
    float* kv2  = b2048 + 2 * T;
    uint32_t* x_sp   = sps;
    uint32_t* att_sp = sps + S;
    uint32_t* zb_sp  = sps + 2 * S;
    uint32_t* y2_sp  = sps + 3 * S;
    uint32_t* Vf1_sp = spb;
    uint32_t* u_sp   = spb + T;

    cudaFuncSetAttribute(mm_gemm_kernel<0,1>, cudaFuncAttributeMaxDynamicSharedMemorySize, MM_SMEM);
    cudaFuncSetAttribute(mm_gemm_kernel<1,0>, cudaFuncAttributeMaxDynamicSharedMemorySize, MM_SMEM);
    cudaFuncSetAttribute(mm_gemm_kernel<2,1>, cudaFuncAttributeMaxDynamicSharedMemorySize, MM_SMEM);
    cudaFuncSetAttribute(mm_gemm_kernel<3,0>, cudaFuncAttributeMaxDynamicSharedMemorySize, MM_SMEM);
    cudaFuncSetAttribute(mm_gemm_kernel<4,0>, cudaFuncAttributeMaxDynamicSharedMemorySize, MM_SMEM);
    cudaFuncSetAttribute(mm_gemm_kernel<5,0>, cudaFuncAttributeMaxDynamicSharedMemorySize, MM_SMEM);
    cudaFuncSetAttribute(scores_topk_kernel, cudaFuncAttributeMaxDynamicSharedMemorySize, ST_SMEM);

    static cudaStream_t s2 = nullptr;
    static cudaEvent_t evF = nullptr, evJ = nullptr, evF1 = nullptr, evJ1 = nullptr,
                       evF2 = nullptr, evJ2 = nullptr;
    if (!s2) {
        cudaStreamCreateWithFlags(&s2, cudaStreamNonBlocking);
        cudaEventCreateWithFlags(&evF,  cudaEventDisableTiming);
        cudaEventCreateWithFlags(&evJ,  cudaEventDisableTiming);
        cudaEventCreateWithFlags(&evF1, cudaEventDisableTiming);
        cudaEventCreateWithFlags(&evJ1, cudaEventDisableTiming);
        cudaEventCreateWithFlags(&evF2, cudaEventDisableTiming);
        cudaEventCreateWithFlags(&evJ2, cudaEventDisableTiming);
    }

    dim3 blk(256);
    dim3 tb(32, 8);
    dim3 tg512(8, (NROWS + 127) / 128);
    dim3 tg1024(16, (NROWS + 127) / 128);
    dim3 tg2048(32, (NROWS + 127) / 128);
    dim3 tg4096(64, (NROWS + 127) / 128);
    dim3 kg(8, (NROWS + 63) / 64, 2);

    // ===== fork 0: A-path on s2 ∥ transpose/convert/av on main =================
    cudaEventRecord(evF, 0);
    cudaStreamWaitEvent(s2, evF, 0);

    kgemm_qk_kernel<<<kg, blk, 0, s2>>>(x, aqw, aqb, qb, akw, akb, kb, NROWS, 512, 512);
    scores_topk_kernel<<<dim3(11, 512), blk, ST_SMEM, s2>>>(qb, kb, Aout, avidx, avwt, avcnt);
    cudaEventRecord(evJ, s2);

    {
        TransArgs ta;
        const float* srcs[11] = {avw, aow, encw, f1qw, f1kw, f1vw, f1ow, f2qw, f2kw, f2vw, f2ow};
        uint32_t offs[11] = {OFF_AV, OFF_AO, OFF_ENC, OFF_F1Q, OFF_F1K, OFF_F1V,
                             OFF_F1O, OFF_F2Q, OFF_F2K, OFF_F2V, OFF_F2O};
        int Ks[11] = {512, 512, 512, 512, 512, 512, 2048, 2048, 2048, 2048, 512};
        int Ns[11] = {512, 512, 512, 2048, 512, 512, 2048, 512, 2048, 2048, 512};
        int acc = 0;
        for (int j = 0; j < 11; j++) {
            ta.job[j].src = srcs[j];
            ta.job[j].dstoff = offs[j];
            ta.job[j].K = Ks[j];
            ta.job[j].N = Ns[j];
            ta.job[j].tstart = acc;
            acc += (Ns[j] >> 5) * (Ks[j] >> 5);
        }
        transpose_split_all<<<acc, tb>>>(ta);
    }
    convert_kernel<<<4096, 256>>>(x, x_sp, (int)S);
    mm_gemm_kernel<1,0><<<tg512, blk, MM_SMEM>>>(x_sp, wt + OFF_AV, avb, nullptr, vb, NROWS, 512, 512);

    cudaStreamWaitEvent(0, evJ, 0);   // join 0
    // ===========================================================================

    av_sparse_kernel<<<NROWS, blk>>>(avidx, avwt, avcnt, vb, att_sp);
    mm_gemm_kernel<2,1><<<tg512, blk, MM_SMEM>>>(att_sp, wt + OFF_AO, aob, x, zb_sp, NROWS, 512, 512);
    mm_gemm_kernel<0,1><<<tg512, blk, MM_SMEM>>>(zb_sp, wt + OFF_ENC, encb, nullptr, y2_sp, NROWS, 512, 512);

    // ---- ff1: f1q (main) ∥ f1kv (s2) ----
    cudaEventRecord(evF1, 0);
    cudaStreamWaitEvent(s2, evF1, 0);
    mm_gemm_kernel<5,0><<<tg1024, blk, MM_SMEM, s2>>>(y2_sp, wt + OFF_F1K, f1kb, f1vb, kv1, NROWS, 1024, 512);
    cudaEventRecord(evJ1, s2);
    mm_gemm_kernel<1,0><<<tg2048, blk, MM_SMEM>>>(y2_sp, wt + OFF_F1Q, f1qb, nullptr, q1, NROWS, 2048, 512);
    cudaStreamWaitEvent(0, evJ1, 0);

    pwattn1_kernel<<<NROWS, 128>>>(q1, kv1, Vf1_sp);
    mm_gemm_kernel<3,0><<<tg2048, blk, MM_SMEM>>>(Vf1_sp, wt + OFF_F1O, f1ob, q1, t1, NROWS, 2048, 2048);
    ln_kernel<<<NROWS, blk>>>(t1, lng, lnb, u_sp);

    // ---- ff2: f2q (s2) ∥ f2kv (main) ----
    cudaEventRecord(evF2, 0);
    cudaStreamWaitEvent(s2, evF2, 0);
    mm_gemm_kernel<1,0><<<tg512, blk, MM_SMEM, s2>>>(u_sp, wt + OFF_F2Q, f2qb, nullptr, qu2, NROWS, 512, 2048);
    cudaEventRecord(evJ2, s2);
    mm_gemm_kernel<5,0><<<tg4096, blk, MM_SMEM>>>(u_sp, wt + OFF_F2K, f2kb, f2vb, kv2, NROWS, 4096, 2048);
    cudaStreamWaitEvent(0, evJ2, 0);

    pwattn2_kernel<<<NROWS / 4, 128>>>(qu2, kv2, x_sp);
    mm_gemm_kernel<4,0><<<tg512, blk, MM_SMEM>>>(x_sp, wt + OFF_F2O, f2ob, qu2, out, NROWS, 512, 512);
}

// round 16
// speedup vs baseline: 1.1078x; 1.0113x over previous
#include <cuda_runtime.h>
#include <cuda_bf16.h>
#include <math.h>
#include <stdint.h>

#define NROWS 20544     // B*L = 64*321
#define LL 321
#define DD 512
#define HH 8
#define EE 64
#define NTOPK 10

// ---------------- scratch (allocation-free: __device__ globals) ----------------
__device__ float    g_buf512[6ULL * NROWS * 512];
__device__ float    g_buf2048[4ULL * NROWS * 2048];
__device__ uint32_t g_sp_small[4ULL * NROWS * 512];  // 4 planar split buffers (512-wide)
__device__ uint32_t g_sp_big[2ULL * NROWS * 2048];   // 2 planar split buffers (2048-wide)
__device__ uint32_t g_wt[16252928];                  // planar split transposed weights
__device__ short    g_avidx[164352 * 24];
__device__ float    g_avwt[164352 * 24];
__device__ int      g_avcnt[164352];

#define OFF_AV   0u
#define OFF_AO   262144u
#define OFF_ENC  524288u
#define OFF_F1Q  786432u
#define OFF_F1K  1835008u
#define OFF_F1V  2097152u
#define OFF_F1O  2359296u
#define OFF_F2Q  6553600u
#define OFF_F2K  7602176u
#define OFF_F2V  11796480u
#define OFF_F2O  15990784u

// ---------------- bf16 split helpers (planar) -----------------------------------
__device__ __forceinline__ void fsplit2(float x, uint16_t& h, uint16_t& l) {
    __nv_bfloat16 hb = __float2bfloat16(x);
    float hf = __bfloat162float(hb);
    __nv_bfloat16 lb = __float2bfloat16(x - hf);
    h = __bfloat16_as_ushort(hb);
    l = __bfloat16_as_ushort(lb);
}

// ------------- blocked compensation: Kahan-merge a block partial ---------------
__device__ __forceinline__ void kadd(float p, float& s, float& c) {
    float y = __fsub_rn(p, c);
    float t = __fadd_rn(s, y);
    c = __fsub_rn(__fsub_rn(t, s), y);
    s = t;
}
__device__ __forceinline__ float kfin(float s, float c) { return __fsub_rn(s, c); }

// ==================== batched weight transpose + planar split ===================
struct TransJob { const float* src; uint32_t dstoff; int K; int N; int tstart; };
struct TransArgs { TransJob job[11]; };

__global__ void transpose_split_all(TransArgs a)
{
    __shared__ float t[32][33];
    int tile = blockIdx.x;
    int ji = 0;
#pragma unroll
    for (int j = 1; j < 11; j++)
        if (tile >= a.job[j].tstart) ji = j;
    const TransJob& J = a.job[ji];
    int local = tile - J.tstart;
    int ntx = J.N >> 5;
    int bx = (local % ntx) * 32, by = (local / ntx) * 32;
    int txi = threadIdx.x, tyi = threadIdx.y;
    const float* src = J.src;
    uint16_t* dst = (uint16_t*)g_wt + 2ULL * J.dstoff;
    size_t plane = (size_t)J.N * J.K;
#pragma unroll
    for (int j = 0; j < 32; j += 8)
        t[tyi + j][txi] = src[(size_t)(by + tyi + j) * J.N + bx + txi];
    __syncthreads();
#pragma unroll
    for (int j = 0; j < 32; j += 8) {
        uint16_t h, l;
        fsplit2(t[txi][tyi + j], h, l);
        size_t o = (size_t)(bx + tyi + j) * J.K + by + txi;
        dst[o] = h;
        dst[plane + o] = l;
    }
}

__global__ void convert_kernel(const float* __restrict__ in, uint16_t* __restrict__ outp, int n)
{
    for (int i = blockIdx.x * 256 + threadIdx.x; i < n; i += gridDim.x * 256) {
        uint16_t h, l;
        fsplit2(in[i], h, l);
        outp[i] = h;
        outp[(size_t)n + i] = l;
    }
}

// ===== bf16x3 mma.sync GEMM: planar smem + ldmatrix, 128x64 tile, 2 CTA/SM =====
// smem stage (bytes): A_hi 10240, A_lo 10240, B_hi 5120, B_lo 5120 = 30720; x2
#define MM_STAGE_B 30720
#define MM_SMEM    (2 * MM_STAGE_B)

__device__ __forceinline__ void mm_load_stage(
    const uint16_t* __restrict__ A, size_t aPlane,
    const uint16_t* __restrict__ B, size_t bPlane,
    int bm, int bn, int M, int K, int k0, uint32_t sb, int tid)
{
#pragma unroll
    for (int j = 0; j < 6; j++) {
        int idx = tid + j * 256;
        if (idx < 1024) {                        // A: 2 planes x 128 rows x 4 chunks
            int plane = idx >> 9;
            int i2 = idx & 511;
            int r = i2 >> 2, c = i2 & 3;
            uint32_t dst = sb + plane * 10240 + r * 80 + c * 16;
            int grow = bm + r;
            const uint16_t* src = A + (size_t)plane * aPlane
                                + (size_t)(grow < M ? grow : 0) * K + k0 + c * 8;
            int sz = (grow < M) ? 16 : 0;
            asm volatile("cp.async.ca.shared.global [%0], [%1], 16, %2;"
                         :: "r"(dst), "l"(src), "r"(sz));
        } else {                                 // B: 2 planes x 64 rows x 4 chunks
            int i3 = idx - 1024;
            int plane = i3 >> 8;
            int i2 = i3 & 255;
            int r = i2 >> 2, c = i2 & 3;
            uint32_t dst = sb + 20480 + plane * 5120 + r * 80 + c * 16;
            const uint16_t* src = B + (size_t)plane * bPlane
                                + (size_t)(bn + r) * K + k0 + c * 8;
            asm volatile("cp.async.ca.shared.global [%0], [%1], 16;"
                         :: "r"(dst), "l"(src));
        }
    }
    asm volatile("cp.async.commit_group;" ::: "memory");
}

#define LDMX4(r0, r1, r2, r3, addr) \
    asm volatile("ldmatrix.sync.aligned.m8n8.x4.shared.b16 {%0,%1,%2,%3}, [%4];" \
                 : "=r"(r0), "=r"(r1), "=r"(r2), "=r"(r3) : "r"(addr))

#define MMA_BF16(acc, a0, a1, a2, a3, b0, b1) \
    asm volatile( \
        "mma.sync.aligned.m16n8k16.row.col.f32.bf16.bf16.f32 " \
        "{%0,%1,%2,%3}, {%4,%5,%6,%7}, {%8,%9}, {%0,%1,%2,%3};" \
        : "+f"((acc)[0]), "+f"((acc)[1]), "+f"((acc)[2]), "+f"((acc)[3]) \
        : "r"(a0), "r"(a1), "r"(a2), "r"(a3), "r"(b0), "r"(b1))

// EP: 0=bias, 1=bias+relu, 2=bias+res+leaky, 3=bias+res+elu, 4=bias+res,
//     5=dual-bias (bias=lower half, res=upper-half bias), relu on upper half
// OM: 0 -> f32 out, 1 -> planar split u16 out
template<int EP, int OM>
__global__ __launch_bounds__(256, 2)
void mm_gemm_kernel(const uint16_t* __restrict__ A, const uint16_t* __restrict__ Bt,
                    const float* __restrict__ bias, const float* __restrict__ res,
                    void* __restrict__ Cv, int M, int N, int K)
{
    extern __shared__ uint32_t smraw[];
    uint32_t s0;
    asm("{ .reg .u64 t; cvta.to.shared.u64 t, %1; cvt.u32.u64 %0, t; }" : "=r"(s0) : "l"(smraw));
    const int tid = threadIdx.x;
    const int wid = tid >> 5, lane = tid & 31;
    const int wm = wid >> 1, wn = wid & 1;
    const int g = lane >> 2, t = lane & 3;
    const int bm = blockIdx.y * 128, bn = blockIdx.x * 64;

    // planar B region select (EP5: two adjacent half-regions)
    const int halfN = N >> 1;
    const uint16_t* Bu = Bt;
    int bnl = bn;
    int bN = N;
    if (EP == 5) {
        bN = halfN;
        if (bn >= halfN) { Bu += (size_t)2 * halfN * K; bnl = bn - halfN; }
    }
    const size_t aPlane = (size_t)M * K;
    const size_t bPlane = (size_t)bN * K;

    float acc[2][4][4];
#pragma unroll
    for (int i = 0; i < 2; i++)
#pragma unroll
        for (int j = 0; j < 4; j++)
#pragma unroll
            for (int q = 0; q < 4; q++) acc[i][j][q] = 0.f;

    const int nc = K >> 5;
    mm_load_stage(A, aPlane, Bu, bPlane, bm, bnl, M, K, 0, s0, tid);

    const uint32_t laneA = (uint32_t)(((lane & 7) + (lane & 8)) * 80 + ((lane >> 4) & 1) * 16);
    const uint32_t laneB = (uint32_t)(((lane & 7) + ((lane >> 1) & 8)) * 80 + ((lane >> 3) & 1) * 16);
    const uint32_t aRow = (uint32_t)(wm * 32) * 80;
    const uint32_t bRow = (uint32_t)(wn * 32) * 80;

    for (int c = 0; c < nc; c++) {
        if (c + 1 < nc)
            mm_load_stage(A, aPlane, Bu, bPlane, bm, bnl, M, K, (c + 1) * 32,
                          s0 + ((c + 1) & 1) * MM_STAGE_B, tid);
        if (c + 1 < nc) asm volatile("cp.async.wait_group 1;" ::: "memory");
        else            asm volatile("cp.async.wait_group 0;" ::: "memory");
        __syncthreads();

        uint32_t sb = s0 + (c & 1) * MM_STAGE_B;
#pragma unroll
        for (int ks = 0; ks < 2; ks++) {
            uint32_t ka = ks * 32;
            uint32_t ah[2][4], al[2][4], bh[4][2], bl[4][2];
            LDMX4(ah[0][0], ah[0][1], ah[0][2], ah[0][3], sb + aRow + laneA + ka);
            LDMX4(ah[1][0], ah[1][1], ah[1][2], ah[1][3], sb + aRow + 1280 + laneA + ka);
            LDMX4(al[0][0], al[0][1], al[0][2], al[0][3], sb + 10240 + aRow + laneA + ka);
            LDMX4(al[1][0], al[1][1], al[1][2], al[1][3], sb + 10240 + aRow + 1280 + laneA + ka);
            LDMX4(bh[0][0], bh[0][1], bh[1][0], bh[1][1], sb + 20480 + bRow + laneB + ka);
            LDMX4(bh[2][0], bh[2][1], bh[3][0], bh[3][1], sb + 20480 + bRow + 1280 + laneB + ka);
            LDMX4(bl[0][0], bl[0][1], bl[1][0], bl[1][1], sb + 25600 + bRow + laneB + ka);
            LDMX4(bl[2][0], bl[2][1], bl[3][0], bl[3][1], sb + 25600 + bRow + 1280 + laneB + ka);
#pragma unroll
            for (int mt = 0; mt < 2; mt++)
#pragma unroll
                for (int nt = 0; nt < 4; nt++)
                    MMA_BF16(acc[mt][nt], ah[mt][0], ah[mt][1], ah[mt][2], ah[mt][3],
                             bl[nt][0], bl[nt][1]);
#pragma unroll
            for (int mt = 0; mt < 2; mt++)
#pragma unroll
                for (int nt = 0; nt < 4; nt++)
                    MMA_BF16(acc[mt][nt], al[mt][0], al[mt][1], al[mt][2], al[mt][3],
                             bh[nt][0], bh[nt][1]);
#pragma unroll
            for (int mt = 0; mt < 2; mt++)
#pragma unroll
                for (int nt = 0; nt < 4; nt++)
                    MMA_BF16(acc[mt][nt], ah[mt][0], ah[mt][1], ah[mt][2], ah[mt][3],
                             bh[nt][0], bh[nt][1]);
        }
        __syncthreads();
    }

    float* Cf = (float*)Cv;
    uint16_t* Cs = (uint16_t*)Cv;
    const size_t oPlane = (size_t)M * N;
    const bool upper = (EP == 5) && (bn >= halfN);
    const float* bp = (EP == 5) ? (upper ? res - halfN : bias) : bias;
#pragma unroll
    for (int mt = 0; mt < 2; mt++) {
#pragma unroll
        for (int hf2 = 0; hf2 < 2; hf2++) {
            int row = bm + wm * 32 + mt * 16 + g + hf2 * 8;
            if (row >= M) continue;
#pragma unroll
            for (int nt = 0; nt < 4; nt++) {
                int col = bn + wn * 32 + nt * 8 + t * 2;
                float v0 = acc[mt][nt][hf2 * 2 + 0] + bp[col];
                float v1 = acc[mt][nt][hf2 * 2 + 1] + bp[col + 1];
                if (EP >= 2 && EP <= 4) {
                    v0 += res[(size_t)row * N + col];
                    v1 += res[(size_t)row * N + col + 1];
                }
                if (EP == 1 || (EP == 5 && upper)) { v0 = fmaxf(v0, 0.f); v1 = fmaxf(v1, 0.f); }
                if (EP == 2) { v0 = (v0 > 0.f) ? v0 : 0.5f * v0; v1 = (v1 > 0.f) ? v1 : 0.5f * v1; }
                if (EP == 3) { v0 = (v0 > 0.f) ? v0 : expm1f(v0); v1 = (v1 > 0.f) ? v1 : expm1f(v1); }
                if (OM == 0) {
                    *(float2*)(Cf + (size_t)row * N + col) = make_float2(v0, v1);
                } else {
                    uint16_t h0, l0, h1, l1;
                    fsplit2(v0, h0, l0);
                    fsplit2(v1, h1, l1);
                    *(uint32_t*)(Cs + (size_t)row * N + col) =
                        (uint32_t)h0 | ((uint32_t)h1 << 16);
                    *(uint32_t*)(Cs + oPlane + (size_t)row * N + col) =
                        (uint32_t)l0 | ((uint32_t)l1 << 16);
                }
            }
        }
    }
}

// ---------- blocked-compensated fp32 GEMM (block 16), q & k fused (grid.z) -----
__global__ __launch_bounds__(256) void kgemm_qk_kernel(
    const float* __restrict__ A,
    const float* __restrict__ Bq, const float* __restrict__ bq, float* __restrict__ Cq,
    const float* __restrict__ Bk, const float* __restrict__ bk, float* __restrict__ Ck,
    int M, int N, int K)
{
    const float* B  = blockIdx.z ? Bk : Bq;
    const float* bb = blockIdx.z ? bk : bq;
    float* C        = blockIdx.z ? Ck : Cq;
    const int relu  = blockIdx.z ? 0 : 1;

    __shared__ float As[16][68];
    __shared__ float Bs[16][68];
    const int tid = threadIdx.x;
    const int bm = blockIdx.y * 64;
    const int bn = blockIdx.x * 64;
    const int ty = tid >> 4, tx = tid & 15;

    float s[4][4], cc[4][4];
#pragma unroll
    for (int i = 0; i < 4; i++)
#pragma unroll
        for (int j = 0; j < 4; j++) { s[i][j] = 0.f; cc[i][j] = 0.f; }

    const int ar = tid >> 2;
    const int ac = (tid & 3) << 2;
    const int br = tid >> 4;
    const int bc = (tid & 15) << 2;

    for (int k0 = 0; k0 < K; k0 += 16) {
        {
            int grow = bm + ar;
            float4 v = make_float4(0.f, 0.f, 0.f, 0.f);
            if (grow < M) v = *(const float4*)(A + (size_t)grow * K + k0 + ac);
            As[ac + 0][ar] = v.x; As[ac + 1][ar] = v.y;
            As[ac + 2][ar] = v.z; As[ac + 3][ar] = v.w;
        }
        *(float4*)&Bs[br][bc] = *(const float4*)(B + (size_t)(k0 + br) * N + bn + bc);
        __syncthreads();
        {
            float p[4][4];
#pragma unroll
            for (int i = 0; i < 4; i++)
#pragma unroll
                for (int j = 0; j < 4; j++) p[i][j] = 0.f;
#pragma unroll
            for (int kk = 0; kk < 16; kk++) {
                float4 av = *(const float4*)&As[kk][ty * 4];
                float4 bv = *(const float4*)&Bs[kk][tx * 4];
                const float* a = (const float*)&av;
                const float* b = (const float*)&bv;
#pragma unroll
                for (int i = 0; i < 4; i++)
#pragma unroll
                    for (int j = 0; j < 4; j++)
                        p[i][j] = __fmaf_rn(a[i], b[j], p[i][j]);
            }
#pragma unroll
            for (int i = 0; i < 4; i++)
#pragma unroll
                for (int j = 0; j < 4; j++)
                    kadd(p[i][j], s[i][j], cc[i][j]);
        }
        __syncthreads();
    }

#pragma unroll
    for (int i = 0; i < 4; i++) {
        int row = bm + ty * 4 + i;
        if (row < M) {
            float4 o;
            float* ov = (float*)&o;
#pragma unroll
            for (int j = 0; j < 4; j++) {
                float v = __fadd_rn(kfin(s[i][j], cc[i][j]), bb[bn + tx * 4 + j]);
                if (relu) v = fmaxf(v, 0.f);
                ov[j] = v;
            }
            *(float4*)(C + (size_t)row * N + bn + tx * 4) = o;
        }
    }
}

// ========== FUSED scores + top-k + softmax + compact-list emission =============
#define ST_SMEM ((32 * 72 * 2 + 32 * 360) * 4)

__global__ __launch_bounds__(256) void scores_topk_kernel(
    const float* __restrict__ q, const float* __restrict__ k, float* __restrict__ out,
    short* __restrict__ avidx, float* __restrict__ avwt, int* __restrict__ avcnt)
{
    extern __shared__ float shb[];
    float (*Qs)[72]  = (float(*)[72])shb;
    float (*Ks)[72]  = (float(*)[72])(shb + 32 * 72);
    float (*SC)[360] = (float(*)[360])(shb + 2 * 32 * 72);

    int bh = blockIdx.y;
    int b = bh >> 3, h = bh & 7;
    int l0 = blockIdx.x * 32;
    int tid = threadIdx.x;
    int r = tid >> 3;
    int c = (tid & 7) * 8;
    {
        int l = l0 + r;
        if (l < LL) {
            const float* src = q + ((size_t)(b * LL + l)) * DD + h * EE + c;
            *(float4*)&Qs[r][c]     = *(const float4*)src;
            *(float4*)&Qs[r][c + 4] = *(const float4*)(src + 4);
        } else {
#pragma unroll
            for (int t = 0; t < 8; t++) Qs[r][c + t] = 0.f;
        }
    }
    int ty = tid >> 4, tx = tid & 15;

    for (int s0 = 0; s0 < 352; s0 += 32) {
        __syncthreads();
        {
            int sdx = s0 + r;
            if (sdx < LL) {
                const float* src = k + ((size_t)(b * LL + sdx)) * DD + h * EE + c;
                *(float4*)&Ks[r][c]     = *(const float4*)src;
                *(float4*)&Ks[r][c + 4] = *(const float4*)(src + 4);
            } else {
#pragma unroll
                for (int t = 0; t < 8; t++) Ks[r][c + t] = 0.f;
            }
        }
        __syncthreads();
        float s00 = 0.f, s01 = 0.f, s10 = 0.f, s11 = 0.f;
        float c00 = 0.f, c01 = 0.f, c10 = 0.f, c11 = 0.f;
#pragma unroll
        for (int blkk = 0; blkk < 4; blkk++) {
            float p00 = 0.f, p01 = 0.f, p10 = 0.f, p11 = 0.f;
#pragma unroll
            for (int kk = blkk * 16; kk < blkk * 16 + 16; kk++) {
                float a0 = Qs[ty * 2 + 0][kk], a1 = Qs[ty * 2 + 1][kk];
                float b0 = Ks[tx * 2 + 0][kk], b1 = Ks[tx * 2 + 1][kk];
                p00 = __fmaf_rn(a0, b0, p00);
                p01 = __fmaf_rn(a0, b1, p01);
                p10 = __fmaf_rn(a1, b0, p10);
                p11 = __fmaf_rn(a1, b1, p11);
            }
            kadd(p00, s00, c00);
            kadd(p01, s01, c01);
            kadd(p10, s10, c10);
            kadd(p11, s11, c11);
        }
        SC[ty * 2 + 0][s0 + tx * 2 + 0] = kfin(s00, c00);
        SC[ty * 2 + 0][s0 + tx * 2 + 1] = kfin(s01, c01);
        SC[ty * 2 + 1][s0 + tx * 2 + 0] = kfin(s10, c10);
        SC[ty * 2 + 1][s0 + tx * 2 + 1] = kfin(s11, c11);
    }
    __syncthreads();

    int wid = tid >> 5, lane = tid & 31;
    for (int rr = 0; rr < 4; rr++) {
        int lrow = wid * 4 + rr;
        int l = l0 + lrow;
        if (l >= LL) break;
        float* s = SC[lrow];
        float rc[11];
#pragma unroll
        for (int j = 0; j < 11; j++) {
            int idx = lane + j * 32;
            float v = (idx < LL) ? s[idx] : -INFINITY;
            rc[j] = v;
            s[idx] = v;
        }
        __syncwarp();

        float kth = 0.f, mmax = 0.f;
        for (int it = 0; it < NTOPK; it++) {
            float lm = -INFINITY;
#pragma unroll
            for (int j = 0; j < 11; j++) lm = fmaxf(lm, s[lane + j * 32]);
            float gm = lm;
#pragma unroll
            for (int o = 16; o > 0; o >>= 1) gm = fmaxf(gm, __shfl_xor_sync(0xffffffffu, gm, o));
            if (it == 0) mmax = gm;
            kth = gm;
            int li = 0x7fffffff;
#pragma unroll
            for (int j = 10; j >= 0; j--) {
                int idx = lane + j * 32;
                if (s[idx] == gm) li = idx;
            }
            int gi = li;
#pragma unroll
            for (int o = 16; o > 0; o >>= 1) gi = min(gi, __shfl_xor_sync(0xffffffffu, gi, o));
            if (li == gi) s[li] = -INFINITY;
            __syncwarp();
        }

        const float scale = 0.125f;
        float e[11];
        float sum = 0.f;
#pragma unroll
        for (int j = 0; j < 11; j++) {
            int idx = lane + j * 32;
            float v = rc[j];
            float t = (idx < LL && v >= kth) ? expf((v - mmax) * scale) : 0.f;
            e[j] = t;
            sum += t;
        }
#pragma unroll
        for (int o = 16; o > 0; o >>= 1) sum += __shfl_xor_sync(0xffffffffu, sum, o);
        float inv = 1.f / sum;

        size_t row = (size_t)bh * LL + l;
        float* rp = out + row * LL;
        int cnt = 0;
#pragma unroll
        for (int j = 0; j < 11; j++) {
            int idx = lane + j * 32;
            float w = (idx < LL) ? e[j] * inv : 0.f;
            if (idx < LL) rp[idx] = w;
            unsigned mk = __ballot_sync(0xffffffffu, w > 0.f);
            if (w > 0.f) {
                int pos = cnt + __popc(mk & ((1u << lane) - 1u));
                if (pos < 24) { avidx[row * 24 + pos] = (short)idx; avwt[row * 24 + pos] = w; }
            }
            cnt += __popc(mk);
        }
        if (lane == 0) avcnt[row] = (cnt < 24) ? cnt : 24;
        __syncwarp();
    }
}

// ---------------- sparse A @ V from compact lists -> planar split out -----------
__global__ __launch_bounds__(256) void av_sparse_kernel(
    const short* __restrict__ avidx, const float* __restrict__ avwt,
    const int* __restrict__ avcnt,
    const float* __restrict__ v, uint16_t* __restrict__ out)
{
    __shared__ short  sidx[8][24];
    __shared__ float  swt[8][24];
    __shared__ int    scnt[8];
    int blk = blockIdx.x;
    int b = blk / LL, l = blk % LL;
    int tid = threadIdx.x;
    int wid = tid >> 5, lane = tid & 31;
    const size_t oPlane = (size_t)NROWS * 512;

    {
        int h = wid;
        size_t row = (size_t)(b * 8 + h) * LL + l;
        if (lane < 24) {
            sidx[h][lane] = avidx[row * 24 + lane];
            swt[h][lane]  = avwt[row * 24 + lane];
        }
        if (lane == 0) scnt[h] = avcnt[row];
    }
    __syncthreads();

    const float* vbase = v + (size_t)b * LL * DD;
#pragma unroll
    for (int e0 = 0; e0 < 2; e0++) {
        int e = tid + e0 * 256;
        int h = e >> 6, c2 = e & 63;
        int n2 = scnt[h];
        const float* vp = vbase + h * EE + c2;
        float acc = 0.f;
        for (int j = 0; j < n2; j++)
            acc = __fmaf_rn(swt[h][j], vp[(size_t)sidx[h][j] * DD], acc);
        uint16_t hh, ll;
        fsplit2(acc, hh, ll);
        size_t o = ((size_t)(b * LL + l)) * DD + e;
        out[o] = hh;
        out[oPlane + o] = ll;
    }
}

// ---------------- pwattn1 (combined k|v, stride 1024) -> planar split ----------
__global__ __launch_bounds__(128) void pwattn1_kernel(
    const float* __restrict__ q, const float* __restrict__ kv,
    uint16_t* __restrict__ out)
{
    int n = blockIdx.x;
    int l = threadIdx.x;
    __shared__ float sk[512];
    __shared__ float sv[512];
    int t4 = l * 4;
    const float* kvp = kv + (size_t)n * 1024;
    *(float4*)&sk[t4] = *(const float4*)(kvp + t4);
    *(float4*)&sv[t4] = *(const float4*)(kvp + 512 + t4);
    __syncthreads();
    float qr[16];
    const float* qp = q + (size_t)n * 2048 + l * 16;
#pragma unroll
    for (int p = 0; p < 16; p++) qr[p] = qp[p];
    float sc[32];
    float m = -INFINITY;
#pragma unroll
    for (int s = 0; s < 32; s++) {
        float d = 0.f;
#pragma unroll
        for (int p = 0; p < 16; p++) d = fmaf(qr[p], sk[s * 16 + p], d);
        sc[s] = d;
        m = fmaxf(m, d);
    }
    float sum = 0.f;
    float V[16];
#pragma unroll
    for (int p = 0; p < 16; p++) V[p] = 0.f;
#pragma unroll
    for (int s = 0; s < 32; s++) {
        float w = expf((sc[s] - m) * 0.25f);
        sum += w;
#pragma unroll
        for (int p = 0; p < 16; p++) V[p] = fmaf(w, sv[s * 16 + p], V[p]);
    }
    float inv = 1.f / sum;
    const size_t oPlane = (size_t)NROWS * 2048;
    size_t base = (size_t)n * 2048 + l * 16;
    uint16_t hh[16], ll[16];
#pragma unroll
    for (int p = 0; p < 16; p++) fsplit2(V[p] * inv, hh[p], ll[p]);
#pragma unroll
    for (int p = 0; p < 8; p++) {
        *(uint32_t*)(out + base + 2 * p) =
            (uint32_t)hh[2 * p] | ((uint32_t)hh[2 * p + 1] << 16);
        *(uint32_t*)(out + oPlane + base + 2 * p) =
            (uint32_t)ll[2 * p] | ((uint32_t)ll[2 * p + 1] << 16);
    }
}

// ------- pwattn2: combined k|v (stride 4096), online softmax -> planar split ---
__global__ __launch_bounds__(128) void pwattn2_kernel(
    const float* __restrict__ q, const float* __restrict__ kv2,
    uint16_t* __restrict__ out)
{
    int n = blockIdx.x * 4 + (threadIdx.x >> 5);
    int lane = threadIdx.x & 31;
    const float* kp = kv2 + (size_t)n * 4096;
    const float* vp = kp + 2048;
    float qr[16];
    const float* qp = q + (size_t)n * 512 + lane * 16;
#pragma unroll
    for (int p = 0; p < 16; p++) qr[p] = qp[p];
    float m = -INFINITY, sum = 0.f;
    float V[16];
#pragma unroll
    for (int p = 0; p < 16; p++) V[p] = 0.f;
    for (int s = 0; s < 128; s++) {
        float d = 0.f;
#pragma unroll
        for (int p = 0; p < 16; p++) d = fmaf(qr[p], kp[s * 16 + p], d);
        if (d > m) {
            float f = expf((m - d) * 0.25f);
            sum *= f;
#pragma unroll
            for (int p = 0; p < 16; p++) V[p] *= f;
            m = d;
        }
        float w = expf((d - m) * 0.25f);
        sum += w;
#pragma unroll
        for (int p = 0; p < 16; p++) V[p] = fmaf(w, vp[s * 16 + p], V[p]);
    }
    float inv = 1.f / sum;
    const size_t oPlane = (size_t)NROWS * 512;
    size_t base = (size_t)n * 512 + lane * 16;
    uint16_t hh[16], ll[16];
#pragma unroll
    for (int p = 0; p < 16; p++) fsplit2(V[p] * inv, hh[p], ll[p]);
#pragma unroll
    for (int p = 0; p < 8; p++) {
        *(uint32_t*)(out + base + 2 * p) =
            (uint32_t)hh[2 * p] | ((uint32_t)hh[2 * p + 1] << 16);
        *(uint32_t*)(out + oPlane + base + 2 * p) =
            (uint32_t)ll[2 * p] | ((uint32_t)ll[2 * p + 1] << 16);
    }
}

// ---------------- layernorm over 2048 -> planar split ---------------------------
__global__ __launch_bounds__(256) void ln_kernel(
    const float* __restrict__ in, const float* __restrict__ g,
    const float* __restrict__ b, uint16_t* __restrict__ out)
{
    int n = blockIdx.x;
    int tid = threadIdx.x;
    __shared__ float red[256];
    const float* x = in + (size_t)n * 2048;
    float s = 0.f;
    for (int i = tid; i < 2048; i += 256) s += x[i];
    red[tid] = s; __syncthreads();
    for (int o = 128; o > 0; o >>= 1) { if (tid < o) red[tid] += red[tid + o]; __syncthreads(); }
    float mean = red[0] * (1.f / 2048.f);
    __syncthreads();
    float vs = 0.f;
    for (int i = tid; i < 2048; i += 256) { float d = x[i] - mean; vs += d * d; }
    red[tid] = vs; __syncthreads();
    for (int o = 128; o > 0; o >>= 1) { if (tid < o) red[tid] += red[tid + o]; __syncthreads(); }
    float var = red[0] * (1.f / 2048.f);
    float inv = rsqrtf(var + 1e-5f);
    const size_t oPlane = (size_t)NROWS * 2048;
    for (int i = tid; i < 2048; i += 256) {
        uint16_t hh, ll;
        fsplit2((x[i] - mean) * inv * g[i] + b[i], hh, ll);
        size_t o = (size_t)n * 2048 + i;
        out[o] = hh;
        out[oPlane + o] = ll;
    }
}

// ---------------- launch --------------------------------------------------------
extern "C" void kernel_launch(void* const* d_in, const int* in_sizes, int n_in,
                              void* d_out, int out_size)
{
    (void)in_sizes; (void)n_in; (void)out_size;
    const float* x     = (const float*)d_in[0];
    const float* aqw   = (const float*)d_in[1];
    const float* aqb   = (const float*)d_in[2];
    const float* akw   = (const float*)d_in[3];
    const float* akb   = (const float*)d_in[4];
    const float* avw   = (const float*)d_in[5];
    const float* avb   = (const float*)d_in[6];
    const float* aow   = (const float*)d_in[7];
    const float* aob   = (const float*)d_in[8];
    const float* encw  = (const float*)d_in[9];
    const float* encb  = (const float*)d_in[10];
    const float* f1qw  = (const float*)d_in[11];
    const float* f1qb  = (const float*)d_in[12];
    const float* f1kw  = (const float*)d_in[13];
    const float* f1kb  = (const float*)d_in[14];
    const float* f1vw  = (const float*)d_in[15];
    const float* f1vb  = (const float*)d_in[16];
    const float* f1ow  = (const float*)d_in[17];
    const float* f1ob  = (const float*)d_in[18];
    const float* f2qw  = (const float*)d_in[19];
    const float* f2qb  = (const float*)d_in[20];
    const float* f2kw  = (const float*)d_in[21];
    const float* f2kb  = (const float*)d_in[22];
    const float* f2vw  = (const float*)d_in[23];
    const float* f2vb  = (const float*)d_in[24];
    const float* f2ow  = (const float*)d_in[25];
    const float* f2ob  = (const float*)d_in[26];
    const float* lng   = (const float*)d_in[27];
    const float* lnb   = (const float*)d_in[28];

    float* out  = (float*)d_out;
    float* Aout = out + (size_t)NROWS * 512;

    float* b512; float* b2048; uint32_t* sps; uint32_t* spb; uint32_t* wt;
    short* avidx; float* avwt; int* avcnt;
    cudaGetSymbolAddress((void**)&b512,  g_buf512);
    cudaGetSymbolAddress((void**)&b2048, g_buf2048);
    cudaGetSymbolAddress((void**)&sps,   g_sp_small);
    cudaGetSymbolAddress((void**)&spb,   g_sp_big);
    cudaGetSymbolAddress((void**)&wt,    g_wt);
    cudaGetSymbolAddress((void**)&avidx, g_avidx);
    cudaGetSymbolAddress((void**)&avwt,  g_avwt);
    cudaGetSymbolAddress((void**)&avcnt, g_avcnt);
    const size_t S = (size_t)NROWS * 512;
    const size_t T = (size_t)NROWS * 2048;
    float* qb   = b512;
    float* kb   = b512 + S;
    float* vb   = b512 + 2 * S;
    float* kv1  = b512 + 3 * S;
    float* qu2  = b512 + 5 * S;
    float* q1   = b2048;
    float* t1   = b2048 + T;
    float* kv2  = b2048 + 2 * T;
    uint16_t* sps16 = (uint16_t*)sps;
    uint16_t* spb16 = (uint16_t*)spb;
    uint16_t* wt16  = (uint16_t*)wt;
    uint16_t* x_sp   = sps16;            // planar: hi S then lo S
    uint16_t* att_sp = sps16 + 2 * S;
    uint16_t* zb_sp  = sps16 + 4 * S;
    uint16_t* y2_sp  = sps16 + 6 * S;
    uint16_t* Vf1_sp = spb16;
    uint16_t* u_sp   = spb16 + 2 * T;

    cudaFuncSetAttribute(mm_gemm_kernel<0,1>, cudaFuncAttributeMaxDynamicSharedMemorySize, MM_SMEM);
    cudaFuncSetAttribute(mm_gemm_kernel<1,0>, cudaFuncAttributeMaxDynamicSharedMemorySize, MM_SMEM);
    cudaFuncSetAttribute(mm_gemm_kernel<2,1>, cudaFuncAttributeMaxDynamicSharedMemorySize, MM_SMEM);
    cudaFuncSetAttribute(mm_gemm_kernel<3,0>, cudaFuncAttributeMaxDynamicSharedMemorySize, MM_SMEM);
    cudaFuncSetAttribute(mm_gemm_kernel<4,0>, cudaFuncAttributeMaxDynamicSharedMemorySize, MM_SMEM);
    cudaFuncSetAttribute(mm_gemm_kernel<5,0>, cudaFuncAttributeMaxDynamicSharedMemorySize, MM_SMEM);
    cudaFuncSetAttribute(scores_topk_kernel, cudaFuncAttributeMaxDynamicSharedMemorySize, ST_SMEM);

    static cudaStream_t s2 = nullptr;
    static cudaEvent_t evF = nullptr, evJ = nullptr, evF1 = nullptr, evJ1 = nullptr,
                       evF2 = nullptr, evJ2 = nullptr;
    if (!s2) {
        cudaStreamCreateWithFlags(&s2, cudaStreamNonBlocking);
        cudaEventCreateWithFlags(&evF,  cudaEventDisableTiming);
        cudaEventCreateWithFlags(&evJ,  cudaEventDisableTiming);
        cudaEventCreateWithFlags(&evF1, cudaEventDisableTiming);
        cudaEventCreateWithFlags(&evJ1, cudaEventDisableTiming);
        cudaEventCreateWithFlags(&evF2, cudaEventDisableTiming);
        cudaEventCreateWithFlags(&evJ2, cudaEventDisableTiming);
    }

    dim3 blk(256);
    dim3 tb(32, 8);
    dim3 tg512(8, (NROWS + 127) / 128);
    dim3 tg1024(16, (NROWS + 127) / 128);
    dim3 tg2048(32, (NROWS + 127) / 128);
    dim3 tg4096(64, (NROWS + 127) / 128);
    dim3 kg(8, (NROWS + 63) / 64, 2);

    // ===== fork 0: A-path on s2 ∥ transpose/convert/av on main =================
    cudaEventRecord(evF, 0);
    cudaStreamWaitEvent(s2, evF, 0);

    kgemm_qk_kernel<<<kg, blk, 0, s2>>>(x, aqw, aqb, qb, akw, akb, kb, NROWS, 512, 512);
    scores_topk_kernel<<<dim3(11, 512), blk, ST_SMEM, s2>>>(qb, kb, Aout, avidx, avwt, avcnt);
    cudaEventRecord(evJ, s2);

    {
        TransArgs ta;
        const float* srcs[11] = {avw, aow, encw, f1qw, f1kw, f1vw, f1ow, f2qw, f2kw, f2vw, f2ow};
        uint32_t offs[11] = {OFF_AV, OFF_AO, OFF_ENC, OFF_F1Q, OFF_F1K, OFF_F1V,
                             OFF_F1O, OFF_F2Q, OFF_F2K, OFF_F2V, OFF_F2O};
        int Ks[11] = {512, 512, 512, 512, 512, 512, 2048, 2048, 2048, 2048, 512};
        int Ns[11] = {512, 512, 512, 2048, 512, 512, 2048, 512, 2048, 2048, 512};
        int acc = 0;
        for (int j = 0; j < 11; j++) {
            ta.job[j].src = srcs[j];
            ta.job[j].dstoff = offs[j];
            ta.job[j].K = Ks[j];
            ta.job[j].N = Ns[j];
            ta.job[j].tstart = acc;
            acc += (Ns[j] >> 5) * (Ks[j] >> 5);
        }
        transpose_split_all<<<acc, tb>>>(ta);
    }
    convert_kernel<<<4096, 256>>>(x, x_sp, (int)S);
    mm_gemm_kernel<1,0><<<tg512, blk, MM_SMEM>>>(x_sp, wt16 + 2 * OFF_AV, avb, nullptr, vb, NROWS, 512, 512);

    cudaStreamWaitEvent(0, evJ, 0);   // join 0
    // ===========================================================================

    av_sparse_kernel<<<NROWS, blk>>>(avidx, avwt, avcnt, vb, att_sp);
    mm_gemm_kernel<2,1><<<tg512, blk, MM_SMEM>>>(att_sp, wt16 + 2 * OFF_AO, aob, x, zb_sp, NROWS, 512, 512);
    mm_gemm_kernel<0,1><<<tg512, blk, MM_SMEM>>>(zb_sp, wt16 + 2 * OFF_ENC, encb, nullptr, y2_sp, NROWS, 512, 512);

    // ---- ff1: f1q (main) ∥ f1kv (s2) ----
    cudaEventRecord(evF1, 0);
    cudaStreamWaitEvent(s2, evF1, 0);
    mm_gemm_kernel<5,0><<<tg1024, blk, MM_SMEM, s2>>>(y2_sp, wt16 + 2 * OFF_F1K, f1kb, f1vb, kv1, NROWS, 1024, 512);
    cudaEventRecord(evJ1, s2);
    mm_gemm_kernel<1,0><<<tg2048, blk, MM_SMEM>>>(y2_sp, wt16 + 2 * OFF_F1Q, f1qb, nullptr, q1, NROWS, 2048, 512);
    cudaStreamWaitEvent(0, evJ1, 0);

    pwattn1_kernel<<<NROWS, 128>>>(q1, kv1, Vf1_sp);
    mm_gemm_kernel<3,0><<<tg2048, blk, MM_SMEM>>>(Vf1_sp, wt16 + 2 * OFF_F1O, f1ob, q1, t1, NROWS, 2048, 2048);
    ln_kernel<<<NROWS, blk>>>(t1, lng, lnb, u_sp);

    // ---- ff2: f2q (s2) ∥ f2kv (main) ----
    cudaEventRecord(evF2, 0);
    cudaStreamWaitEvent(s2, evF2, 0);
    mm_gemm_kernel<1,0><<<tg512, blk, MM_SMEM, s2>>>(u_sp, wt16 + 2 * OFF_F2Q, f2qb, nullptr, qu2, NROWS, 512, 2048);
    cudaEventRecord(evJ2, s2);
    mm_gemm_kernel<5,0><<<tg4096, blk, MM_SMEM>>>(u_sp, wt16 + 2 * OFF_F2K, f2kb, f2vb, kv2, NROWS, 4096, 2048);
    cudaStreamWaitEvent(0, evJ2, 0);

    pwattn2_kernel<<<NROWS / 4, 128>>>(qu2, kv2, x_sp);   // att2 -> reuse x_sp
    mm_gemm_kernel<4,0><<<tg512, blk, MM_SMEM>>>(x_sp, wt16 + 2 * OFF_F2O, f2ob, qu2, out, NROWS, 512, 512);
}

// round 17
// speedup vs baseline: 1.2813x; 1.1566x over previous
#include <cuda_runtime.h>
#include <cuda_fp16.h>
#include <math.h>
#include <stdint.h>

#define NROWS 20544     // B*L = 64*321
#define LL 321
#define DD 512
#define HH 8
#define EE 64
#define NTOPK 10

// ---------------- scratch (allocation-free: __device__ globals) ----------------
__device__ float    g_buf512[6ULL * NROWS * 512];
__device__ float    g_buf2048[4ULL * NROWS * 2048];
__device__ uint32_t g_sp_small[4ULL * NROWS * 512];  // 4 planar split buffers (512-wide)
__device__ uint32_t g_sp_big[2ULL * NROWS * 2048];   // 2 planar split buffers (2048-wide)
__device__ uint32_t g_wt[16252928];                  // planar split transposed weights
__device__ short    g_avidx[164352 * 24];
__device__ float    g_avwt[164352 * 24];
__device__ int      g_avcnt[164352];

#define OFF_AV   0u
#define OFF_AO   262144u
#define OFF_ENC  524288u
#define OFF_F1Q  786432u
#define OFF_F1K  1835008u
#define OFF_F1V  2097152u
#define OFF_F1O  2359296u
#define OFF_F2Q  6553600u
#define OFF_F2K  7602176u
#define OFF_F2V  11796480u
#define OFF_F2O  15990784u

// ---------------- fp16 split helpers (planar) -----------------------------------
__device__ __forceinline__ void fsplit2(float x, uint16_t& h, uint16_t& l) {
    __half hb = __float2half_rn(x);
    float hf = __half2float(hb);
    __half lb = __float2half_rn(x - hf);
    h = __half_as_ushort(hb);
    l = __half_as_ushort(lb);
}

// ------------- blocked compensation: Kahan-merge a block partial ---------------
__device__ __forceinline__ void kadd(float p, float& s, float& c) {
    float y = __fsub_rn(p, c);
    float t = __fadd_rn(s, y);
    c = __fsub_rn(__fsub_rn(t, s), y);
    s = t;
}
__device__ __forceinline__ float kfin(float s, float c) { return __fsub_rn(s, c); }

// ==================== batched weight transpose + planar split ===================
struct TransJob { const float* src; uint32_t dstoff; int K; int N; int tstart; };
struct TransArgs { TransJob job[11]; };

__global__ void transpose_split_all(TransArgs a)
{
    __shared__ float t[32][33];
    int tile = blockIdx.x;
    int ji = 0;
#pragma unroll
    for (int j = 1; j < 11; j++)
        if (tile >= a.job[j].tstart) ji = j;
    const TransJob& J = a.job[ji];
    int local = tile - J.tstart;
    int ntx = J.N >> 5;
    int bx = (local % ntx) * 32, by = (local / ntx) * 32;
    int txi = threadIdx.x, tyi = threadIdx.y;
    const float* src = J.src;
    uint16_t* dst = (uint16_t*)g_wt + 2ULL * J.dstoff;
    size_t plane = (size_t)J.N * J.K;
#pragma unroll
    for (int j = 0; j < 32; j += 8)
        t[tyi + j][txi] = src[(size_t)(by + tyi + j) * J.N + bx + txi];
    __syncthreads();
#pragma unroll
    for (int j = 0; j < 32; j += 8) {
        uint16_t h, l;
        fsplit2(t[txi][tyi + j], h, l);
        size_t o = (size_t)(bx + tyi + j) * J.K + by + txi;
        dst[o] = h;
        dst[plane + o] = l;   // lo plane kept for layout compat (unread by GEMM)
    }
}

__global__ void convert_kernel(const float* __restrict__ in, uint16_t* __restrict__ outp, int n)
{
    for (int i = blockIdx.x * 256 + threadIdx.x; i < n; i += gridDim.x * 256) {
        uint16_t h, l;
        fsplit2(in[i], h, l);
        outp[i] = h;
        outp[(size_t)n + i] = l;
    }
}

// ==== fp16x2 mma.sync GEMM: A 2-plane (exact), B 1-plane; 128x64, 2 CTA/SM =====
// smem stage (bytes): A_hi 10240, A_lo 10240, B_hi 5120 = 25600; x2 stages
#define MM_STAGE_B 25600
#define MM_SMEM    (2 * MM_STAGE_B)

__device__ __forceinline__ void mm_load_stage(
    const uint16_t* __restrict__ A, size_t aPlane,
    const uint16_t* __restrict__ B,
    int bm, int bn, int M, int K, int k0, uint32_t sb, int tid)
{
#pragma unroll
    for (int j = 0; j < 5; j++) {
        int idx = tid + j * 256;
        if (idx < 1024) {                        // A: 2 planes x 128 rows x 4 chunks
            int plane = idx >> 9;
            int i2 = idx & 511;
            int r = i2 >> 2, c = i2 & 3;
            uint32_t dst = sb + plane * 10240 + r * 80 + c * 16;
            int grow = bm + r;
            const uint16_t* src = A + (size_t)plane * aPlane
                                + (size_t)(grow < M ? grow : 0) * K + k0 + c * 8;
            int sz = (grow < M) ? 16 : 0;
            asm volatile("cp.async.ca.shared.global [%0], [%1], 16, %2;"
                         :: "r"(dst), "l"(src), "r"(sz));
        } else {                                 // B: 1 plane x 64 rows x 4 chunks
            int i2 = idx - 1024;
            int r = i2 >> 2, c = i2 & 3;
            uint32_t dst = sb + 20480 + r * 80 + c * 16;
            const uint16_t* src = B + (size_t)(bn + r) * K + k0 + c * 8;
            asm volatile("cp.async.ca.shared.global [%0], [%1], 16;"
                         :: "r"(dst), "l"(src));
        }
    }
    asm volatile("cp.async.commit_group;" ::: "memory");
}

#define LDMX4(r0, r1, r2, r3, addr) \
    asm volatile("ldmatrix.sync.aligned.m8n8.x4.shared.b16 {%0,%1,%2,%3}, [%4];" \
                 : "=r"(r0), "=r"(r1), "=r"(r2), "=r"(r3) : "r"(addr))

#define MMA_F16(acc, a0, a1, a2, a3, b0, b1) \
    asm volatile( \
        "mma.sync.aligned.m16n8k16.row.col.f32.f16.f16.f32 " \
        "{%0,%1,%2,%3}, {%4,%5,%6,%7}, {%8,%9}, {%0,%1,%2,%3};" \
        : "+f"((acc)[0]), "+f"((acc)[1]), "+f"((acc)[2]), "+f"((acc)[3]) \
        : "r"(a0), "r"(a1), "r"(a2), "r"(a3), "r"(b0), "r"(b1))

// EP: 0=bias, 1=bias+relu, 2=bias+res+leaky, 3=bias+res+elu, 4=bias+res,
//     5=dual-bias (bias=lower half, res=upper-half bias), relu on upper half
// OM: 0 -> f32 out, 1 -> planar split u16 out
template<int EP, int OM>
__global__ __launch_bounds__(256, 2)
void mm_gemm_kernel(const uint16_t* __restrict__ A, const uint16_t* __restrict__ Bt,
                    const float* __restrict__ bias, const float* __restrict__ res,
                    void* __restrict__ Cv, int M, int N, int K)
{
    extern __shared__ uint32_t smraw[];
    uint32_t s0;
    asm("{ .reg .u64 t; cvta.to.shared.u64 t, %1; cvt.u32.u64 %0, t; }" : "=r"(s0) : "l"(smraw));
    const int tid = threadIdx.x;
    const int wid = tid >> 5, lane = tid & 31;
    const int wm = wid >> 1, wn = wid & 1;
    const int g = lane >> 2, t = lane & 3;
    const int bm = blockIdx.y * 128, bn = blockIdx.x * 64;

    const int halfN = N >> 1;
    const uint16_t* Bu = Bt;
    int bnl = bn;
    if (EP == 5 && bn >= halfN) { Bu += (size_t)2 * halfN * K; bnl = bn - halfN; }
    const size_t aPlane = (size_t)M * K;

    float acc[2][4][4];
#pragma unroll
    for (int i = 0; i < 2; i++)
#pragma unroll
        for (int j = 0; j < 4; j++)
#pragma unroll
            for (int q = 0; q < 4; q++) acc[i][j][q] = 0.f;

    const int nc = K >> 5;
    mm_load_stage(A, aPlane, Bu, bm, bnl, M, K, 0, s0, tid);

    const uint32_t laneA = (uint32_t)(((lane & 7) + (lane & 8)) * 80 + ((lane >> 4) & 1) * 16);
    const uint32_t laneB = (uint32_t)(((lane & 7) + ((lane >> 1) & 8)) * 80 + ((lane >> 3) & 1) * 16);
    const uint32_t aRow = (uint32_t)(wm * 32) * 80;
    const uint32_t bRow = (uint32_t)(wn * 32) * 80;

    for (int c = 0; c < nc; c++) {
        if (c + 1 < nc)
            mm_load_stage(A, aPlane, Bu, bm, bnl, M, K, (c + 1) * 32,
                          s0 + ((c + 1) & 1) * MM_STAGE_B, tid);
        if (c + 1 < nc) asm volatile("cp.async.wait_group 1;" ::: "memory");
        else            asm volatile("cp.async.wait_group 0;" ::: "memory");
        __syncthreads();

        uint32_t sb = s0 + (c & 1) * MM_STAGE_B;
#pragma unroll
        for (int ks = 0; ks < 2; ks++) {
            uint32_t ka = ks * 32;
            uint32_t ah[2][4], al[2][4], bh[4][2];
            LDMX4(ah[0][0], ah[0][1], ah[0][2], ah[0][3], sb + aRow + laneA + ka);
            LDMX4(ah[1][0], ah[1][1], ah[1][2], ah[1][3], sb + aRow + 1280 + laneA + ka);
            LDMX4(al[0][0], al[0][1], al[0][2], al[0][3], sb + 10240 + aRow + laneA + ka);
            LDMX4(al[1][0], al[1][1], al[1][2], al[1][3], sb + 10240 + aRow + 1280 + laneA + ka);
            LDMX4(bh[0][0], bh[0][1], bh[1][0], bh[1][1], sb + 20480 + bRow + laneB + ka);
            LDMX4(bh[2][0], bh[2][1], bh[3][0], bh[3][1], sb + 20480 + bRow + 1280 + laneB + ka);
#pragma unroll
            for (int mt = 0; mt < 2; mt++)
#pragma unroll
                for (int nt = 0; nt < 4; nt++)
                    MMA_F16(acc[mt][nt], al[mt][0], al[mt][1], al[mt][2], al[mt][3],
                            bh[nt][0], bh[nt][1]);
#pragma unroll
            for (int mt = 0; mt < 2; mt++)
#pragma unroll
                for (int nt = 0; nt < 4; nt++)
                    MMA_F16(acc[mt][nt], ah[mt][0], ah[mt][1], ah[mt][2], ah[mt][3],
                            bh[nt][0], bh[nt][1]);
        }
        __syncthreads();
    }

    float* Cf = (float*)Cv;
    uint16_t* Cs = (uint16_t*)Cv;
    const size_t oPlane = (size_t)M * N;
    const bool upper = (EP == 5) && (bn >= halfN);
    const float* bp = (EP == 5) ? (upper ? res - halfN : bias) : bias;
#pragma unroll
    for (int mt = 0; mt < 2; mt++) {
#pragma unroll
        for (int hf2 = 0; hf2 < 2; hf2++) {
            int row = bm + wm * 32 + mt * 16 + g + hf2 * 8;
            if (row >= M) continue;
#pragma unroll
            for (int nt = 0; nt < 4; nt++) {
                int col = bn + wn * 32 + nt * 8 + t * 2;
                float v0 = acc[mt][nt][hf2 * 2 + 0] + bp[col];
                float v1 = acc[mt][nt][hf2 * 2 + 1] + bp[col + 1];
                if (EP >= 2 && EP <= 4) {
                    v0 += res[(size_t)row * N + col];
                    v1 += res[(size_t)row * N + col + 1];
                }
                if (EP == 1 || (EP == 5 && upper)) { v0 = fmaxf(v0, 0.f); v1 = fmaxf(v1, 0.f); }
                if (EP == 2) { v0 = (v0 > 0.f) ? v0 : 0.5f * v0; v1 = (v1 > 0.f) ? v1 : 0.5f * v1; }
                if (EP == 3) { v0 = (v0 > 0.f) ? v0 : expm1f(v0); v1 = (v1 > 0.f) ? v1 : expm1f(v1); }
                if (OM == 0) {
                    *(float2*)(Cf + (size_t)row * N + col) = make_float2(v0, v1);
                } else {
                    uint16_t h0, l0, h1, l1;
                    fsplit2(v0, h0, l0);
                    fsplit2(v1, h1, l1);
                    *(uint32_t*)(Cs + (size_t)row * N + col) =
                        (uint32_t)h0 | ((uint32_t)h1 << 16);
                    *(uint32_t*)(Cs + oPlane + (size_t)row * N + col) =
                        (uint32_t)l0 | ((uint32_t)l1 << 16);
                }
            }
        }
    }
}

// ---------- blocked-compensated fp32 GEMM (block 16), q & k fused (grid.z) -----
__global__ __launch_bounds__(256) void kgemm_qk_kernel(
    const float* __restrict__ A,
    const float* __restrict__ Bq, const float* __restrict__ bq, float* __restrict__ Cq,
    const float* __restrict__ Bk, const float* __restrict__ bk, float* __restrict__ Ck,
    int M, int N, int K)
{
    const float* B  = blockIdx.z ? Bk : Bq;
    const float* bb = blockIdx.z ? bk : bq;
    float* C        = blockIdx.z ? Ck : Cq;
    const int relu  = blockIdx.z ? 0 : 1;

    __shared__ float As[16][68];
    __shared__ float Bs[16][68];
    const int tid = threadIdx.x;
    const int bm = blockIdx.y * 64;
    const int bn = blockIdx.x * 64;
    const int ty = tid >> 4, tx = tid & 15;

    float s[4][4], cc[4][4];
#pragma unroll
    for (int i = 0; i < 4; i++)
#pragma unroll
        for (int j = 0; j < 4; j++) { s[i][j] = 0.f; cc[i][j] = 0.f; }

    const int ar = tid >> 2;
    const int ac = (tid & 3) << 2;
    const int br = tid >> 4;
    const int bc = (tid & 15) << 2;

    for (int k0 = 0; k0 < K; k0 += 16) {
        {
            int grow = bm + ar;
            float4 v = make_float4(0.f, 0.f, 0.f, 0.f);
            if (grow < M) v = *(const float4*)(A + (size_t)grow * K + k0 + ac);
            As[ac + 0][ar] = v.x; As[ac + 1][ar] = v.y;
            As[ac + 2][ar] = v.z; As[ac + 3][ar] = v.w;
        }
        *(float4*)&Bs[br][bc] = *(const float4*)(B + (size_t)(k0 + br) * N + bn + bc);
        __syncthreads();
        {
            float p[4][4];
#pragma unroll
            for (int i = 0; i < 4; i++)
#pragma unroll
                for (int j = 0; j < 4; j++) p[i][j] = 0.f;
#pragma unroll
            for (int kk = 0; kk < 16; kk++) {
                float4 av = *(const float4*)&As[kk][ty * 4];
                float4 bv = *(const float4*)&Bs[kk][tx * 4];
                const float* a = (const float*)&av;
                const float* b = (const float*)&bv;
#pragma unroll
                for (int i = 0; i < 4; i++)
#pragma unroll
                    for (int j = 0; j < 4; j++)
                        p[i][j] = __fmaf_rn(a[i], b[j], p[i][j]);
            }
#pragma unroll
            for (int i = 0; i < 4; i++)
#pragma unroll
                for (int j = 0; j < 4; j++)
                    kadd(p[i][j], s[i][j], cc[i][j]);
        }
        __syncthreads();
    }

#pragma unroll
    for (int i = 0; i < 4; i++) {
        int row = bm + ty * 4 + i;
        if (row < M) {
            float4 o;
            float* ov = (float*)&o;
#pragma unroll
            for (int j = 0; j < 4; j++) {
                float v = __fadd_rn(kfin(s[i][j], cc[i][j]), bb[bn + tx * 4 + j]);
                if (relu) v = fmaxf(v, 0.f);
                ov[j] = v;
            }
            *(float4*)(C + (size_t)row * N + bn + tx * 4) = o;
        }
    }
}

// ========== FUSED scores + top-k + softmax + compact-list emission =============
#define ST_SMEM ((32 * 72 * 2 + 32 * 360) * 4)

__global__ __launch_bounds__(256) void scores_topk_kernel(
    const float* __restrict__ q, const float* __restrict__ k, float* __restrict__ out,
    short* __restrict__ avidx, float* __restrict__ avwt, int* __restrict__ avcnt)
{
    extern __shared__ float shb[];
    float (*Qs)[72]  = (float(*)[72])shb;
    float (*Ks)[72]  = (float(*)[72])(shb + 32 * 72);
    float (*SC)[360] = (float(*)[360])(shb + 2 * 32 * 72);

    int bh = blockIdx.y;
    int b = bh >> 3, h = bh & 7;
    int l0 = blockIdx.x * 32;
    int tid = threadIdx.x;
    int r = tid >> 3;
    int c = (tid & 7) * 8;
    {
        int l = l0 + r;
        if (l < LL) {
            const float* src = q + ((size_t)(b * LL + l)) * DD + h * EE + c;
            *(float4*)&Qs[r][c]     = *(const float4*)src;
            *(float4*)&Qs[r][c + 4] = *(const float4*)(src + 4);
        } else {
#pragma unroll
            for (int t = 0; t < 8; t++) Qs[r][c + t] = 0.f;
        }
    }
    int ty = tid >> 4, tx = tid & 15;

    for (int s0 = 0; s0 < 352; s0 += 32) {
        __syncthreads();
        {
            int sdx = s0 + r;
            if (sdx < LL) {
                const float* src = k + ((size_t)(b * LL + sdx)) * DD + h * EE + c;
                *(float4*)&Ks[r][c]     = *(const float4*)src;
                *(float4*)&Ks[r][c + 4] = *(const float4*)(src + 4);
            } else {
#pragma unroll
                for (int t = 0; t < 8; t++) Ks[r][c + t] = 0.f;
            }
        }
        __syncthreads();
        float s00 = 0.f, s01 = 0.f, s10 = 0.f, s11 = 0.f;
        float c00 = 0.f, c01 = 0.f, c10 = 0.f, c11 = 0.f;
#pragma unroll
        for (int blkk = 0; blkk < 4; blkk++) {
            float p00 = 0.f, p01 = 0.f, p10 = 0.f, p11 = 0.f;
#pragma unroll
            for (int kk = blkk * 16; kk < blkk * 16 + 16; kk++) {
                float a0 = Qs[ty * 2 + 0][kk], a1 = Qs[ty * 2 + 1][kk];
                float b0 = Ks[tx * 2 + 0][kk], b1 = Ks[tx * 2 + 1][kk];
                p00 = __fmaf_rn(a0, b0, p00);
                p01 = __fmaf_rn(a0, b1, p01);
                p10 = __fmaf_rn(a1, b0, p10);
                p11 = __fmaf_rn(a1, b1, p11);
            }
            kadd(p00, s00, c00);
            kadd(p01, s01, c01);
            kadd(p10, s10, c10);
            kadd(p11, s11, c11);
        }
        SC[ty * 2 + 0][s0 + tx * 2 + 0] = kfin(s00, c00);
        SC[ty * 2 + 0][s0 + tx * 2 + 1] = kfin(s01, c01);
        SC[ty * 2 + 1][s0 + tx * 2 + 0] = kfin(s10, c10);
        SC[ty * 2 + 1][s0 + tx * 2 + 1] = kfin(s11, c11);
    }
    __syncthreads();

    int wid = tid >> 5, lane = tid & 31;
    for (int rr = 0; rr < 4; rr++) {
        int lrow = wid * 4 + rr;
        int l = l0 + lrow;
        if (l >= LL) break;
        float* s = SC[lrow];
        float rc[11];
#pragma unroll
        for (int j = 0; j < 11; j++) {
            int idx = lane + j * 32;
            float v = (idx < LL) ? s[idx] : -INFINITY;
            rc[j] = v;
            s[idx] = v;
        }
        __syncwarp();

        float kth = 0.f, mmax = 0.f;
        for (int it = 0; it < NTOPK; it++) {
            float lm = -INFINITY;
#pragma unroll
            for (int j = 0; j < 11; j++) lm = fmaxf(lm, s[lane + j * 32]);
            float gm = lm;
#pragma unroll
            for (int o = 16; o > 0; o >>= 1) gm = fmaxf(gm, __shfl_xor_sync(0xffffffffu, gm, o));
            if (it == 0) mmax = gm;
            kth = gm;
            int li = 0x7fffffff;
#pragma unroll
            for (int j = 10; j >= 0; j--) {
                int idx = lane + j * 32;
                if (s[idx] == gm) li = idx;
            }
            int gi = li;
#pragma unroll
            for (int o = 16; o > 0; o >>= 1) gi = min(gi, __shfl_xor_sync(0xffffffffu, gi, o));
            if (li == gi) s[li] = -INFINITY;
            __syncwarp();
        }

        const float scale = 0.125f;
        float e[11];
        float sum = 0.f;
#pragma unroll
        for (int j = 0; j < 11; j++) {
            int idx = lane + j * 32;
            float v = rc[j];
            float t = (idx < LL && v >= kth) ? expf((v - mmax) * scale) : 0.f;
            e[j] = t;
            sum += t;
        }
#pragma unroll
        for (int o = 16; o > 0; o >>= 1) sum += __shfl_xor_sync(0xffffffffu, sum, o);
        float inv = 1.f / sum;

        size_t row = (size_t)bh * LL + l;
        float* rp = out + row * LL;
        int cnt = 0;
#pragma unroll
        for (int j = 0; j < 11; j++) {
            int idx = lane + j * 32;
            float w = (idx < LL) ? e[j] * inv : 0.f;
            if (idx < LL) rp[idx] = w;
            unsigned mk = __ballot_sync(0xffffffffu, w > 0.f);
            if (w > 0.f) {
                int pos = cnt + __popc(mk & ((1u << lane) - 1u));
                if (pos < 24) { avidx[row * 24 + pos] = (short)idx; avwt[row * 24 + pos] = w; }
            }
            cnt += __popc(mk);
        }
        if (lane == 0) avcnt[row] = (cnt < 24) ? cnt : 24;
        __syncwarp();
    }
}

// ---------------- sparse A @ V from compact lists -> planar split out -----------
__global__ __launch_bounds__(256) void av_sparse_kernel(
    const short* __restrict__ avidx, const float* __restrict__ avwt,
    const int* __restrict__ avcnt,
    const float* __restrict__ v, uint16_t* __restrict__ out)
{
    __shared__ short  sidx[8][24];
    __shared__ float  swt[8][24];
    __shared__ int    scnt[8];
    int blk = blockIdx.x;
    int b = blk / LL, l = blk % LL;
    int tid = threadIdx.x;
    int wid = tid >> 5, lane = tid & 31;
    const size_t oPlane = (size_t)NROWS * 512;

    {
        int h = wid;
        size_t row = (size_t)(b * 8 + h) * LL + l;
        if (lane < 24) {
            sidx[h][lane] = avidx[row * 24 + lane];
            swt[h][lane]  = avwt[row * 24 + lane];
        }
        if (lane == 0) scnt[h] = avcnt[row];
    }
    __syncthreads();

    const float* vbase = v + (size_t)b * LL * DD;
#pragma unroll
    for (int e0 = 0; e0 < 2; e0++) {
        int e = tid + e0 * 256;
        int h = e >> 6, c2 = e & 63;
        int n2 = scnt[h];
        const float* vp = vbase + h * EE + c2;
        float acc = 0.f;
        for (int j = 0; j < n2; j++)
            acc = __fmaf_rn(swt[h][j], vp[(size_t)sidx[h][j] * DD], acc);
        uint16_t hh, ll;
        fsplit2(acc, hh, ll);
        size_t o = ((size_t)(b * LL + l)) * DD + e;
        out[o] = hh;
        out[oPlane + o] = ll;
    }
}

// ---------------- pwattn1 (combined k|v, stride 1024) -> planar split ----------
__global__ __launch_bounds__(128) void pwattn1_kernel(
    const float* __restrict__ q, const float* __restrict__ kv,
    uint16_t* __restrict__ out)
{
    int n = blockIdx.x;
    int l = threadIdx.x;
    __shared__ float sk[512];
    __shared__ float sv[512];
    int t4 = l * 4;
    const float* kvp = kv + (size_t)n * 1024;
    *(float4*)&sk[t4] = *(const float4*)(kvp + t4);
    *(float4*)&sv[t4] = *(const float4*)(kvp + 512 + t4);
    __syncthreads();
    float qr[16];
    const float* qp = q + (size_t)n * 2048 + l * 16;
#pragma unroll
    for (int p = 0; p < 16; p++) qr[p] = qp[p];
    float sc[32];
    float m = -INFINITY;
#pragma unroll
    for (int s = 0; s < 32; s++) {
        float d = 0.f;
#pragma unroll
        for (int p = 0; p < 16; p++) d = fmaf(qr[p], sk[s * 16 + p], d);
        sc[s] = d;
        m = fmaxf(m, d);
    }
    float sum = 0.f;
    float V[16];
#pragma unroll
    for (int p = 0; p < 16; p++) V[p] = 0.f;
#pragma unroll
    for (int s = 0; s < 32; s++) {
        float w = expf((sc[s] - m) * 0.25f);
        sum += w;
#pragma unroll
        for (int p = 0; p < 16; p++) V[p] = fmaf(w, sv[s * 16 + p], V[p]);
    }
    float inv = 1.f / sum;
    const size_t oPlane = (size_t)NROWS * 2048;
    size_t base = (size_t)n * 2048 + l * 16;
    uint16_t hh[16], ll[16];
#pragma unroll
    for (int p = 0; p < 16; p++) fsplit2(V[p] * inv, hh[p], ll[p]);
#pragma unroll
    for (int p = 0; p < 8; p++) {
        *(uint32_t*)(out + base + 2 * p) =
            (uint32_t)hh[2 * p] | ((uint32_t)hh[2 * p + 1] << 16);
        *(uint32_t*)(out + oPlane + base + 2 * p) =
            (uint32_t)ll[2 * p] | ((uint32_t)ll[2 * p + 1] << 16);
    }
}

// ------- pwattn2: combined k|v (stride 4096), online softmax -> planar split ---
__global__ __launch_bounds__(128) void pwattn2_kernel(
    const float* __restrict__ q, const float* __restrict__ kv2,
    uint16_t* __restrict__ out)
{
    int n = blockIdx.x * 4 + (threadIdx.x >> 5);
    int lane = threadIdx.x & 31;
    const float* kp = kv2 + (size_t)n * 4096;
    const float* vp = kp + 2048;
    float qr[16];
    const float* qp = q + (size_t)n * 512 + lane * 16;
#pragma unroll
    for (int p = 0; p < 16; p++) qr[p] = qp[p];
    float m = -INFINITY, sum = 0.f;
    float V[16];
#pragma unroll
    for (int p = 0; p < 16; p++) V[p] = 0.f;
    for (int s = 0; s < 128; s++) {
        float d = 0.f;
#pragma unroll
        for (int p = 0; p < 16; p++) d = fmaf(qr[p], kp[s * 16 + p], d);
        if (d > m) {
            float f = expf((m - d) * 0.25f);
            sum *= f;
#pragma unroll
            for (int p = 0; p < 16; p++) V[p] *= f;
            m = d;
        }
        float w = expf((d - m) * 0.25f);
        sum += w;
#pragma unroll
        for (int p = 0; p < 16; p++) V[p] = fmaf(w, vp[s * 16 + p], V[p]);
    }
    float inv = 1.f / sum;
    const size_t oPlane = (size_t)NROWS * 512;
    size_t base = (size_t)n * 512 + lane * 16;
    uint16_t hh[16], ll[16];
#pragma unroll
    for (int p = 0; p < 16; p++) fsplit2(V[p] * inv, hh[p], ll[p]);
#pragma unroll
    for (int p = 0; p < 8; p++) {
        *(uint32_t*)(out + base + 2 * p) =
            (uint32_t)hh[2 * p] | ((uint32_t)hh[2 * p + 1] << 16);
        *(uint32_t*)(out + oPlane + base + 2 * p) =
            (uint32_t)ll[2 * p] | ((uint32_t)ll[2 * p + 1] << 16);
    }
}

// ---------------- layernorm over 2048 -> planar split ---------------------------
__global__ __launch_bounds__(256) void ln_kernel(
    const float* __restrict__ in, const float* __restrict__ g,
    const float* __restrict__ b, uint16_t* __restrict__ out)
{
    int n = blockIdx.x;
    int tid = threadIdx.x;
    __shared__ float red[256];
    const float* x = in + (size_t)n * 2048;
    float s = 0.f;
    for (int i = tid; i < 2048; i += 256) s += x[i];
    red[tid] = s; __syncthreads();
    for (int o = 128; o > 0; o >>= 1) { if (tid < o) red[tid] += red[tid + o]; __syncthreads(); }
    float mean = red[0] * (1.f / 2048.f);
    __syncthreads();
    float vs = 0.f;
    for (int i = tid; i < 2048; i += 256) { float d = x[i] - mean; vs += d * d; }
    red[tid] = vs; __syncthreads();
    for (int o = 128; o > 0; o >>= 1) { if (tid < o) red[tid] += red[tid + o]; __syncthreads(); }
    float var = red[0] * (1.f / 2048.f);
    float inv = rsqrtf(var + 1e-5f);
    const size_t oPlane = (size_t)NROWS * 2048;
    for (int i = tid; i < 2048; i += 256) {
        uint16_t hh, ll;
        fsplit2((x[i] - mean) * inv * g[i] + b[i], hh, ll);
        size_t o = (size_t)n * 2048 + i;
        out[o] = hh;
        out[oPlane + o] = ll;
    }
}

// ---------------- launch --------------------------------------------------------
extern "C" void kernel_launch(void* const* d_in, const int* in_sizes, int n_in,
                              void* d_out, int out_size)
{
    (void)in_sizes; (void)n_in; (void)out_size;
    const float* x     = (const float*)d_in[0];
    const float* aqw   = (const float*)d_in[1];
    const float* aqb   = (const float*)d_in[2];
    const float* akw   = (const float*)d_in[3];
    const float* akb   = (const float*)d_in[4];
    const float* avw   = (const float*)d_in[5];
    const float* avb   = (const float*)d_in[6];
    const float* aow   = (const float*)d_in[7];
    const float* aob   = (const float*)d_in[8];
    const float* encw  = (const float*)d_in[9];
    const float* encb  = (const float*)d_in[10];
    const float* f1qw  = (const float*)d_in[11];
    const float* f1qb  = (const float*)d_in[12];
    const float* f1kw  = (const float*)d_in[13];
    const float* f1kb  = (const float*)d_in[14];
    const float* f1vw  = (const float*)d_in[15];
    const float* f1vb  = (const float*)d_in[16];
    const float* f1ow  = (const float*)d_in[17];
    const float* f1ob  = (const float*)d_in[18];
    const float* f2qw  = (const float*)d_in[19];
    const float* f2qb  = (const float*)d_in[20];
    const float* f2kw  = (const float*)d_in[21];
    const float* f2kb  = (const float*)d_in[22];
    const float* f2vw  = (const float*)d_in[23];
    const float* f2vb  = (const float*)d_in[24];
    const float* f2ow  = (const float*)d_in[25];
    const float* f2ob  = (const float*)d_in[26];
    const float* lng   = (const float*)d_in[27];
    const float* lnb   = (const float*)d_in[28];

    float* out  = (float*)d_out;
    float* Aout = out + (size_t)NROWS * 512;

    float* b512; float* b2048; uint32_t* sps; uint32_t* spb; uint32_t* wt;
    short* avidx; float* avwt; int* avcnt;
    cudaGetSymbolAddress((void**)&b512,  g_buf512);
    cudaGetSymbolAddress((void**)&b2048, g_buf2048);
    cudaGetSymbolAddress((void**)&sps,   g_sp_small);
    cudaGetSymbolAddress((void**)&spb,   g_sp_big);
    cudaGetSymbolAddress((void**)&wt,    g_wt);
    cudaGetSymbolAddress((void**)&avidx, g_avidx);
    cudaGetSymbolAddress((void**)&avwt,  g_avwt);
    cudaGetSymbolAddress((void**)&avcnt, g_avcnt);
    const size_t S = (size_t)NROWS * 512;
    const size_t T = (size_t)NROWS * 2048;
    float* qb   = b512;
    float* kb   = b512 + S;
    float* vb   = b512 + 2 * S;
    float* kv1  = b512 + 3 * S;
    float* qu2  = b512 + 5 * S;
    float* q1   = b2048;
    float* t1   = b2048 + T;
    float* kv2  = b2048 + 2 * T;
    uint16_t* sps16 = (uint16_t*)sps;
    uint16_t* spb16 = (uint16_t*)spb;
    uint16_t* wt16  = (uint16_t*)wt;
    uint16_t* x_sp   = sps16;            // planar: hi S then lo S
    uint16_t* att_sp = sps16 + 2 * S;
    uint16_t* zb_sp  = sps16 + 4 * S;
    uint16_t* y2_sp  = sps16 + 6 * S;
    uint16_t* Vf1_sp = spb16;
    uint16_t* u_sp   = spb16 + 2 * T;

    cudaFuncSetAttribute(mm_gemm_kernel<0,1>, cudaFuncAttributeMaxDynamicSharedMemorySize, MM_SMEM);
    cudaFuncSetAttribute(mm_gemm_kernel<1,0>, cudaFuncAttributeMaxDynamicSharedMemorySize, MM_SMEM);
    cudaFuncSetAttribute(mm_gemm_kernel<2,1>, cudaFuncAttributeMaxDynamicSharedMemorySize, MM_SMEM);
    cudaFuncSetAttribute(mm_gemm_kernel<3,0>, cudaFuncAttributeMaxDynamicSharedMemorySize, MM_SMEM);
    cudaFuncSetAttribute(mm_gemm_kernel<4,0>, cudaFuncAttributeMaxDynamicSharedMemorySize, MM_SMEM);
    cudaFuncSetAttribute(mm_gemm_kernel<5,0>, cudaFuncAttributeMaxDynamicSharedMemorySize, MM_SMEM);
    cudaFuncSetAttribute(scores_topk_kernel, cudaFuncAttributeMaxDynamicSharedMemorySize, ST_SMEM);

    static cudaStream_t s2 = nullptr;
    static cudaEvent_t evF = nullptr, evJ = nullptr, evF1 = nullptr, evJ1 = nullptr,
                       evF2 = nullptr, evJ2 = nullptr;
    if (!s2) {
        cudaStreamCreateWithFlags(&s2, cudaStreamNonBlocking);
        cudaEventCreateWithFlags(&evF,  cudaEventDisableTiming);
        cudaEventCreateWithFlags(&evJ,  cudaEventDisableTiming);
        cudaEventCreateWithFlags(&evF1, cudaEventDisableTiming);
        cudaEventCreateWithFlags(&evJ1, cudaEventDisableTiming);
        cudaEventCreateWithFlags(&evF2, cudaEventDisableTiming);
        cudaEventCreateWithFlags(&evJ2, cudaEventDisableTiming);
    }

    dim3 blk(256);
    dim3 tb(32, 8);
    dim3 tg512(8, (NROWS + 127) / 128);
    dim3 tg1024(16, (NROWS + 127) / 128);
    dim3 tg2048(32, (NROWS + 127) / 128);
    dim3 tg4096(64, (NROWS + 127) / 128);
    dim3 kg(8, (NROWS + 63) / 64, 2);

    // ===== fork 0: A-path on s2 ∥ transpose/convert/av on main =================
    cudaEventRecord(evF, 0);
    cudaStreamWaitEvent(s2, evF, 0);

    kgemm_qk_kernel<<<kg, blk, 0, s2>>>(x, aqw, aqb, qb, akw, akb, kb, NROWS, 512, 512);
    scores_topk_kernel<<<dim3(11, 512), blk, ST_SMEM, s2>>>(qb, kb, Aout, avidx, avwt, avcnt);
    cudaEventRecord(evJ, s2);

    {
        TransArgs ta;
        const float* srcs[11] = {avw, aow, encw, f1qw, f1kw, f1vw, f1ow, f2qw, f2kw, f2vw, f2ow};
        uint32_t offs[11] = {OFF_AV, OFF_AO, OFF_ENC, OFF_F1Q, OFF_F1K, OFF_F1V,
                             OFF_F1O, OFF_F2Q, OFF_F2K, OFF_F2V, OFF_F2O};
        int Ks[11] = {512, 512, 512, 512, 512, 512, 2048, 2048, 2048, 2048, 512};
        int Ns[11] = {512, 512, 512, 2048, 512, 512, 2048, 512, 2048, 2048, 512};
        int acc = 0;
        for (int j = 0; j < 11; j++) {
            ta.job[j].src = srcs[j];
            ta.job[j].dstoff = offs[j];
            ta.job[j].K = Ks[j];
            ta.job[j].N = Ns[j];
            ta.job[j].tstart = acc;
            acc += (Ns[j] >> 5) * (Ks[j] >> 5);
        }
        transpose_split_all<<<acc, tb>>>(ta);
    }
    convert_kernel<<<4096, 256>>>(x, x_sp, (int)S);
    mm_gemm_kernel<1,0><<<tg512, blk, MM_SMEM>>>(x_sp, wt16 + 2 * OFF_AV, avb, nullptr, vb, NROWS, 512, 512);

    cudaStreamWaitEvent(0, evJ, 0);   // join 0
    // ===========================================================================

    av_sparse_kernel<<<NROWS, blk>>>(avidx, avwt, avcnt, vb, att_sp);
    mm_gemm_kernel<2,1><<<tg512, blk, MM_SMEM>>>(att_sp, wt16 + 2 * OFF_AO, aob, x, zb_sp, NROWS, 512, 512);
    mm_gemm_kernel<0,1><<<tg512, blk, MM_SMEM>>>(zb_sp, wt16 + 2 * OFF_ENC, encb, nullptr, y2_sp, NROWS, 512, 512);

    // ---- ff1: f1q (main) ∥ f1kv (s2) ----
    cudaEventRecord(evF1, 0);
    cudaStreamWaitEvent(s2, evF1, 0);
    mm_gemm_kernel<5,0><<<tg1024, blk, MM_SMEM, s2>>>(y2_sp, wt16 + 2 * OFF_F1K, f1kb, f1vb, kv1, NROWS, 1024, 512);
    cudaEventRecord(evJ1, s2);
    mm_gemm_kernel<1,0><<<tg2048, blk, MM_SMEM>>>(y2_sp, wt16 + 2 * OFF_F1Q, f1qb, nullptr, q1, NROWS, 2048, 512);
    cudaStreamWaitEvent(0, evJ1, 0);

    pwattn1_kernel<<<NROWS, 128>>>(q1, kv1, Vf1_sp);
    mm_gemm_kernel<3,0><<<tg2048, blk, MM_SMEM>>>(Vf1_sp, wt16 + 2 * OFF_F1O, f1ob, q1, t1, NROWS, 2048, 2048);
    ln_kernel<<<NROWS, blk>>>(t1, lng, lnb, u_sp);

    // ---- ff2: f2q (s2) ∥ f2kv (main) ----
    cudaEventRecord(evF2, 0);
    cudaStreamWaitEvent(s2, evF2, 0);
    mm_gemm_kernel<1,0><<<tg512, blk, MM_SMEM, s2>>>(u_sp, wt16 + 2 * OFF_F2Q, f2qb, nullptr, qu2, NROWS, 512, 2048);
    cudaEventRecord(evJ2, s2);
    mm_gemm_kernel<5,0><<<tg4096, blk, MM_SMEM>>>(u_sp, wt16 + 2 * OFF_F2K, f2kb, f2vb, kv2, NROWS, 4096, 2048);
    cudaStreamWaitEvent(0, evJ2, 0);

    pwattn2_kernel<<<NROWS / 4, 128>>>(qu2, kv2, x_sp);   // att2 -> reuse x_sp
    mm_gemm_kernel<4,0><<<tg512, blk, MM_SMEM>>>(x_sp, wt16 + 2 * OFF_F2O, f2ob, qu2, out, NROWS, 512, 512);
}